// round 1
// baseline (speedup 1.0000x reference)
#include <cuda_runtime.h>

#define BB 4
#define TT 2048
#define DD 1024
#define HH 16
#define SS 64
#define MM (BB*TT)

// ---------------- device scratch (static, allocation-free) ----------------
__device__ float g_absmax[8];
__device__ float g_wq_q[DD*DD];
__device__ float g_wk_q[DD*DD];
__device__ float g_wq_eff[DD*DD];
__device__ float g_wk_eff[DD*DD];
__device__ float g_wv_q[DD*DD];
__device__ float g_wo_q[DD*DD];
__device__ float g_wu_q[SS*SS];
__device__ float g_wsv_q[SS*SS];
__device__ float g_Q[(size_t)BB*HH*TT*SS];
__device__ float g_K[(size_t)BB*HH*TT*SS];
__device__ float g_V[(size_t)BB*HH*TT*SS];
__device__ float g_attn[(size_t)BB*TT*DD];

// ---------------- weight quantization ----------------
__global__ void zero_absmax_kernel() {
    if (threadIdx.x < 8) g_absmax[threadIdx.x] = 0.0f;
}

__global__ void absmax_kernel(const float* __restrict__ w, int n, int slot) {
    float m = 0.0f;
    for (int i = blockIdx.x * blockDim.x + threadIdx.x; i < n; i += gridDim.x * blockDim.x)
        m = fmaxf(m, fabsf(w[i]));
    #pragma unroll
    for (int o = 16; o > 0; o >>= 1) m = fmaxf(m, __shfl_xor_sync(0xffffffffu, m, o));
    __shared__ float sm[8];
    int lane = threadIdx.x & 31, wid = threadIdx.x >> 5;
    if (lane == 0) sm[wid] = m;
    __syncthreads();
    if (wid == 0) {
        int nw = blockDim.x >> 5;
        m = (lane < nw) ? sm[lane] : 0.0f;
        #pragma unroll
        for (int o = 4; o > 0; o >>= 1) m = fmaxf(m, __shfl_xor_sync(0xffffffffu, m, o));
        if (lane == 0) atomicMax((int*)&g_absmax[slot], __float_as_int(m));
    }
}

__global__ void quant_kernel(const float* __restrict__ w, int n, int slot, int dst) {
    float* out;
    switch (dst) {
        case 0: out = g_wq_q;  break;
        case 1: out = g_wk_q;  break;
        case 2: out = g_wv_q;  break;
        case 3: out = g_wo_q;  break;
        case 4: out = g_wu_q;  break;
        default: out = g_wsv_q; break;
    }
    float sc = g_absmax[slot] / 31.0f + 1e-8f;
    for (int i = blockIdx.x * blockDim.x + threadIdx.x; i < n; i += gridDim.x * blockDim.x) {
        float q = rintf(w[i] / sc);           // rintf = round-half-even, matches jnp.round
        q = fminf(fmaxf(q, -31.0f), 31.0f);
        out[i] = q * sc;
    }
}

// Fold quantized stalk map (S x S) into quantized projection (D x D):
//   weff[h*S+sp, k] = sum_s wsmall[sp,s] * wbig[h*S+s, k]
__global__ void compose_kernel(int which) {
    const float* wsmall = which ? g_wsv_q : g_wu_q;
    const float* wbig   = which ? g_wk_q  : g_wq_q;
    float* out          = which ? g_wk_eff : g_wq_eff;
    int idx = blockIdx.x * 256 + threadIdx.x;      // over D*D
    int row = idx >> 10, k = idx & 1023;
    int h = row >> 6, sp = row & 63;
    const float* bw = wbig + (size_t)(h << 6) * DD + k;
    const float* sw = wsmall + sp * SS;
    float acc = 0.0f;
    #pragma unroll 16
    for (int s = 0; s < SS; s++) acc += sw[s] * bw[(size_t)s * DD];
    out[idx] = acc;
}

// ---------------- 128x128x16 fp32 GEMM:  Y = A @ W^T ----------------
// A: [M,1024] row-major, W: [1024 rows n][1024 k] row-major.
// Rotation swizzle keeps all smem traffic <=2-way conflicted, all float4.
template<bool TO_BHTS>
__device__ __forceinline__ void gemm_body(const float* __restrict__ A,
                                          const float* __restrict__ W,
                                          float* __restrict__ Out) {
    __shared__ float As[16][128];
    __shared__ float Bs[16][128];
    const int tid = threadIdx.x;
    const int tx = tid & 15, ty = tid >> 4;
    const int m0 = blockIdx.y * 128;
    const int n0 = blockIdx.x * 128;

    float c[2][2][4][4];
    #pragma unroll
    for (int a = 0; a < 2; a++)
        #pragma unroll
        for (int b = 0; b < 2; b++)
            #pragma unroll
            for (int i = 0; i < 4; i++)
                #pragma unroll
                for (int j = 0; j < 4; j++) c[a][b][i][j] = 0.0f;

    const float* Ag = A + (size_t)m0 * DD;
    const float* Wg = W + (size_t)n0 * DD;

    for (int k0 = 0; k0 < DD; k0 += 16) {
        __syncthreads();
        #pragma unroll
        for (int r = 0; r < 2; r++) {
            int idx = tid + r * 256;           // 0..511
            int mrow = idx >> 2, kv = idx & 3;
            float4 va = *(const float4*)(Ag + (size_t)mrow * DD + k0 + kv * 4);
            float4 vb = *(const float4*)(Wg + (size_t)mrow * DD + k0 + kv * 4);
            int kb = kv * 4;
            As[kb+0][(mrow + (kb+0)*4) & 127] = va.x;
            As[kb+1][(mrow + (kb+1)*4) & 127] = va.y;
            As[kb+2][(mrow + (kb+2)*4) & 127] = va.z;
            As[kb+3][(mrow + (kb+3)*4) & 127] = va.w;
            Bs[kb+0][(mrow + (kb+0)*4) & 127] = vb.x;
            Bs[kb+1][(mrow + (kb+1)*4) & 127] = vb.y;
            Bs[kb+2][(mrow + (kb+2)*4) & 127] = vb.z;
            Bs[kb+3][(mrow + (kb+3)*4) & 127] = vb.w;
        }
        __syncthreads();
        #pragma unroll
        for (int k = 0; k < 16; k++) {
            int rot = (k * 4) & 127;
            float4 a0 = *(const float4*)&As[k][( 4*ty      + rot) & 127];
            float4 a1 = *(const float4*)&As[k][((64+4*ty)  + rot) & 127];
            float4 b0 = *(const float4*)&Bs[k][( 4*tx      + rot) & 127];
            float4 b1 = *(const float4*)&Bs[k][((64+4*tx)  + rot) & 127];
            float av[2][4] = {{a0.x,a0.y,a0.z,a0.w},{a1.x,a1.y,a1.z,a1.w}};
            float bv[2][4] = {{b0.x,b0.y,b0.z,b0.w},{b1.x,b1.y,b1.z,b1.w}};
            #pragma unroll
            for (int rh = 0; rh < 2; rh++)
                #pragma unroll
                for (int ch = 0; ch < 2; ch++)
                    #pragma unroll
                    for (int i = 0; i < 4; i++)
                        #pragma unroll
                        for (int j = 0; j < 4; j++)
                            c[rh][ch][i][j] += av[rh][i] * bv[ch][j];
        }
    }

    #pragma unroll
    for (int rh = 0; rh < 2; rh++)
        #pragma unroll
        for (int i = 0; i < 4; i++) {
            int mrow = m0 + rh * 64 + 4 * ty + i;
            #pragma unroll
            for (int ch = 0; ch < 2; ch++) {
                int nb = n0 + ch * 64 + 4 * tx;
                float4 v = make_float4(c[rh][ch][i][0], c[rh][ch][i][1],
                                       c[rh][ch][i][2], c[rh][ch][i][3]);
                if (TO_BHTS) {
                    int b = mrow >> 11;     // / T
                    int t = mrow & 2047;
                    int hh = nb >> 6;       // / S
                    int s = nb & 63;
                    *(float4*)(Out + (((size_t)b * HH + hh) * TT + t) * SS + s) = v;
                } else {
                    *(float4*)(Out + (size_t)mrow * DD + nb) = v;
                }
            }
        }
}

__global__ __launch_bounds__(256, 2) void gemm_qkv_kernel(const float* __restrict__ X) {
    const float* W = (blockIdx.z == 0) ? g_wq_eff : (blockIdx.z == 1) ? g_wk_eff : g_wv_q;
    float* O       = (blockIdx.z == 0) ? g_Q      : (blockIdx.z == 1) ? g_K      : g_V;
    gemm_body<true>(X, W, O);
}

__global__ __launch_bounds__(256, 2) void gemm_out_kernel(float* __restrict__ Out) {
    gemm_body<false>(g_attn, g_wo_q, Out);
}

// ---------------- flash attention with p-adic bias, causal ----------------
// grid (T/64, B*H), 256 threads, 64x64 tiles, 4x4 microtile per thread.
__global__ __launch_bounds__(256) void attn_kernel(const float* __restrict__ ps_in) {
    __shared__ float Qs[64][64];   // [s][q-col rotated]
    __shared__ float KPs[64][64];  // K: [s][k-col rotated], then reused as P: [k][q-col rotated]
    __shared__ float Vs[64][64];   // [k][s] natural

    const int tid = threadIdx.x;
    const int tx = tid & 15, ty = tid >> 4;
    const int qt = blockIdx.x;
    const int bh = blockIdx.y;
    const float pscale = ps_in[0];

    const float* Qg = g_Q + ((size_t)bh * TT + qt * 64) * SS;
    const float* Kg = g_K + (size_t)bh * TT * SS;
    const float* Vg = g_V + (size_t)bh * TT * SS;

    // load + transpose Q tile (rotation by (s & ~3))
    #pragma unroll
    for (int r = 0; r < 4; r++) {
        int idx = tid + r * 256;
        int qr = idx >> 4, sv = idx & 15;
        float4 v = *(const float4*)(Qg + qr * SS + sv * 4);
        int s0 = sv * 4;
        int col = (qr + s0) & 63;
        Qs[s0+0][col] = v.x;  Qs[s0+1][col] = v.y;
        Qs[s0+2][col] = v.z;  Qs[s0+3][col] = v.w;
    }

    float m_i[4], l_i[4], o_acc[4][4];
    #pragma unroll
    for (int i = 0; i < 4; i++) {
        m_i[i] = -1e30f; l_i[i] = 0.0f;
        #pragma unroll
        for (int j = 0; j < 4; j++) o_acc[i][j] = 0.0f;
    }

    for (int kt = 0; kt <= qt; kt++) {
        __syncthreads();  // previous PV done before K/V overwrite
        const float* Kt = Kg + (size_t)kt * 64 * SS;
        const float* Vt = Vg + (size_t)kt * 64 * SS;
        #pragma unroll
        for (int r = 0; r < 4; r++) {
            int idx = tid + r * 256;
            int kk = idx >> 4, sv = idx & 15;
            int s0 = sv * 4;
            float4 kv4 = *(const float4*)(Kt + kk * SS + s0);
            int col = (kk + s0) & 63;
            KPs[s0+0][col] = kv4.x;  KPs[s0+1][col] = kv4.y;
            KPs[s0+2][col] = kv4.z;  KPs[s0+3][col] = kv4.w;
            float4 vv4 = *(const float4*)(Vt + kk * SS + s0);
            *(float4*)&Vs[kk][s0] = vv4;
        }
        __syncthreads();

        // S = Q K^T
        float acc[4][4];
        #pragma unroll
        for (int i = 0; i < 4; i++)
            #pragma unroll
            for (int j = 0; j < 4; j++) acc[i][j] = 0.0f;
        #pragma unroll 16
        for (int s = 0; s < 64; s++) {
            int rot = s & 60;
            float4 a4 = *(const float4*)&Qs[s][(4*ty + rot) & 63];
            float4 b4 = *(const float4*)&KPs[s][(4*tx + rot) & 63];
            float av[4] = {a4.x, a4.y, a4.z, a4.w};
            float bv[4] = {b4.x, b4.y, b4.z, b4.w};
            #pragma unroll
            for (int i = 0; i < 4; i++)
                #pragma unroll
                for (int j = 0; j < 4; j++)
                    acc[i][j] += av[i] * bv[j];
        }

        // scale + p-adic bias + causal mask
        const int ib = qt * 64 + 4 * ty;
        const int jb = kt * 64 + 4 * tx;
        float pr[4][4];
        #pragma unroll
        for (int i = 0; i < 4; i++)
            #pragma unroll
            for (int j = 0; j < 4; j++) {
                int d = (ib + i) - (jb + j);
                float v;
                if (d < 0) v = -1e30f;
                else {
                    float bias = (d == 0) ? 1.0f : (float)(__ffs(d) - 1) * 0.0625f;
                    v = acc[i][j] * 0.125f + pscale * bias;
                }
                pr[i][j] = v;
            }

        // online softmax (row stats replicated across the 16 tx lanes)
        #pragma unroll
        for (int i = 0; i < 4; i++) {
            float tm = fmaxf(fmaxf(pr[i][0], pr[i][1]), fmaxf(pr[i][2], pr[i][3]));
            #pragma unroll
            for (int off = 8; off > 0; off >>= 1)
                tm = fmaxf(tm, __shfl_xor_sync(0xffffffffu, tm, off, 16));
            float mnew = fmaxf(m_i[i], tm);
            float alpha = __expf(m_i[i] - mnew);
            m_i[i] = mnew;
            float rs = 0.0f;
            #pragma unroll
            for (int j = 0; j < 4; j++) {
                float p = __expf(pr[i][j] - mnew);
                pr[i][j] = p;
                rs += p;
            }
            #pragma unroll
            for (int off = 8; off > 0; off >>= 1)
                rs += __shfl_xor_sync(0xffffffffu, rs, off, 16);
            l_i[i] = l_i[i] * alpha + rs;
            #pragma unroll
            for (int j = 0; j < 4; j++) o_acc[i][j] *= alpha;
        }

        __syncthreads();  // done reading K before overwriting with P
        #pragma unroll
        for (int i = 0; i < 4; i++) {
            int col = (4*ty + i + 4*tx) & 63;   // rotation by (kcol & ~3) = 4*tx
            #pragma unroll
            for (int j = 0; j < 4; j++)
                KPs[4*tx + j][col] = pr[i][j];
        }
        __syncthreads();

        // O += P V
        #pragma unroll 16
        for (int kk = 0; kk < 64; kk++) {
            int rot = kk & 60;
            float4 a4 = *(const float4*)&KPs[kk][(4*ty + rot) & 63];
            float4 b4 = *(const float4*)&Vs[kk][4*tx];
            float av[4] = {a4.x, a4.y, a4.z, a4.w};
            float bv[4] = {b4.x, b4.y, b4.z, b4.w};
            #pragma unroll
            for (int i = 0; i < 4; i++)
                #pragma unroll
                for (int j = 0; j < 4; j++)
                    o_acc[i][j] += av[i] * bv[j];
        }
    }

    // epilogue: write [B,T,D] layout for the final projection
    int b = bh >> 4, hh = bh & 15;
    #pragma unroll
    for (int i = 0; i < 4; i++) {
        int t = qt * 64 + 4 * ty + i;
        float inv = 1.0f / l_i[i];
        float4 v = make_float4(o_acc[i][0]*inv, o_acc[i][1]*inv,
                               o_acc[i][2]*inv, o_acc[i][3]*inv);
        *(float4*)(g_attn + ((size_t)(b * TT + t)) * DD + hh * SS + 4 * tx) = v;
    }
}

// ---------------- launch ----------------
extern "C" void kernel_launch(void* const* d_in, const int* in_sizes, int n_in,
                              void* d_out, int out_size) {
    const float* x   = (const float*)d_in[0];
    const float* wq  = (const float*)d_in[1];
    const float* wk  = (const float*)d_in[2];
    const float* wv  = (const float*)d_in[3];
    const float* wo  = (const float*)d_in[4];
    const float* wu  = (const float*)d_in[5];
    const float* wsv = (const float*)d_in[6];
    const float* ps  = (const float*)d_in[7];
    float* out = (float*)d_out;

    zero_absmax_kernel<<<1, 32>>>();
    absmax_kernel<<<256, 256>>>(wq, DD*DD, 0);
    absmax_kernel<<<256, 256>>>(wk, DD*DD, 1);
    absmax_kernel<<<256, 256>>>(wv, DD*DD, 2);
    absmax_kernel<<<256, 256>>>(wo, DD*DD, 3);
    absmax_kernel<<<16, 256>>>(wu, SS*SS, 4);
    absmax_kernel<<<16, 256>>>(wsv, SS*SS, 5);

    quant_kernel<<<512, 256>>>(wq, DD*DD, 0, 0);
    quant_kernel<<<512, 256>>>(wk, DD*DD, 1, 1);
    quant_kernel<<<512, 256>>>(wv, DD*DD, 2, 2);
    quant_kernel<<<512, 256>>>(wo, DD*DD, 3, 3);
    quant_kernel<<<16, 256>>>(wu, SS*SS, 4, 4);
    quant_kernel<<<16, 256>>>(wsv, SS*SS, 5, 5);

    compose_kernel<<<DD*DD/256, 256>>>(0);
    compose_kernel<<<DD*DD/256, 256>>>(1);

    gemm_qkv_kernel<<<dim3(DD/128, MM/128, 3), 256>>>(x);
    attn_kernel<<<dim3(TT/64, BB*HH), 256>>>(ps);
    gemm_out_kernel<<<dim3(DD/128, MM/128), 256>>>(out);
}

// round 2
// speedup vs baseline: 1.6116x; 1.6116x over previous
#include <cuda_runtime.h>
#include <cuda_bf16.h>
#include <cstdint>

#define BB 4
#define TT 2048
#define DD 1024
#define HH 16
#define SS 64
#define MM (BB*TT)
#define K3 3072          // [hi | lo | hi] segments of K=1024

// ---------------- device scratch (static, allocation-free) ----------------
__device__ float g_absmax[8];
__device__ float g_wq_q[DD*DD];
__device__ float g_wk_q[DD*DD];
__device__ float g_wq_eff[DD*DD];
__device__ float g_wk_eff[DD*DD];
__device__ float g_wv_q[DD*DD];
__device__ float g_wo_q[DD*DD];
__device__ float g_wu_q[SS*SS];
__device__ float g_wsv_q[SS*SS];
__device__ float g_Q[(size_t)BB*HH*TT*SS];
__device__ float g_K[(size_t)BB*HH*TT*SS];
__device__ float g_V[(size_t)BB*HH*TT*SS];
__device__ float g_attn[(size_t)BB*TT*DD];
__device__ __nv_bfloat16 g_A3[(size_t)MM*K3];       // split activations
__device__ __nv_bfloat16 g_W3[(size_t)4*DD*K3];     // split weights (q,k,v,o)

// ---------------- weight quantization ----------------
__global__ void zero_absmax_kernel() {
    if (threadIdx.x < 8) g_absmax[threadIdx.x] = 0.0f;
}

__global__ void absmax_kernel(const float* __restrict__ w, int n, int slot) {
    float m = 0.0f;
    for (int i = blockIdx.x * blockDim.x + threadIdx.x; i < n; i += gridDim.x * blockDim.x)
        m = fmaxf(m, fabsf(w[i]));
    #pragma unroll
    for (int o = 16; o > 0; o >>= 1) m = fmaxf(m, __shfl_xor_sync(0xffffffffu, m, o));
    __shared__ float sm[8];
    int lane = threadIdx.x & 31, wid = threadIdx.x >> 5;
    if (lane == 0) sm[wid] = m;
    __syncthreads();
    if (wid == 0) {
        int nw = blockDim.x >> 5;
        m = (lane < nw) ? sm[lane] : 0.0f;
        #pragma unroll
        for (int o = 4; o > 0; o >>= 1) m = fmaxf(m, __shfl_xor_sync(0xffffffffu, m, o));
        if (lane == 0) atomicMax((int*)&g_absmax[slot], __float_as_int(m));
    }
}

__global__ void quant_kernel(const float* __restrict__ w, int n, int slot, int dst) {
    float* out;
    switch (dst) {
        case 0: out = g_wq_q;  break;
        case 1: out = g_wk_q;  break;
        case 2: out = g_wv_q;  break;
        case 3: out = g_wo_q;  break;
        case 4: out = g_wu_q;  break;
        default: out = g_wsv_q; break;
    }
    float sc = g_absmax[slot] / 31.0f + 1e-8f;
    for (int i = blockIdx.x * blockDim.x + threadIdx.x; i < n; i += gridDim.x * blockDim.x) {
        float q = rintf(w[i] / sc);           // round-half-even, matches jnp.round
        q = fminf(fmaxf(q, -31.0f), 31.0f);
        out[i] = q * sc;
    }
}

// Fold quantized stalk map (S x S) into quantized projection (D x D)
__global__ void compose_kernel(int which) {
    const float* wsmall = which ? g_wsv_q : g_wu_q;
    const float* wbig   = which ? g_wk_q  : g_wq_q;
    float* out          = which ? g_wk_eff : g_wq_eff;
    int idx = blockIdx.x * 256 + threadIdx.x;      // over D*D
    int row = idx >> 10, k = idx & 1023;
    int h = row >> 6, sp = row & 63;
    const float* bw = wbig + (size_t)(h << 6) * DD + k;
    const float* sw = wsmall + sp * SS;
    float acc = 0.0f;
    #pragma unroll 16
    for (int s = 0; s < SS; s++) acc += sw[s] * bw[(size_t)s * DD];
    out[idx] = acc;
}

// ---------------- hi/lo bf16 splits ----------------
// activations: A3 = [hi | lo | hi]
__global__ void split_act_kernel(const float* __restrict__ xext, int use_attn) {
    const float* src = use_attn ? g_attn : xext;
    int i = blockIdx.x * 256 + threadIdx.x;      // one float4 each; grid = MM*DD/1024
    int row = i >> 8;
    int k4 = (i & 255) * 4;
    float4 v = *(const float4*)(src + (size_t)row * DD + k4);
    __nv_bfloat16 h0 = __float2bfloat16(v.x), h1 = __float2bfloat16(v.y);
    __nv_bfloat16 h2 = __float2bfloat16(v.z), h3 = __float2bfloat16(v.w);
    __nv_bfloat16 l0 = __float2bfloat16(v.x - __bfloat162float(h0));
    __nv_bfloat16 l1 = __float2bfloat16(v.y - __bfloat162float(h1));
    __nv_bfloat16 l2 = __float2bfloat16(v.z - __bfloat162float(h2));
    __nv_bfloat16 l3 = __float2bfloat16(v.w - __bfloat162float(h3));
    __nv_bfloat16* o = g_A3 + (size_t)row * K3 + k4;
    *(__nv_bfloat162*)(o)          = __nv_bfloat162(h0, h1);
    *(__nv_bfloat162*)(o + 2)      = __nv_bfloat162(h2, h3);
    *(__nv_bfloat162*)(o + 1024)   = __nv_bfloat162(l0, l1);
    *(__nv_bfloat162*)(o + 1026)   = __nv_bfloat162(l2, l3);
    *(__nv_bfloat162*)(o + 2048)   = __nv_bfloat162(h0, h1);
    *(__nv_bfloat162*)(o + 2050)   = __nv_bfloat162(h2, h3);
}

// weights: W3 = [hi | hi | lo]
__global__ void split_w_kernel(int srcsel, int dst) {
    const float* src = (srcsel == 0) ? g_wq_eff : (srcsel == 1) ? g_wk_eff
                     : (srcsel == 2) ? g_wv_q   : g_wo_q;
    int i = blockIdx.x * 256 + threadIdx.x;      // one float4 each; grid = DD*DD/1024
    int row = i >> 8;
    int k4 = (i & 255) * 4;
    float4 v = *(const float4*)(src + (size_t)row * DD + k4);
    __nv_bfloat16 h0 = __float2bfloat16(v.x), h1 = __float2bfloat16(v.y);
    __nv_bfloat16 h2 = __float2bfloat16(v.z), h3 = __float2bfloat16(v.w);
    __nv_bfloat16 l0 = __float2bfloat16(v.x - __bfloat162float(h0));
    __nv_bfloat16 l1 = __float2bfloat16(v.y - __bfloat162float(h1));
    __nv_bfloat16 l2 = __float2bfloat16(v.z - __bfloat162float(h2));
    __nv_bfloat16 l3 = __float2bfloat16(v.w - __bfloat162float(h3));
    __nv_bfloat16* o = g_W3 + (size_t)dst * DD * K3 + (size_t)row * K3 + k4;
    *(__nv_bfloat162*)(o)          = __nv_bfloat162(h0, h1);
    *(__nv_bfloat162*)(o + 2)      = __nv_bfloat162(h2, h3);
    *(__nv_bfloat162*)(o + 1024)   = __nv_bfloat162(h0, h1);
    *(__nv_bfloat162*)(o + 1026)   = __nv_bfloat162(h2, h3);
    *(__nv_bfloat162*)(o + 2048)   = __nv_bfloat162(l0, l1);
    *(__nv_bfloat162*)(o + 2050)   = __nv_bfloat162(l2, l3);
}

// ---------------- bf16 tensor-core GEMM:  C[M,N] = A3 @ W3^T ----------------
__device__ __forceinline__ void cp16(void* dst, const void* src) {
    unsigned d = (unsigned)__cvta_generic_to_shared(dst);
    asm volatile("cp.async.cg.shared.global [%0], [%1], 16;\n" :: "r"(d), "l"(src));
}

#define LDM4(R, PTR) do { \
    unsigned _a = (unsigned)__cvta_generic_to_shared(PTR); \
    asm volatile("ldmatrix.sync.aligned.m8n8.x4.shared.b16 {%0,%1,%2,%3}, [%4];" \
        : "=r"((R)[0]), "=r"((R)[1]), "=r"((R)[2]), "=r"((R)[3]) : "r"(_a)); \
} while (0)

#define MMA16816(C, A, B0, B1) \
    asm volatile("mma.sync.aligned.m16n8k16.row.col.f32.bf16.bf16.f32 " \
        "{%0,%1,%2,%3}, {%4,%5,%6,%7}, {%8,%9}, {%0,%1,%2,%3};" \
        : "+f"((C)[0]), "+f"((C)[1]), "+f"((C)[2]), "+f"((C)[3]) \
        : "r"((A)[0]), "r"((A)[1]), "r"((A)[2]), "r"((A)[3]), "r"(B0), "r"(B1))

#define SWZ(row, ch) ((ch) ^ (((row) >> 1) & 3))

__global__ __launch_bounds__(256, 2) void gemm_bf16_kernel(float* __restrict__ ext_out,
                                                           int base_which) {
    __shared__ alignas(16) __nv_bfloat16 As[2][128 * 32];
    __shared__ alignas(16) __nv_bfloat16 Bs[2][128 * 32];

    const int which = base_which + blockIdx.z;
    const __nv_bfloat16* __restrict__ Wg = g_W3 + (size_t)which * DD * K3;
    const int tid = threadIdx.x;
    const int lane = tid & 31, wid = tid >> 5;
    const int warp_m = wid >> 1, warp_n = wid & 1;
    const int m0 = blockIdx.y * 128;
    const int n0 = blockIdx.x * 128;

    const __nv_bfloat16* Ag = g_A3 + (size_t)m0 * K3;
    const __nv_bfloat16* Bg = Wg + (size_t)n0 * K3;

    float c[2][4][2][4];
    #pragma unroll
    for (int i = 0; i < 2; i++)
        #pragma unroll
        for (int g = 0; g < 4; g++)
            #pragma unroll
            for (int j = 0; j < 2; j++)
                #pragma unroll
                for (int q = 0; q < 4; q++) c[i][g][j][q] = 0.0f;

    // precompute per-thread load offsets
    int ld_row[2], ld_ch[2];
    #pragma unroll
    for (int p = 0; p < 2; p++) {
        int e = tid + p * 256;
        ld_row[p] = e >> 2;
        ld_ch[p] = e & 3;
    }

    const int NC = K3 / 32;   // 96 chunks

    // preload stage 0
    #pragma unroll
    for (int p = 0; p < 2; p++) {
        int row = ld_row[p], ch = ld_ch[p];
        int so = row * 32 + SWZ(row, ch) * 8;
        cp16(&As[0][so], Ag + (size_t)row * K3 + ch * 8);
        cp16(&Bs[0][so], Bg + (size_t)row * K3 + ch * 8);
    }
    asm volatile("cp.async.commit_group;");

    for (int kc = 0; kc < NC; kc++) {
        if (kc + 1 < NC) {
            int s = (kc + 1) & 1;
            int koff = (kc + 1) * 32;
            #pragma unroll
            for (int p = 0; p < 2; p++) {
                int row = ld_row[p], ch = ld_ch[p];
                int so = row * 32 + SWZ(row, ch) * 8;
                cp16(&As[s][so], Ag + (size_t)row * K3 + koff + ch * 8);
                cp16(&Bs[s][so], Bg + (size_t)row * K3 + koff + ch * 8);
            }
            asm volatile("cp.async.commit_group;");
            asm volatile("cp.async.wait_group 1;");
        } else {
            asm volatile("cp.async.wait_group 0;");
        }
        __syncthreads();

        const __nv_bfloat16* Asb = As[kc & 1];
        const __nv_bfloat16* Bsb = Bs[kc & 1];

        #pragma unroll
        for (int kk = 0; kk < 2; kk++) {
            uint32_t af[2][4], bf[4][4];
            #pragma unroll
            for (int i = 0; i < 2; i++) {
                int row = warp_m * 32 + i * 16 + (lane & 15);
                int ch = kk * 2 + (lane >> 4);
                LDM4(af[i], Asb + row * 32 + SWZ(row, ch) * 8);
            }
            #pragma unroll
            for (int g = 0; g < 4; g++) {
                int row = warp_n * 64 + g * 16 + (lane & 7) + ((lane >> 4) << 3);
                int ch = kk * 2 + ((lane >> 3) & 1);
                LDM4(bf[g], Bsb + row * 32 + SWZ(row, ch) * 8);
            }
            #pragma unroll
            for (int i = 0; i < 2; i++)
                #pragma unroll
                for (int g = 0; g < 4; g++) {
                    MMA16816(c[i][g][0], af[i], bf[g][0], bf[g][1]);
                    MMA16816(c[i][g][1], af[i], bf[g][2], bf[g][3]);
                }
        }
        __syncthreads();
    }

    // epilogue
    float* dst = (which == 0) ? g_Q : (which == 1) ? g_K : (which == 2) ? g_V : ext_out;
    #pragma unroll
    for (int i = 0; i < 2; i++)
        #pragma unroll
        for (int g = 0; g < 4; g++)
            #pragma unroll
            for (int j = 0; j < 2; j++) {
                int rr = m0 + warp_m * 32 + i * 16 + (lane >> 2);
                int cc = n0 + warp_n * 64 + g * 16 + j * 8 + ((lane & 3) << 1);
                float2 v0 = make_float2(c[i][g][j][0], c[i][g][j][1]);
                float2 v1 = make_float2(c[i][g][j][2], c[i][g][j][3]);
                if (which < 3) {
                    int b = rr >> 11, t = rr & 2047;
                    int hh = cc >> 6, s2 = cc & 63;
                    float* p0 = dst + (((size_t)(b * HH + hh) * TT) + t) * SS + s2;
                    float* p1 = dst + (((size_t)(b * HH + hh) * TT) + t + 8) * SS + s2;
                    *(float2*)p0 = v0;
                    *(float2*)p1 = v1;
                } else {
                    *(float2*)(dst + (size_t)rr * DD + cc) = v0;
                    *(float2*)(dst + (size_t)(rr + 8) * DD + cc) = v1;
                }
            }
}

// ---------------- flash attention with p-adic bias, causal (fp32) ----------------
__global__ __launch_bounds__(256) void attn_kernel(const float* __restrict__ ps_in) {
    __shared__ float Qs[64][64];
    __shared__ float KPs[64][64];
    __shared__ float Vs[64][64];

    const int tid = threadIdx.x;
    const int tx = tid & 15, ty = tid >> 4;
    const int qt = blockIdx.x;
    const int bh = blockIdx.y;
    const float pscale = ps_in[0];

    const float* Qg = g_Q + ((size_t)bh * TT + qt * 64) * SS;
    const float* Kg = g_K + (size_t)bh * TT * SS;
    const float* Vg = g_V + (size_t)bh * TT * SS;

    #pragma unroll
    for (int r = 0; r < 4; r++) {
        int idx = tid + r * 256;
        int qr = idx >> 4, sv = idx & 15;
        float4 v = *(const float4*)(Qg + qr * SS + sv * 4);
        int s0 = sv * 4;
        int col = (qr + s0) & 63;
        Qs[s0+0][col] = v.x;  Qs[s0+1][col] = v.y;
        Qs[s0+2][col] = v.z;  Qs[s0+3][col] = v.w;
    }

    float m_i[4], l_i[4], o_acc[4][4];
    #pragma unroll
    for (int i = 0; i < 4; i++) {
        m_i[i] = -1e30f; l_i[i] = 0.0f;
        #pragma unroll
        for (int j = 0; j < 4; j++) o_acc[i][j] = 0.0f;
    }

    for (int kt = 0; kt <= qt; kt++) {
        __syncthreads();
        const float* Kt = Kg + (size_t)kt * 64 * SS;
        const float* Vt = Vg + (size_t)kt * 64 * SS;
        #pragma unroll
        for (int r = 0; r < 4; r++) {
            int idx = tid + r * 256;
            int kk = idx >> 4, sv = idx & 15;
            int s0 = sv * 4;
            float4 kv4 = *(const float4*)(Kt + kk * SS + s0);
            int col = (kk + s0) & 63;
            KPs[s0+0][col] = kv4.x;  KPs[s0+1][col] = kv4.y;
            KPs[s0+2][col] = kv4.z;  KPs[s0+3][col] = kv4.w;
            float4 vv4 = *(const float4*)(Vt + kk * SS + s0);
            *(float4*)&Vs[kk][s0] = vv4;
        }
        __syncthreads();

        float acc[4][4];
        #pragma unroll
        for (int i = 0; i < 4; i++)
            #pragma unroll
            for (int j = 0; j < 4; j++) acc[i][j] = 0.0f;
        #pragma unroll 16
        for (int s = 0; s < 64; s++) {
            int rot = s & 60;
            float4 a4 = *(const float4*)&Qs[s][(4*ty + rot) & 63];
            float4 b4 = *(const float4*)&KPs[s][(4*tx + rot) & 63];
            float av[4] = {a4.x, a4.y, a4.z, a4.w};
            float bv[4] = {b4.x, b4.y, b4.z, b4.w};
            #pragma unroll
            for (int i = 0; i < 4; i++)
                #pragma unroll
                for (int j = 0; j < 4; j++)
                    acc[i][j] += av[i] * bv[j];
        }

        const int ib = qt * 64 + 4 * ty;
        const int jb = kt * 64 + 4 * tx;
        float pr[4][4];
        #pragma unroll
        for (int i = 0; i < 4; i++)
            #pragma unroll
            for (int j = 0; j < 4; j++) {
                int d = (ib + i) - (jb + j);
                float v;
                if (d < 0) v = -1e30f;
                else {
                    float bias = (d == 0) ? 1.0f : (float)(__ffs(d) - 1) * 0.0625f;
                    v = acc[i][j] * 0.125f + pscale * bias;
                }
                pr[i][j] = v;
            }

        #pragma unroll
        for (int i = 0; i < 4; i++) {
            float tm = fmaxf(fmaxf(pr[i][0], pr[i][1]), fmaxf(pr[i][2], pr[i][3]));
            #pragma unroll
            for (int off = 8; off > 0; off >>= 1)
                tm = fmaxf(tm, __shfl_xor_sync(0xffffffffu, tm, off, 16));
            float mnew = fmaxf(m_i[i], tm);
            float alpha = __expf(m_i[i] - mnew);
            m_i[i] = mnew;
            float rs = 0.0f;
            #pragma unroll
            for (int j = 0; j < 4; j++) {
                float p = __expf(pr[i][j] - mnew);
                pr[i][j] = p;
                rs += p;
            }
            #pragma unroll
            for (int off = 8; off > 0; off >>= 1)
                rs += __shfl_xor_sync(0xffffffffu, rs, off, 16);
            l_i[i] = l_i[i] * alpha + rs;
            #pragma unroll
            for (int j = 0; j < 4; j++) o_acc[i][j] *= alpha;
        }

        __syncthreads();
        #pragma unroll
        for (int i = 0; i < 4; i++) {
            int col = (4*ty + i + 4*tx) & 63;
            #pragma unroll
            for (int j = 0; j < 4; j++)
                KPs[4*tx + j][col] = pr[i][j];
        }
        __syncthreads();

        #pragma unroll 16
        for (int kk = 0; kk < 64; kk++) {
            int rot = kk & 60;
            float4 a4 = *(const float4*)&KPs[kk][(4*ty + rot) & 63];
            float4 b4 = *(const float4*)&Vs[kk][4*tx];
            float av[4] = {a4.x, a4.y, a4.z, a4.w};
            float bv[4] = {b4.x, b4.y, b4.z, b4.w};
            #pragma unroll
            for (int i = 0; i < 4; i++)
                #pragma unroll
                for (int j = 0; j < 4; j++)
                    o_acc[i][j] += av[i] * bv[j];
        }
    }

    int b = bh >> 4, hh = bh & 15;
    #pragma unroll
    for (int i = 0; i < 4; i++) {
        int t = qt * 64 + 4 * ty + i;
        float inv = 1.0f / l_i[i];
        float4 v = make_float4(o_acc[i][0]*inv, o_acc[i][1]*inv,
                               o_acc[i][2]*inv, o_acc[i][3]*inv);
        *(float4*)(g_attn + ((size_t)(b * TT + t)) * DD + hh * SS + 4 * tx) = v;
    }
}

// ---------------- launch ----------------
extern "C" void kernel_launch(void* const* d_in, const int* in_sizes, int n_in,
                              void* d_out, int out_size) {
    const float* x   = (const float*)d_in[0];
    const float* wq  = (const float*)d_in[1];
    const float* wk  = (const float*)d_in[2];
    const float* wv  = (const float*)d_in[3];
    const float* wo  = (const float*)d_in[4];
    const float* wu  = (const float*)d_in[5];
    const float* wsv = (const float*)d_in[6];
    const float* ps  = (const float*)d_in[7];
    float* out = (float*)d_out;

    zero_absmax_kernel<<<1, 32>>>();
    absmax_kernel<<<256, 256>>>(wq, DD*DD, 0);
    absmax_kernel<<<256, 256>>>(wk, DD*DD, 1);
    absmax_kernel<<<256, 256>>>(wv, DD*DD, 2);
    absmax_kernel<<<256, 256>>>(wo, DD*DD, 3);
    absmax_kernel<<<16, 256>>>(wu, SS*SS, 4);
    absmax_kernel<<<16, 256>>>(wsv, SS*SS, 5);

    quant_kernel<<<512, 256>>>(wq, DD*DD, 0, 0);
    quant_kernel<<<512, 256>>>(wk, DD*DD, 1, 1);
    quant_kernel<<<512, 256>>>(wv, DD*DD, 2, 2);
    quant_kernel<<<512, 256>>>(wo, DD*DD, 3, 3);
    quant_kernel<<<16, 256>>>(wu, SS*SS, 4, 4);
    quant_kernel<<<16, 256>>>(wsv, SS*SS, 5, 5);

    compose_kernel<<<DD*DD/256, 256>>>(0);
    compose_kernel<<<DD*DD/256, 256>>>(1);

    split_w_kernel<<<DD*DD/1024, 256>>>(0, 0);
    split_w_kernel<<<DD*DD/1024, 256>>>(1, 1);
    split_w_kernel<<<DD*DD/1024, 256>>>(2, 2);
    split_w_kernel<<<DD*DD/1024, 256>>>(3, 3);

    split_act_kernel<<<MM*DD/1024, 256>>>(x, 0);
    gemm_bf16_kernel<<<dim3(DD/128, MM/128, 3), 256>>>(nullptr, 0);

    attn_kernel<<<dim3(TT/64, BB*HH), 256>>>(ps);

    split_act_kernel<<<MM*DD/1024, 256>>>(nullptr, 1);
    gemm_bf16_kernel<<<dim3(DD/128, MM/128, 1), 256>>>(out, 3);
}

// round 3
// speedup vs baseline: 2.3836x; 1.4790x over previous
#include <cuda_runtime.h>
#include <cuda_bf16.h>
#include <cstdint>

#define BB 4
#define TT 2048
#define DD 1024
#define HH 16
#define SS 64
#define MM (BB*TT)
#define K3 3072          // [hi | lo | hi] segments of K=1024

// ---------------- device scratch (static, allocation-free) ----------------
__device__ float g_absmax[8];
__device__ float g_wq_q[DD*DD];
__device__ float g_wk_q[DD*DD];
__device__ float g_wq_eff[DD*DD];
__device__ float g_wk_eff[DD*DD];
__device__ float g_wv_q[DD*DD];
__device__ float g_wo_q[DD*DD];
__device__ float g_wu_q[SS*SS];
__device__ float g_wsv_q[SS*SS];
__device__ float g_Q[(size_t)BB*HH*TT*SS];
__device__ float g_K[(size_t)BB*HH*TT*SS];
__device__ float g_V[(size_t)BB*HH*TT*SS];
__device__ float g_attn[(size_t)BB*TT*DD];
__device__ __nv_bfloat16 g_A3[(size_t)MM*K3];       // split activations
__device__ __nv_bfloat16 g_W3[(size_t)4*DD*K3];     // split weights (q,k,v,o)
__device__ float g_ebias[2112 + 32];                // exp(pscale*bias(d)) table, idx=d+64, 0 for d<0

// ---------------- weight quantization ----------------
__global__ void zero_absmax_kernel() {
    if (threadIdx.x < 8) g_absmax[threadIdx.x] = 0.0f;
}

__global__ void absmax_kernel(const float* __restrict__ w, int n, int slot) {
    float m = 0.0f;
    for (int i = blockIdx.x * blockDim.x + threadIdx.x; i < n; i += gridDim.x * blockDim.x)
        m = fmaxf(m, fabsf(w[i]));
    #pragma unroll
    for (int o = 16; o > 0; o >>= 1) m = fmaxf(m, __shfl_xor_sync(0xffffffffu, m, o));
    __shared__ float sm[8];
    int lane = threadIdx.x & 31, wid = threadIdx.x >> 5;
    if (lane == 0) sm[wid] = m;
    __syncthreads();
    if (wid == 0) {
        int nw = blockDim.x >> 5;
        m = (lane < nw) ? sm[lane] : 0.0f;
        #pragma unroll
        for (int o = 4; o > 0; o >>= 1) m = fmaxf(m, __shfl_xor_sync(0xffffffffu, m, o));
        if (lane == 0) atomicMax((int*)&g_absmax[slot], __float_as_int(m));
    }
}

__global__ void quant_kernel(const float* __restrict__ w, int n, int slot, int dst) {
    float* out;
    switch (dst) {
        case 0: out = g_wq_q;  break;
        case 1: out = g_wk_q;  break;
        case 2: out = g_wv_q;  break;
        case 3: out = g_wo_q;  break;
        case 4: out = g_wu_q;  break;
        default: out = g_wsv_q; break;
    }
    float sc = g_absmax[slot] / 31.0f + 1e-8f;
    for (int i = blockIdx.x * blockDim.x + threadIdx.x; i < n; i += gridDim.x * blockDim.x) {
        float q = rintf(w[i] / sc);
        q = fminf(fmaxf(q, -31.0f), 31.0f);
        out[i] = q * sc;
    }
}

__global__ void compose_kernel(int which) {
    const float* wsmall = which ? g_wsv_q : g_wu_q;
    const float* wbig   = which ? g_wk_q  : g_wq_q;
    float* out          = which ? g_wk_eff : g_wq_eff;
    int idx = blockIdx.x * 256 + threadIdx.x;
    int row = idx >> 10, k = idx & 1023;
    int h = row >> 6, sp = row & 63;
    const float* bw = wbig + (size_t)(h << 6) * DD + k;
    const float* sw = wsmall + sp * SS;
    float acc = 0.0f;
    #pragma unroll 16
    for (int s = 0; s < SS; s++) acc += sw[s] * bw[(size_t)s * DD];
    out[idx] = acc;
}

// p-adic bias exp table: g_ebias[i] = (i<64) ? 0 : exp(pscale*bias(i-64))
__global__ void build_ebias_kernel(const float* __restrict__ ps) {
    int i = blockIdx.x * 256 + threadIdx.x;
    if (i >= 2112 + 32) return;
    float v = 0.0f;
    if (i >= 64 && i < 2112) {
        int d = i - 64;
        float bias = (d == 0) ? 1.0f : (float)min(__ffs(d) - 1, 16) * 0.0625f;
        v = __expf(ps[0] * bias);
    }
    g_ebias[i] = v;
}

// ---------------- hi/lo bf16 splits for the big GEMMs ----------------
__global__ void split_act_kernel(const float* __restrict__ xext, int use_attn) {
    const float* src = use_attn ? g_attn : xext;
    int i = blockIdx.x * 256 + threadIdx.x;
    int row = i >> 8;
    int k4 = (i & 255) * 4;
    float4 v = *(const float4*)(src + (size_t)row * DD + k4);
    __nv_bfloat16 h0 = __float2bfloat16(v.x), h1 = __float2bfloat16(v.y);
    __nv_bfloat16 h2 = __float2bfloat16(v.z), h3 = __float2bfloat16(v.w);
    __nv_bfloat16 l0 = __float2bfloat16(v.x - __bfloat162float(h0));
    __nv_bfloat16 l1 = __float2bfloat16(v.y - __bfloat162float(h1));
    __nv_bfloat16 l2 = __float2bfloat16(v.z - __bfloat162float(h2));
    __nv_bfloat16 l3 = __float2bfloat16(v.w - __bfloat162float(h3));
    __nv_bfloat16* o = g_A3 + (size_t)row * K3 + k4;
    *(__nv_bfloat162*)(o)          = __nv_bfloat162(h0, h1);
    *(__nv_bfloat162*)(o + 2)      = __nv_bfloat162(h2, h3);
    *(__nv_bfloat162*)(o + 1024)   = __nv_bfloat162(l0, l1);
    *(__nv_bfloat162*)(o + 1026)   = __nv_bfloat162(l2, l3);
    *(__nv_bfloat162*)(o + 2048)   = __nv_bfloat162(h0, h1);
    *(__nv_bfloat162*)(o + 2050)   = __nv_bfloat162(h2, h3);
}

__global__ void split_w_kernel(int srcsel, int dst) {
    const float* src = (srcsel == 0) ? g_wq_eff : (srcsel == 1) ? g_wk_eff
                     : (srcsel == 2) ? g_wv_q   : g_wo_q;
    int i = blockIdx.x * 256 + threadIdx.x;
    int row = i >> 8;
    int k4 = (i & 255) * 4;
    float4 v = *(const float4*)(src + (size_t)row * DD + k4);
    __nv_bfloat16 h0 = __float2bfloat16(v.x), h1 = __float2bfloat16(v.y);
    __nv_bfloat16 h2 = __float2bfloat16(v.z), h3 = __float2bfloat16(v.w);
    __nv_bfloat16 l0 = __float2bfloat16(v.x - __bfloat162float(h0));
    __nv_bfloat16 l1 = __float2bfloat16(v.y - __bfloat162float(h1));
    __nv_bfloat16 l2 = __float2bfloat16(v.z - __bfloat162float(h2));
    __nv_bfloat16 l3 = __float2bfloat16(v.w - __bfloat162float(h3));
    __nv_bfloat16* o = g_W3 + (size_t)dst * DD * K3 + (size_t)row * K3 + k4;
    *(__nv_bfloat162*)(o)          = __nv_bfloat162(h0, h1);
    *(__nv_bfloat162*)(o + 2)      = __nv_bfloat162(h2, h3);
    *(__nv_bfloat162*)(o + 1024)   = __nv_bfloat162(h0, h1);
    *(__nv_bfloat162*)(o + 1026)   = __nv_bfloat162(h2, h3);
    *(__nv_bfloat162*)(o + 2048)   = __nv_bfloat162(l0, l1);
    *(__nv_bfloat162*)(o + 2050)   = __nv_bfloat162(l2, l3);
}

// ---------------- common PTX helpers ----------------
__device__ __forceinline__ void cp16(void* dst, const void* src) {
    unsigned d = (unsigned)__cvta_generic_to_shared(dst);
    asm volatile("cp.async.cg.shared.global [%0], [%1], 16;\n" :: "r"(d), "l"(src));
}

#define LDM4(R, PTR) do { \
    unsigned _a = (unsigned)__cvta_generic_to_shared(PTR); \
    asm volatile("ldmatrix.sync.aligned.m8n8.x4.shared.b16 {%0,%1,%2,%3}, [%4];" \
        : "=r"((R)[0]), "=r"((R)[1]), "=r"((R)[2]), "=r"((R)[3]) : "r"(_a)); \
} while (0)

#define MMA16816(C, A, B0, B1) \
    asm volatile("mma.sync.aligned.m16n8k16.row.col.f32.bf16.bf16.f32 " \
        "{%0,%1,%2,%3}, {%4,%5,%6,%7}, {%8,%9}, {%0,%1,%2,%3};" \
        : "+f"((C)[0]), "+f"((C)[1]), "+f"((C)[2]), "+f"((C)[3]) \
        : "r"((A)[0]), "r"((A)[1]), "r"((A)[2]), "r"((A)[3]), "r"(B0), "r"(B1))

#define SWZ(row, ch) ((ch) ^ (((row) >> 1) & 3))

__device__ __forceinline__ uint32_t prmt_hi(uint32_t a, uint32_t b) {
    uint32_t r;
    asm("prmt.b32 %0, %1, %2, 0x7632;" : "=r"(r) : "r"(a), "r"(b));
    return r;
}
__device__ __forceinline__ uint32_t pack_bf16x2(float lo, float hi) {
    uint32_t r;
    asm("cvt.rn.bf16x2.f32 %0, %1, %2;" : "=r"(r) : "f"(hi), "f"(lo));
    return r;
}
// fast 2^y on fma/alu pipes (y <= ~1), ~3e-6 rel err
__device__ __forceinline__ float exp2p(float y) {
    y = fmaxf(y, -125.0f);
    float z = y + 12582912.0f;
    float f = y - (z - 12582912.0f);
    int e = __float_as_int(z) << 23;
    float r = 0.0013333558146f;
    r = fmaf(r, f, 0.0096181291076f);
    r = fmaf(r, f, 0.055504108664f);
    r = fmaf(r, f, 0.24022650696f);
    r = fmaf(r, f, 0.69314718056f);
    r = fmaf(r, f, 1.0f);
    return __int_as_float(__float_as_int(r) + e);
}

// ---------------- bf16 tensor-core GEMM:  C[M,N] = A3 @ W3^T ----------------
__global__ __launch_bounds__(256, 2) void gemm_bf16_kernel(float* __restrict__ ext_out,
                                                           int base_which) {
    __shared__ alignas(16) __nv_bfloat16 As[2][128 * 32];
    __shared__ alignas(16) __nv_bfloat16 Bs[2][128 * 32];

    const int which = base_which + blockIdx.z;
    const __nv_bfloat16* __restrict__ Wg = g_W3 + (size_t)which * DD * K3;
    const int tid = threadIdx.x;
    const int lane = tid & 31, wid = tid >> 5;
    const int warp_m = wid >> 1, warp_n = wid & 1;
    const int m0 = blockIdx.y * 128;
    const int n0 = blockIdx.x * 128;

    const __nv_bfloat16* Ag = g_A3 + (size_t)m0 * K3;
    const __nv_bfloat16* Bg = Wg + (size_t)n0 * K3;

    float c[2][4][2][4];
    #pragma unroll
    for (int i = 0; i < 2; i++)
        #pragma unroll
        for (int g = 0; g < 4; g++)
            #pragma unroll
            for (int j = 0; j < 2; j++)
                #pragma unroll
                for (int q = 0; q < 4; q++) c[i][g][j][q] = 0.0f;

    int ld_row[2], ld_ch[2];
    #pragma unroll
    for (int p = 0; p < 2; p++) {
        int e = tid + p * 256;
        ld_row[p] = e >> 2;
        ld_ch[p] = e & 3;
    }

    const int NC = K3 / 32;

    #pragma unroll
    for (int p = 0; p < 2; p++) {
        int row = ld_row[p], ch = ld_ch[p];
        int so = row * 32 + SWZ(row, ch) * 8;
        cp16(&As[0][so], Ag + (size_t)row * K3 + ch * 8);
        cp16(&Bs[0][so], Bg + (size_t)row * K3 + ch * 8);
    }
    asm volatile("cp.async.commit_group;");

    for (int kc = 0; kc < NC; kc++) {
        if (kc + 1 < NC) {
            int s = (kc + 1) & 1;
            int koff = (kc + 1) * 32;
            #pragma unroll
            for (int p = 0; p < 2; p++) {
                int row = ld_row[p], ch = ld_ch[p];
                int so = row * 32 + SWZ(row, ch) * 8;
                cp16(&As[s][so], Ag + (size_t)row * K3 + koff + ch * 8);
                cp16(&Bs[s][so], Bg + (size_t)row * K3 + koff + ch * 8);
            }
            asm volatile("cp.async.commit_group;");
            asm volatile("cp.async.wait_group 1;");
        } else {
            asm volatile("cp.async.wait_group 0;");
        }
        __syncthreads();

        const __nv_bfloat16* Asb = As[kc & 1];
        const __nv_bfloat16* Bsb = Bs[kc & 1];

        #pragma unroll
        for (int kk = 0; kk < 2; kk++) {
            uint32_t af[2][4], bf[4][4];
            #pragma unroll
            for (int i = 0; i < 2; i++) {
                int row = warp_m * 32 + i * 16 + (lane & 15);
                int ch = kk * 2 + (lane >> 4);
                LDM4(af[i], Asb + row * 32 + SWZ(row, ch) * 8);
            }
            #pragma unroll
            for (int g = 0; g < 4; g++) {
                int row = warp_n * 64 + g * 16 + (lane & 7) + ((lane >> 4) << 3);
                int ch = kk * 2 + ((lane >> 3) & 1);
                LDM4(bf[g], Bsb + row * 32 + SWZ(row, ch) * 8);
            }
            #pragma unroll
            for (int i = 0; i < 2; i++)
                #pragma unroll
                for (int g = 0; g < 4; g++) {
                    MMA16816(c[i][g][0], af[i], bf[g][0], bf[g][1]);
                    MMA16816(c[i][g][1], af[i], bf[g][2], bf[g][3]);
                }
        }
        __syncthreads();
    }

    float* dst = (which == 0) ? g_Q : (which == 1) ? g_K : (which == 2) ? g_V : ext_out;
    #pragma unroll
    for (int i = 0; i < 2; i++)
        #pragma unroll
        for (int g = 0; g < 4; g++)
            #pragma unroll
            for (int j = 0; j < 2; j++) {
                int rr = m0 + warp_m * 32 + i * 16 + (lane >> 2);
                int cc = n0 + warp_n * 64 + g * 16 + j * 8 + ((lane & 3) << 1);
                float2 v0 = make_float2(c[i][g][j][0], c[i][g][j][1]);
                float2 v1 = make_float2(c[i][g][j][2], c[i][g][j][3]);
                if (which < 3) {
                    int b = rr >> 11, t = rr & 2047;
                    int hh = cc >> 6, s2 = cc & 63;
                    float* p0 = dst + (((size_t)(b * HH + hh) * TT) + t) * SS + s2;
                    float* p1 = dst + (((size_t)(b * HH + hh) * TT) + t + 8) * SS + s2;
                    *(float2*)p0 = v0;
                    *(float2*)p1 = v1;
                } else {
                    *(float2*)(dst + (size_t)rr * DD + cc) = v0;
                    *(float2*)(dst + (size_t)(rr + 8) * DD + cc) = v1;
                }
            }
}

// ---------------- tensor-core flash attention ----------------
#define CLOG2E 0.18033688011112042f   // 0.125 * log2(e)
#define SWZ8(row, ch) (((ch) ^ ((row) & 7)) << 3)

// load 64x64 fp32 row-major tile -> swizzled bf16 hi/lo (truncation split)
__device__ __forceinline__ void load_rm_split(const float* __restrict__ src,
                                              __nv_bfloat16* hb, __nv_bfloat16* lb, int tid) {
    #pragma unroll
    for (int it = 0; it < 8; it++) {
        int row = (tid >> 4) + it * 8;
        int s0 = (tid & 15) * 4;
        float4 v = *(const float4*)(src + row * 64 + s0);
        uint32_t ux = __float_as_uint(v.x), uy = __float_as_uint(v.y);
        uint32_t uz = __float_as_uint(v.z), uw = __float_as_uint(v.w);
        uint32_t h01 = prmt_hi(ux, uy), h23 = prmt_hi(uz, uw);
        float lx = v.x - __uint_as_float(ux & 0xffff0000u);
        float ly = v.y - __uint_as_float(uy & 0xffff0000u);
        float lz = v.z - __uint_as_float(uz & 0xffff0000u);
        float lw = v.w - __uint_as_float(uw & 0xffff0000u);
        uint32_t l01 = pack_bf16x2(lx, ly), l23 = pack_bf16x2(lz, lw);
        int off = row * 64 + SWZ8(row, s0 >> 3) + (s0 & 7);
        *(uint32_t*)&hb[off] = h01; *(uint32_t*)&hb[off + 2] = h23;
        *(uint32_t*)&lb[off] = l01; *(uint32_t*)&lb[off + 2] = l23;
    }
}

// load 64x64 fp32 [key][s] tile -> transposed [s][key] swizzled bf16 hi/lo
__device__ __forceinline__ void load_tr_split(const float* __restrict__ src,
                                              __nv_bfloat16* hb, __nv_bfloat16* lb, int tid) {
    #pragma unroll
    for (int it = 0; it < 4; it++) {
        int k0 = (((tid >> 4) + it * 8) << 1);
        int s0 = (tid & 15) * 4;
        float4 a = *(const float4*)(src + k0 * 64 + s0);
        float4 b = *(const float4*)(src + (k0 + 1) * 64 + s0);
        float av[4] = {a.x, a.y, a.z, a.w};
        float bv[4] = {b.x, b.y, b.z, b.w};
        #pragma unroll
        for (int e = 0; e < 4; e++) {
            uint32_t ua = __float_as_uint(av[e]), ub = __float_as_uint(bv[e]);
            uint32_t h = prmt_hi(ua, ub);
            float la = av[e] - __uint_as_float(ua & 0xffff0000u);
            float lbv = bv[e] - __uint_as_float(ub & 0xffff0000u);
            uint32_t l = pack_bf16x2(la, lbv);
            int srow = s0 + e;
            int off = srow * 64 + SWZ8(srow, k0 >> 3) + (k0 & 7);
            *(uint32_t*)&hb[off] = h;
            *(uint32_t*)&lb[off] = l;
        }
    }
}

__global__ __launch_bounds__(128) void attn_tc_kernel() {
    __shared__ alignas(16) __nv_bfloat16 Qh[64*64], Ql[64*64];
    __shared__ alignas(16) __nv_bfloat16 Kh[64*64], Kl[64*64];
    __shared__ alignas(16) __nv_bfloat16 Vh[64*64], Vl[64*64];

    const int tid = threadIdx.x, lane = tid & 31, warp = tid >> 5;
    const int qt = blockIdx.x, bh = blockIdx.y;

    const float* Qg = g_Q + ((size_t)bh * TT + qt * 64) * SS;
    const float* Kg = g_K + (size_t)bh * TT * SS;
    const float* Vg = g_V + (size_t)bh * TT * SS;

    load_rm_split(Qg, Qh, Ql, tid);
    __syncthreads();

    // Q A-fragments (persist across all k-tiles)
    uint32_t qh[4][4], ql[4][4];
    {
        int row = warp * 16 + (lane & 15);
        #pragma unroll
        for (int kk = 0; kk < 4; kk++) {
            int ch = kk * 2 + (lane >> 4);
            LDM4(qh[kk], &Qh[row * 64 + SWZ8(row, ch)]);
            LDM4(ql[kk], &Ql[row * 64 + SWZ8(row, ch)]);
        }
    }

    float oc[8][4];
    #pragma unroll
    for (int j = 0; j < 8; j++)
        #pragma unroll
        for (int q = 0; q < 4; q++) oc[j][q] = 0.0f;
    float m0 = -1e30f, m1 = -1e30f, l0 = 0.0f, l1 = 0.0f;

    const int rg = lane >> 2;
    const int brow = (lane & 7) + ((lane >> 4) << 3);   // ldmatrix B row pattern
    const int bchx = (lane >> 3) & 1;

    for (int kt = 0; kt <= qt; kt++) {
        __syncthreads();
        load_rm_split(Kg + (size_t)kt * 64 * SS, Kh, Kl, tid);
        load_tr_split(Vg + (size_t)kt * 64 * SS, Vh, Vl, tid);
        __syncthreads();

        // ---- S = Q K^T (3-term split) ----
        float sc[8][4];
        #pragma unroll
        for (int j = 0; j < 8; j++)
            #pragma unroll
            for (int q = 0; q < 4; q++) sc[j][q] = 0.0f;

        #pragma unroll
        for (int g = 0; g < 4; g++) {
            int row = g * 16 + brow;
            #pragma unroll
            for (int kk = 0; kk < 4; kk++) {
                int ch = kk * 2 + bchx;
                uint32_t bh4[4], bl4[4];
                LDM4(bh4, &Kh[row * 64 + SWZ8(row, ch)]);
                MMA16816(sc[2*g],   qh[kk], bh4[0], bh4[1]);
                MMA16816(sc[2*g+1], qh[kk], bh4[2], bh4[3]);
                MMA16816(sc[2*g],   ql[kk], bh4[0], bh4[1]);
                MMA16816(sc[2*g+1], ql[kk], bh4[2], bh4[3]);
                LDM4(bl4, &Kl[row * 64 + SWZ8(row, ch)]);
                MMA16816(sc[2*g],   qh[kk], bl4[0], bl4[1]);
                MMA16816(sc[2*g+1], qh[kk], bl4[2], bl4[3]);
            }
        }

        // ---- softmax (exp2 poly on fma/alu; bias via table) ----
        float mx0 = -1e30f, mx1 = -1e30f;
        #pragma unroll
        for (int j = 0; j < 8; j++) {
            mx0 = fmaxf(mx0, fmaxf(sc[j][0], sc[j][1]));
            mx1 = fmaxf(mx1, fmaxf(sc[j][2], sc[j][3]));
        }
        mx0 = fmaxf(mx0, __shfl_xor_sync(0xffffffffu, mx0, 1));
        mx0 = fmaxf(mx0, __shfl_xor_sync(0xffffffffu, mx0, 2));
        mx1 = fmaxf(mx1, __shfl_xor_sync(0xffffffffu, mx1, 1));
        mx1 = fmaxf(mx1, __shfl_xor_sync(0xffffffffu, mx1, 2));
        float mn0 = fmaxf(m0, mx0 * CLOG2E);
        float mn1 = fmaxf(m1, mx1 * CLOG2E);
        float a0 = exp2p(m0 - mn0), a1 = exp2p(m1 - mn1);
        m0 = mn0; m1 = mn1;

        int base0 = ((qt - kt) << 6) + 64 + warp * 16 + rg;
        int base1 = base0 + 8;
        int cb = (lane & 3) << 1;
        float ls0 = 0.0f, ls1 = 0.0f;
        #pragma unroll
        for (int j = 0; j < 8; j++) {
            int c0 = j * 8 + cb;
            float e0 = exp2p(fmaf(sc[j][0], CLOG2E, -mn0)) * __ldg(&g_ebias[base0 - c0]);
            float e1 = exp2p(fmaf(sc[j][1], CLOG2E, -mn0)) * __ldg(&g_ebias[base0 - c0 - 1]);
            float e2 = exp2p(fmaf(sc[j][2], CLOG2E, -mn1)) * __ldg(&g_ebias[base1 - c0]);
            float e3 = exp2p(fmaf(sc[j][3], CLOG2E, -mn1)) * __ldg(&g_ebias[base1 - c0 - 1]);
            sc[j][0] = e0; sc[j][1] = e1; sc[j][2] = e2; sc[j][3] = e3;
            ls0 += e0 + e1; ls1 += e2 + e3;
        }
        ls0 += __shfl_xor_sync(0xffffffffu, ls0, 1);
        ls0 += __shfl_xor_sync(0xffffffffu, ls0, 2);
        ls1 += __shfl_xor_sync(0xffffffffu, ls1, 1);
        ls1 += __shfl_xor_sync(0xffffffffu, ls1, 2);
        l0 = l0 * a0 + ls0;
        l1 = l1 * a1 + ls1;
        #pragma unroll
        for (int j = 0; j < 8; j++) {
            oc[j][0] *= a0; oc[j][1] *= a0; oc[j][2] *= a1; oc[j][3] *= a1;
        }

        // ---- repack P (C-frag -> A-frag, trunc hi + bf16 lo) ----
        uint32_t pah[4][4], pal[4][4];
        #pragma unroll
        for (int kk = 0; kk < 4; kk++) {
            #pragma unroll
            for (int half = 0; half < 2; half++) {
                int j = 2 * kk + half;
                uint32_t u0 = __float_as_uint(sc[j][0]), u1 = __float_as_uint(sc[j][1]);
                uint32_t u2 = __float_as_uint(sc[j][2]), u3 = __float_as_uint(sc[j][3]);
                pah[kk][half * 2]     = prmt_hi(u0, u1);
                pah[kk][half * 2 + 1] = prmt_hi(u2, u3);
                float p0 = sc[j][0] - __uint_as_float(u0 & 0xffff0000u);
                float p1 = sc[j][1] - __uint_as_float(u1 & 0xffff0000u);
                float p2 = sc[j][2] - __uint_as_float(u2 & 0xffff0000u);
                float p3 = sc[j][3] - __uint_as_float(u3 & 0xffff0000u);
                pal[kk][half * 2]     = pack_bf16x2(p0, p1);
                pal[kk][half * 2 + 1] = pack_bf16x2(p2, p3);
            }
        }

        // ---- O += P V (3-term split) ----
        #pragma unroll
        for (int g = 0; g < 4; g++) {
            int row = g * 16 + brow;
            #pragma unroll
            for (int kk = 0; kk < 4; kk++) {
                int ch = kk * 2 + bchx;
                uint32_t vh4[4], vl4[4];
                LDM4(vh4, &Vh[row * 64 + SWZ8(row, ch)]);
                MMA16816(oc[2*g],   pah[kk], vh4[0], vh4[1]);
                MMA16816(oc[2*g+1], pah[kk], vh4[2], vh4[3]);
                MMA16816(oc[2*g],   pal[kk], vh4[0], vh4[1]);
                MMA16816(oc[2*g+1], pal[kk], vh4[2], vh4[3]);
                LDM4(vl4, &Vl[row * 64 + SWZ8(row, ch)]);
                MMA16816(oc[2*g],   pah[kk], vl4[0], vl4[1]);
                MMA16816(oc[2*g+1], pah[kk], vl4[2], vl4[3]);
            }
        }
    }

    // ---- epilogue ----
    float inv0 = 1.0f / l0, inv1 = 1.0f / l1;
    int b = bh >> 4, hh = bh & 15;
    int t0 = qt * 64 + warp * 16 + rg;
    #pragma unroll
    for (int j = 0; j < 8; j++) {
        int s = j * 8 + ((lane & 3) << 1);
        float* p = g_attn + ((size_t)(b * TT + t0)) * DD + hh * 64 + s;
        *(float2*)p = make_float2(oc[j][0] * inv0, oc[j][1] * inv0);
        *(float2*)(p + 8 * DD) = make_float2(oc[j][2] * inv1, oc[j][3] * inv1);
    }
}

// ---------------- launch ----------------
extern "C" void kernel_launch(void* const* d_in, const int* in_sizes, int n_in,
                              void* d_out, int out_size) {
    const float* x   = (const float*)d_in[0];
    const float* wq  = (const float*)d_in[1];
    const float* wk  = (const float*)d_in[2];
    const float* wv  = (const float*)d_in[3];
    const float* wo  = (const float*)d_in[4];
    const float* wu  = (const float*)d_in[5];
    const float* wsv = (const float*)d_in[6];
    const float* ps  = (const float*)d_in[7];
    float* out = (float*)d_out;

    zero_absmax_kernel<<<1, 32>>>();
    absmax_kernel<<<256, 256>>>(wq, DD*DD, 0);
    absmax_kernel<<<256, 256>>>(wk, DD*DD, 1);
    absmax_kernel<<<256, 256>>>(wv, DD*DD, 2);
    absmax_kernel<<<256, 256>>>(wo, DD*DD, 3);
    absmax_kernel<<<16, 256>>>(wu, SS*SS, 4);
    absmax_kernel<<<16, 256>>>(wsv, SS*SS, 5);

    quant_kernel<<<512, 256>>>(wq, DD*DD, 0, 0);
    quant_kernel<<<512, 256>>>(wk, DD*DD, 1, 1);
    quant_kernel<<<512, 256>>>(wv, DD*DD, 2, 2);
    quant_kernel<<<512, 256>>>(wo, DD*DD, 3, 3);
    quant_kernel<<<16, 256>>>(wu, SS*SS, 4, 4);
    quant_kernel<<<16, 256>>>(wsv, SS*SS, 5, 5);

    compose_kernel<<<DD*DD/256, 256>>>(0);
    compose_kernel<<<DD*DD/256, 256>>>(1);
    build_ebias_kernel<<<9, 256>>>(ps);

    split_w_kernel<<<DD*DD/1024, 256>>>(0, 0);
    split_w_kernel<<<DD*DD/1024, 256>>>(1, 1);
    split_w_kernel<<<DD*DD/1024, 256>>>(2, 2);
    split_w_kernel<<<DD*DD/1024, 256>>>(3, 3);

    split_act_kernel<<<MM*DD/1024, 256>>>(x, 0);
    gemm_bf16_kernel<<<dim3(DD/128, MM/128, 3), 256>>>(nullptr, 0);

    attn_tc_kernel<<<dim3(TT/64, BB*HH), 128>>>();

    split_act_kernel<<<MM*DD/1024, 256>>>(nullptr, 1);
    gemm_bf16_kernel<<<dim3(DD/128, MM/128, 1), 256>>>(out, 3);
}

// round 4
// speedup vs baseline: 2.7235x; 1.1426x over previous
#include <cuda_runtime.h>
#include <cuda_bf16.h>
#include <cstdint>

#define BB 4
#define TT 2048
#define DD 1024
#define HH 16
#define SS 64
#define MM (BB*TT)
#define K3 3072          // [hi | lo | hi] segments of K=1024
#define EBN 2208         // ebias table size (index = d + 128)

// ---------------- device scratch (static, allocation-free) ----------------
__device__ float g_absmax[8];
__device__ float g_wq_q[DD*DD];
__device__ float g_wk_q[DD*DD];
__device__ float g_wq_eff[DD*DD];
__device__ float g_wk_eff[DD*DD];
__device__ float g_wv_q[DD*DD];
__device__ float g_wo_q[DD*DD];
__device__ float g_wu_q[SS*SS];
__device__ float g_wsv_q[SS*SS];
__device__ __nv_bfloat16 g_Qh[(size_t)BB*HH*TT*SS], g_Ql[(size_t)BB*HH*TT*SS];
__device__ __nv_bfloat16 g_Kh[(size_t)BB*HH*TT*SS], g_Kl[(size_t)BB*HH*TT*SS];
__device__ __nv_bfloat16 g_Vh[(size_t)BB*HH*TT*SS], g_Vl[(size_t)BB*HH*TT*SS];
__device__ __nv_bfloat16 g_A3[(size_t)MM*K3];       // split activations
__device__ __nv_bfloat16 g_W3[(size_t)4*DD*K3];     // split weights (q,k,v,o)
__device__ float g_ebias[EBN];

// ---------------- fused weight quantization ----------------
__global__ void zero_absmax_kernel() {
    if (threadIdx.x < 8) g_absmax[threadIdx.x] = 0.0f;
}

__global__ void absmax_all_kernel(const float* __restrict__ wq, const float* __restrict__ wk,
                                  const float* __restrict__ wv, const float* __restrict__ wo,
                                  const float* __restrict__ wu, const float* __restrict__ wsv) {
    int slot = blockIdx.y;
    const float* w = (slot == 0) ? wq : (slot == 1) ? wk : (slot == 2) ? wv
                   : (slot == 3) ? wo : (slot == 4) ? wu : wsv;
    int n = (slot < 4) ? DD * DD : SS * SS;
    float m = 0.0f;
    for (int i = blockIdx.x * blockDim.x + threadIdx.x; i < n; i += gridDim.x * blockDim.x)
        m = fmaxf(m, fabsf(w[i]));
    #pragma unroll
    for (int o = 16; o > 0; o >>= 1) m = fmaxf(m, __shfl_xor_sync(0xffffffffu, m, o));
    __shared__ float sm[8];
    int lane = threadIdx.x & 31, wid = threadIdx.x >> 5;
    if (lane == 0) sm[wid] = m;
    __syncthreads();
    if (wid == 0) {
        int nw = blockDim.x >> 5;
        m = (lane < nw) ? sm[lane] : 0.0f;
        #pragma unroll
        for (int o = 4; o > 0; o >>= 1) m = fmaxf(m, __shfl_xor_sync(0xffffffffu, m, o));
        if (lane == 0) atomicMax((int*)&g_absmax[slot], __float_as_int(m));
    }
}

__global__ void quant_all_kernel(const float* __restrict__ wq, const float* __restrict__ wk,
                                 const float* __restrict__ wv, const float* __restrict__ wo,
                                 const float* __restrict__ wu, const float* __restrict__ wsv) {
    int slot = blockIdx.y;
    const float* w = (slot == 0) ? wq : (slot == 1) ? wk : (slot == 2) ? wv
                   : (slot == 3) ? wo : (slot == 4) ? wu : wsv;
    float* out = (slot == 0) ? g_wq_q : (slot == 1) ? g_wk_q : (slot == 2) ? g_wv_q
               : (slot == 3) ? g_wo_q : (slot == 4) ? g_wu_q : g_wsv_q;
    int n = (slot < 4) ? DD * DD : SS * SS;
    float sc = g_absmax[slot] / 31.0f + 1e-8f;
    for (int i = blockIdx.x * blockDim.x + threadIdx.x; i < n; i += gridDim.x * blockDim.x) {
        float q = rintf(w[i] / sc);
        q = fminf(fmaxf(q, -31.0f), 31.0f);
        out[i] = q * sc;
    }
}

__global__ void compose_kernel() {
    int which = blockIdx.y;
    const float* wsmall = which ? g_wsv_q : g_wu_q;
    const float* wbig   = which ? g_wk_q  : g_wq_q;
    float* out          = which ? g_wk_eff : g_wq_eff;
    int idx = blockIdx.x * 256 + threadIdx.x;
    int row = idx >> 10, k = idx & 1023;
    int h = row >> 6, sp = row & 63;
    const float* bw = wbig + (size_t)(h << 6) * DD + k;
    const float* sw = wsmall + sp * SS;
    float acc = 0.0f;
    #pragma unroll 16
    for (int s = 0; s < SS; s++) acc += sw[s] * bw[(size_t)s * DD];
    out[idx] = acc;
}

// p-adic bias exp table: g_ebias[i] = (i<128) ? 0 : exp(pscale*bias(i-128))
__global__ void build_ebias_kernel(const float* __restrict__ ps) {
    int i = blockIdx.x * 256 + threadIdx.x;
    if (i >= EBN) return;
    float v = 0.0f;
    if (i >= 128 && i < 128 + 2048) {
        int d = i - 128;
        float bias = (d == 0) ? 1.0f : (float)min(__ffs(d) - 1, 16) * 0.0625f;
        v = __expf(ps[0] * bias);
    }
    g_ebias[i] = v;
}

// ---------------- hi/lo bf16 splits for the big GEMMs ----------------
__global__ void split_act_kernel(const float* __restrict__ src) {
    int i = blockIdx.x * 256 + threadIdx.x;
    int row = i >> 8;
    int k4 = (i & 255) * 4;
    float4 v = *(const float4*)(src + (size_t)row * DD + k4);
    __nv_bfloat16 h0 = __float2bfloat16(v.x), h1 = __float2bfloat16(v.y);
    __nv_bfloat16 h2 = __float2bfloat16(v.z), h3 = __float2bfloat16(v.w);
    __nv_bfloat16 l0 = __float2bfloat16(v.x - __bfloat162float(h0));
    __nv_bfloat16 l1 = __float2bfloat16(v.y - __bfloat162float(h1));
    __nv_bfloat16 l2 = __float2bfloat16(v.z - __bfloat162float(h2));
    __nv_bfloat16 l3 = __float2bfloat16(v.w - __bfloat162float(h3));
    __nv_bfloat16* o = g_A3 + (size_t)row * K3 + k4;
    *(__nv_bfloat162*)(o)          = __nv_bfloat162(h0, h1);
    *(__nv_bfloat162*)(o + 2)      = __nv_bfloat162(h2, h3);
    *(__nv_bfloat162*)(o + 1024)   = __nv_bfloat162(l0, l1);
    *(__nv_bfloat162*)(o + 1026)   = __nv_bfloat162(l2, l3);
    *(__nv_bfloat162*)(o + 2048)   = __nv_bfloat162(h0, h1);
    *(__nv_bfloat162*)(o + 2050)   = __nv_bfloat162(h2, h3);
}

__global__ void split_w_kernel() {
    int dst = blockIdx.y;
    const float* src = (dst == 0) ? g_wq_eff : (dst == 1) ? g_wk_eff
                     : (dst == 2) ? g_wv_q   : g_wo_q;
    int i = blockIdx.x * 256 + threadIdx.x;
    int row = i >> 8;
    int k4 = (i & 255) * 4;
    float4 v = *(const float4*)(src + (size_t)row * DD + k4);
    __nv_bfloat16 h0 = __float2bfloat16(v.x), h1 = __float2bfloat16(v.y);
    __nv_bfloat16 h2 = __float2bfloat16(v.z), h3 = __float2bfloat16(v.w);
    __nv_bfloat16 l0 = __float2bfloat16(v.x - __bfloat162float(h0));
    __nv_bfloat16 l1 = __float2bfloat16(v.y - __bfloat162float(h1));
    __nv_bfloat16 l2 = __float2bfloat16(v.z - __bfloat162float(h2));
    __nv_bfloat16 l3 = __float2bfloat16(v.w - __bfloat162float(h3));
    __nv_bfloat16* o = g_W3 + (size_t)dst * DD * K3 + (size_t)row * K3 + k4;
    *(__nv_bfloat162*)(o)          = __nv_bfloat162(h0, h1);
    *(__nv_bfloat162*)(o + 2)      = __nv_bfloat162(h2, h3);
    *(__nv_bfloat162*)(o + 1024)   = __nv_bfloat162(h0, h1);
    *(__nv_bfloat162*)(o + 1026)   = __nv_bfloat162(h2, h3);
    *(__nv_bfloat162*)(o + 2048)   = __nv_bfloat162(l0, l1);
    *(__nv_bfloat162*)(o + 2050)   = __nv_bfloat162(l2, l3);
}

// ---------------- common PTX helpers ----------------
__device__ __forceinline__ void cp16(void* dst, const void* src) {
    unsigned d = (unsigned)__cvta_generic_to_shared(dst);
    asm volatile("cp.async.cg.shared.global [%0], [%1], 16;\n" :: "r"(d), "l"(src));
}

#define LDM4(R, PTR) do { \
    unsigned _a = (unsigned)__cvta_generic_to_shared(PTR); \
    asm volatile("ldmatrix.sync.aligned.m8n8.x4.shared.b16 {%0,%1,%2,%3}, [%4];" \
        : "=r"((R)[0]), "=r"((R)[1]), "=r"((R)[2]), "=r"((R)[3]) : "r"(_a)); \
} while (0)

#define LDM4T(R, PTR) do { \
    unsigned _a = (unsigned)__cvta_generic_to_shared(PTR); \
    asm volatile("ldmatrix.sync.aligned.m8n8.x4.trans.shared.b16 {%0,%1,%2,%3}, [%4];" \
        : "=r"((R)[0]), "=r"((R)[1]), "=r"((R)[2]), "=r"((R)[3]) : "r"(_a)); \
} while (0)

#define MMA16816(C, A, B0, B1) \
    asm volatile("mma.sync.aligned.m16n8k16.row.col.f32.bf16.bf16.f32 " \
        "{%0,%1,%2,%3}, {%4,%5,%6,%7}, {%8,%9}, {%0,%1,%2,%3};" \
        : "+f"((C)[0]), "+f"((C)[1]), "+f"((C)[2]), "+f"((C)[3]) \
        : "r"((A)[0]), "r"((A)[1]), "r"((A)[2]), "r"((A)[3]), "r"(B0), "r"(B1))

#define SWZ(row, ch) ((ch) ^ (((row) >> 1) & 3))
#define SWZ8(row, ch) (((ch) ^ ((row) & 7)) << 3)

__device__ __forceinline__ uint32_t prmt_hi(uint32_t a, uint32_t b) {
    uint32_t r;
    asm("prmt.b32 %0, %1, %2, 0x7632;" : "=r"(r) : "r"(a), "r"(b));
    return r;
}
__device__ __forceinline__ uint32_t pack_bf16x2(float lo, float hi) {
    uint32_t r;
    asm("cvt.rn.bf16x2.f32 %0, %1, %2;" : "=r"(r) : "f"(hi), "f"(lo));
    return r;
}
// fast 2^y on fma/alu pipes, ~3e-6 rel err
__device__ __forceinline__ float exp2p(float y) {
    y = fmaxf(y, -125.0f);
    float z = y + 12582912.0f;
    float f = y - (z - 12582912.0f);
    int e = __float_as_int(z) << 23;
    float r = 0.0013333558146f;
    r = fmaf(r, f, 0.0096181291076f);
    r = fmaf(r, f, 0.055504108664f);
    r = fmaf(r, f, 0.24022650696f);
    r = fmaf(r, f, 0.69314718056f);
    r = fmaf(r, f, 1.0f);
    return __int_as_float(__float_as_int(r) + e);
}
// write hi/lo pair (truncation split) to separate arrays
__device__ __forceinline__ void emit_hl(__nv_bfloat16* dh, __nv_bfloat16* dl, float f0, float f1) {
    uint32_t u0 = __float_as_uint(f0), u1 = __float_as_uint(f1);
    *(uint32_t*)dh = prmt_hi(u0, u1);
    *(uint32_t*)dl = pack_bf16x2(f0 - __uint_as_float(u0 & 0xffff0000u),
                                 f1 - __uint_as_float(u1 & 0xffff0000u));
}
// write [hi|lo|hi] triple into an A3 row
__device__ __forceinline__ void store3(__nv_bfloat16* p, float f0, float f1) {
    uint32_t u0 = __float_as_uint(f0), u1 = __float_as_uint(f1);
    uint32_t hi = prmt_hi(u0, u1);
    uint32_t lo = pack_bf16x2(f0 - __uint_as_float(u0 & 0xffff0000u),
                              f1 - __uint_as_float(u1 & 0xffff0000u));
    *(uint32_t*)p = hi;
    *(uint32_t*)(p + 2048) = hi;
    *(uint32_t*)(p + 1024) = lo;
}

// ---------------- bf16 tensor-core GEMM:  C[M,N] = A3 @ W3^T ----------------
__global__ __launch_bounds__(256, 2) void gemm_bf16_kernel(float* __restrict__ ext_out,
                                                           int base_which) {
    __shared__ alignas(16) __nv_bfloat16 As[2][128 * 32];
    __shared__ alignas(16) __nv_bfloat16 Bs[2][128 * 32];

    const int which = base_which + blockIdx.z;
    const __nv_bfloat16* __restrict__ Wg = g_W3 + (size_t)which * DD * K3;
    const int tid = threadIdx.x;
    const int lane = tid & 31, wid = tid >> 5;
    const int warp_m = wid >> 1, warp_n = wid & 1;
    const int m0 = blockIdx.y * 128;
    const int n0 = blockIdx.x * 128;

    const __nv_bfloat16* Ag = g_A3 + (size_t)m0 * K3;
    const __nv_bfloat16* Bg = Wg + (size_t)n0 * K3;

    float c[2][4][2][4];
    #pragma unroll
    for (int i = 0; i < 2; i++)
        #pragma unroll
        for (int g = 0; g < 4; g++)
            #pragma unroll
            for (int j = 0; j < 2; j++)
                #pragma unroll
                for (int q = 0; q < 4; q++) c[i][g][j][q] = 0.0f;

    int ld_row[2], ld_ch[2];
    #pragma unroll
    for (int p = 0; p < 2; p++) {
        int e = tid + p * 256;
        ld_row[p] = e >> 2;
        ld_ch[p] = e & 3;
    }

    const int NC = K3 / 32;

    #pragma unroll
    for (int p = 0; p < 2; p++) {
        int row = ld_row[p], ch = ld_ch[p];
        int so = row * 32 + SWZ(row, ch) * 8;
        cp16(&As[0][so], Ag + (size_t)row * K3 + ch * 8);
        cp16(&Bs[0][so], Bg + (size_t)row * K3 + ch * 8);
    }
    asm volatile("cp.async.commit_group;");

    for (int kc = 0; kc < NC; kc++) {
        if (kc + 1 < NC) {
            int s = (kc + 1) & 1;
            int koff = (kc + 1) * 32;
            #pragma unroll
            for (int p = 0; p < 2; p++) {
                int row = ld_row[p], ch = ld_ch[p];
                int so = row * 32 + SWZ(row, ch) * 8;
                cp16(&As[s][so], Ag + (size_t)row * K3 + koff + ch * 8);
                cp16(&Bs[s][so], Bg + (size_t)row * K3 + koff + ch * 8);
            }
            asm volatile("cp.async.commit_group;");
            asm volatile("cp.async.wait_group 1;");
        } else {
            asm volatile("cp.async.wait_group 0;");
        }
        __syncthreads();

        const __nv_bfloat16* Asb = As[kc & 1];
        const __nv_bfloat16* Bsb = Bs[kc & 1];

        #pragma unroll
        for (int kk = 0; kk < 2; kk++) {
            uint32_t af[2][4], bf[4][4];
            #pragma unroll
            for (int i = 0; i < 2; i++) {
                int row = warp_m * 32 + i * 16 + (lane & 15);
                int ch = kk * 2 + (lane >> 4);
                LDM4(af[i], Asb + row * 32 + SWZ(row, ch) * 8);
            }
            #pragma unroll
            for (int g = 0; g < 4; g++) {
                int row = warp_n * 64 + g * 16 + (lane & 7) + ((lane >> 4) << 3);
                int ch = kk * 2 + ((lane >> 3) & 1);
                LDM4(bf[g], Bsb + row * 32 + SWZ(row, ch) * 8);
            }
            #pragma unroll
            for (int i = 0; i < 2; i++)
                #pragma unroll
                for (int g = 0; g < 4; g++) {
                    MMA16816(c[i][g][0], af[i], bf[g][0], bf[g][1]);
                    MMA16816(c[i][g][1], af[i], bf[g][2], bf[g][3]);
                }
        }
        __syncthreads();
    }

    // epilogue
    __nv_bfloat16* dh = (which == 0) ? g_Qh : (which == 1) ? g_Kh : g_Vh;
    __nv_bfloat16* dl = (which == 0) ? g_Ql : (which == 1) ? g_Kl : g_Vl;
    #pragma unroll
    for (int i = 0; i < 2; i++)
        #pragma unroll
        for (int g = 0; g < 4; g++)
            #pragma unroll
            for (int j = 0; j < 2; j++) {
                int rr = m0 + warp_m * 32 + i * 16 + (lane >> 2);
                int cc = n0 + warp_n * 64 + g * 16 + j * 8 + ((lane & 3) << 1);
                if (which < 3) {
                    int b = rr >> 11, t = rr & 2047;
                    int hh = cc >> 6, s2 = cc & 63;
                    size_t off = ((size_t)(b * HH + hh) * TT + t) * SS + s2;
                    emit_hl(dh + off, dl + off, c[i][g][j][0], c[i][g][j][1]);
                    emit_hl(dh + off + 8 * SS, dl + off + 8 * SS, c[i][g][j][2], c[i][g][j][3]);
                } else {
                    *(float2*)(ext_out + (size_t)rr * DD + cc) =
                        make_float2(c[i][g][j][0], c[i][g][j][1]);
                    *(float2*)(ext_out + (size_t)(rr + 8) * DD + cc) =
                        make_float2(c[i][g][j][2], c[i][g][j][3]);
                }
            }
}

// ---------------- tensor-core flash attention (128-row q tiles) ----------------
#define CLOG2E 0.18033688011112042f   // 0.125 * log2(e)

__global__ __launch_bounds__(256, 2) void attn_tc_kernel() {
    extern __shared__ __nv_bfloat16 smraw[];   // [2 stages][4 arrays][64*64]
    const int tid = threadIdx.x, lane = tid & 31, warp = tid >> 5;
    const int qt = blockIdx.x, bh = blockIdx.y;
    const size_t bhbase = (size_t)bh * TT * SS;

    // ---- stage Q (128x64 hi/lo) into stage0 via cp.async ----
    {
        int g = tid >> 6;   // 0,1: Qh rows 0-63/64-127; 2,3: Ql
        const __nv_bfloat16* src = ((g & 2) ? g_Ql : g_Qh) + bhbase
                                 + ((size_t)qt * 128 + (g & 1) * 64) * 64;
        __nv_bfloat16* dst = smraw + g * 4096;
        #pragma unroll
        for (int i = 0; i < 8; i++) {
            int ci = (tid & 63) + 64 * i;
            int r = ci >> 3, ch = ci & 7;
            cp16(&dst[r * 64 + SWZ8(r, ch)], src + r * 64 + ch * 8);
        }
    }
    asm volatile("cp.async.commit_group;");
    asm volatile("cp.async.wait_group 0;");
    __syncthreads();

    uint32_t qh[4][4], ql[4][4];
    {
        int r = warp * 16 + (lane & 15);
        int a = r >> 6, rl = r & 63;
        #pragma unroll
        for (int kk = 0; kk < 4; kk++) {
            int ch = kk * 2 + (lane >> 4);
            LDM4(qh[kk], smraw + a * 4096 + rl * 64 + SWZ8(r, ch));
            LDM4(ql[kk], smraw + (2 + a) * 4096 + rl * 64 + SWZ8(r, ch));
        }
    }
    __syncthreads();

    float oc[8][4];
    #pragma unroll
    for (int j = 0; j < 8; j++)
        #pragma unroll
        for (int q = 0; q < 4; q++) oc[j][q] = 0.0f;
    float m0 = -1e30f, m1 = -1e30f, l0 = 0.0f, l1 = 0.0f;

    const int rg = lane >> 2;
    const int cb = (lane & 3) << 1;
    const int brow = (lane & 7) + ((lane >> 4) << 3);
    const int bchx = (lane >> 3) & 1;
    const int vrow16 = ((lane >> 3) & 1) * 8 + (lane & 7);
    const int vchh = lane >> 4;
    const int ktmax = 2 * qt + 1;

    // K/V tile loader: g = tid>>6 selects {Kh,Kl,Vh,Vl}
    const int lg = tid >> 6;
    const __nv_bfloat16* lsrc0 = (lg == 0) ? g_Kh : (lg == 1) ? g_Kl : (lg == 2) ? g_Vh : g_Vl;

    #define LOAD_KV(KT, ST) do { \
        const __nv_bfloat16* _s = lsrc0 + bhbase + (size_t)(KT) * 64 * 64; \
        __nv_bfloat16* _d = smraw + ((ST) * 4 + lg) * 4096; \
        _Pragma("unroll") \
        for (int _i = 0; _i < 8; _i++) { \
            int _ci = (tid & 63) + 64 * _i; \
            int _r = _ci >> 3, _ch = _ci & 7; \
            cp16(&_d[_r * 64 + SWZ8(_r, _ch)], _s + _r * 64 + _ch * 8); \
        } \
        asm volatile("cp.async.commit_group;"); \
    } while (0)

    LOAD_KV(0, 0);

    for (int kt = 0; kt <= ktmax; kt++) {
        const int st = kt & 1;
        if (kt < ktmax) {
            LOAD_KV(kt + 1, st ^ 1);
            asm volatile("cp.async.wait_group 1;");
        } else {
            asm volatile("cp.async.wait_group 0;");
        }
        __syncthreads();

        if (qt * 128 + warp * 16 + 15 >= kt * 64) {   // warp has unmasked rows
            const __nv_bfloat16* Kh_ = smraw + (st * 4 + 0) * 4096;
            const __nv_bfloat16* Kl_ = smraw + (st * 4 + 1) * 4096;
            const __nv_bfloat16* Vh_ = smraw + (st * 4 + 2) * 4096;
            const __nv_bfloat16* Vl_ = smraw + (st * 4 + 3) * 4096;

            // ---- S = Q K^T (3-term) ----
            float sc[8][4];
            #pragma unroll
            for (int j = 0; j < 8; j++)
                #pragma unroll
                for (int q = 0; q < 4; q++) sc[j][q] = 0.0f;
            #pragma unroll
            for (int g = 0; g < 4; g++) {
                int row = g * 16 + brow;
                #pragma unroll
                for (int kk = 0; kk < 4; kk++) {
                    int ch = kk * 2 + bchx;
                    uint32_t bh4[4], bl4[4];
                    LDM4(bh4, &Kh_[row * 64 + SWZ8(row, ch)]);
                    MMA16816(sc[2*g],   qh[kk], bh4[0], bh4[1]);
                    MMA16816(sc[2*g+1], qh[kk], bh4[2], bh4[3]);
                    MMA16816(sc[2*g],   ql[kk], bh4[0], bh4[1]);
                    MMA16816(sc[2*g+1], ql[kk], bh4[2], bh4[3]);
                    LDM4(bl4, &Kl_[row * 64 + SWZ8(row, ch)]);
                    MMA16816(sc[2*g],   qh[kk], bl4[0], bl4[1]);
                    MMA16816(sc[2*g+1], qh[kk], bl4[2], bl4[3]);
                }
            }

            // ---- softmax ----
            float mx0 = -1e30f, mx1 = -1e30f;
            #pragma unroll
            for (int j = 0; j < 8; j++) {
                mx0 = fmaxf(mx0, fmaxf(sc[j][0], sc[j][1]));
                mx1 = fmaxf(mx1, fmaxf(sc[j][2], sc[j][3]));
            }
            mx0 = fmaxf(mx0, __shfl_xor_sync(0xffffffffu, mx0, 1));
            mx0 = fmaxf(mx0, __shfl_xor_sync(0xffffffffu, mx0, 2));
            mx1 = fmaxf(mx1, __shfl_xor_sync(0xffffffffu, mx1, 1));
            mx1 = fmaxf(mx1, __shfl_xor_sync(0xffffffffu, mx1, 2));
            float mn0 = fmaxf(m0, mx0 * CLOG2E);
            float mn1 = fmaxf(m1, mx1 * CLOG2E);
            float a0 = exp2p(m0 - mn0), a1 = exp2p(m1 - mn1);
            m0 = mn0; m1 = mn1;

            int base0 = qt * 128 + warp * 16 + rg - kt * 64 + 128;
            int base1 = base0 + 8;
            float ls0 = 0.0f, ls1 = 0.0f;
            #pragma unroll
            for (int j = 0; j < 8; j++) {
                int c0 = j * 8 + cb;
                float e0 = exp2p(fmaf(sc[j][0], CLOG2E, -mn0)) * __ldg(&g_ebias[base0 - c0]);
                float e1 = exp2p(fmaf(sc[j][1], CLOG2E, -mn0)) * __ldg(&g_ebias[base0 - c0 - 1]);
                float e2 = exp2p(fmaf(sc[j][2], CLOG2E, -mn1)) * __ldg(&g_ebias[base1 - c0]);
                float e3 = exp2p(fmaf(sc[j][3], CLOG2E, -mn1)) * __ldg(&g_ebias[base1 - c0 - 1]);
                sc[j][0] = e0; sc[j][1] = e1; sc[j][2] = e2; sc[j][3] = e3;
                ls0 += e0 + e1; ls1 += e2 + e3;
            }
            ls0 += __shfl_xor_sync(0xffffffffu, ls0, 1);
            ls0 += __shfl_xor_sync(0xffffffffu, ls0, 2);
            ls1 += __shfl_xor_sync(0xffffffffu, ls1, 1);
            ls1 += __shfl_xor_sync(0xffffffffu, ls1, 2);
            l0 = l0 * a0 + ls0;
            l1 = l1 * a1 + ls1;
            #pragma unroll
            for (int j = 0; j < 8; j++) {
                oc[j][0] *= a0; oc[j][1] *= a0; oc[j][2] *= a1; oc[j][3] *= a1;
            }

            // ---- repack P (C-frag -> A-frag) ----
            uint32_t pah[4][4], pal[4][4];
            #pragma unroll
            for (int kk = 0; kk < 4; kk++) {
                #pragma unroll
                for (int half = 0; half < 2; half++) {
                    int j = 2 * kk + half;
                    uint32_t u0 = __float_as_uint(sc[j][0]), u1 = __float_as_uint(sc[j][1]);
                    uint32_t u2 = __float_as_uint(sc[j][2]), u3 = __float_as_uint(sc[j][3]);
                    pah[kk][half * 2]     = prmt_hi(u0, u1);
                    pah[kk][half * 2 + 1] = prmt_hi(u2, u3);
                    float p0 = sc[j][0] - __uint_as_float(u0 & 0xffff0000u);
                    float p1 = sc[j][1] - __uint_as_float(u1 & 0xffff0000u);
                    float p2 = sc[j][2] - __uint_as_float(u2 & 0xffff0000u);
                    float p3 = sc[j][3] - __uint_as_float(u3 & 0xffff0000u);
                    pal[kk][half * 2]     = pack_bf16x2(p0, p1);
                    pal[kk][half * 2 + 1] = pack_bf16x2(p2, p3);
                }
            }

            // ---- O += P V (3-term; V row-major via ldmatrix.trans) ----
            #pragma unroll
            for (int g = 0; g < 4; g++) {
                int ch = 2 * g + vchh;
                #pragma unroll
                for (int kk = 0; kk < 4; kk++) {
                    int row = kk * 16 + vrow16;
                    uint32_t vh4[4], vl4[4];
                    LDM4T(vh4, &Vh_[row * 64 + SWZ8(row, ch)]);
                    MMA16816(oc[2*g],   pah[kk], vh4[0], vh4[1]);
                    MMA16816(oc[2*g+1], pah[kk], vh4[2], vh4[3]);
                    MMA16816(oc[2*g],   pal[kk], vh4[0], vh4[1]);
                    MMA16816(oc[2*g+1], pal[kk], vh4[2], vh4[3]);
                    LDM4T(vl4, &Vl_[row * 64 + SWZ8(row, ch)]);
                    MMA16816(oc[2*g],   pah[kk], vl4[0], vl4[1]);
                    MMA16816(oc[2*g+1], pah[kk], vl4[2], vl4[3]);
                }
            }
        }
        __syncthreads();
    }

    // ---- epilogue: write split [hi|lo|hi] rows of A3 directly ----
    float inv0 = 1.0f / l0, inv1 = 1.0f / l1;
    int b = bh >> 4, hh = bh & 15;
    int t0 = qt * 128 + warp * 16 + rg;
    __nv_bfloat16* rowp = g_A3 + (size_t)(b * TT + t0) * K3 + hh * 64 + cb;
    #pragma unroll
    for (int j = 0; j < 8; j++) {
        store3(rowp + j * 8, oc[j][0] * inv0, oc[j][1] * inv0);
        store3(rowp + (size_t)8 * K3 + j * 8, oc[j][2] * inv1, oc[j][3] * inv1);
    }
}

// ---------------- launch ----------------
extern "C" void kernel_launch(void* const* d_in, const int* in_sizes, int n_in,
                              void* d_out, int out_size) {
    const float* x   = (const float*)d_in[0];
    const float* wq  = (const float*)d_in[1];
    const float* wk  = (const float*)d_in[2];
    const float* wv  = (const float*)d_in[3];
    const float* wo  = (const float*)d_in[4];
    const float* wu  = (const float*)d_in[5];
    const float* wsv = (const float*)d_in[6];
    const float* ps  = (const float*)d_in[7];
    float* out = (float*)d_out;

    static int smem_set = 0;
    if (!smem_set) {
        cudaFuncSetAttribute(attn_tc_kernel, cudaFuncAttributeMaxDynamicSharedMemorySize, 65536);
        smem_set = 1;
    }

    zero_absmax_kernel<<<1, 32>>>();
    absmax_all_kernel<<<dim3(64, 6), 256>>>(wq, wk, wv, wo, wu, wsv);
    quant_all_kernel<<<dim3(64, 6), 256>>>(wq, wk, wv, wo, wu, wsv);
    compose_kernel<<<dim3(DD*DD/256, 2), 256>>>();
    build_ebias_kernel<<<9, 256>>>(ps);
    split_w_kernel<<<dim3(DD*DD/1024, 4), 256>>>();
    split_act_kernel<<<MM*DD/1024, 256>>>(x);
    gemm_bf16_kernel<<<dim3(DD/128, MM/128, 3), 256>>>(nullptr, 0);
    attn_tc_kernel<<<dim3(TT/128, BB*HH), 256, 65536>>>();
    gemm_bf16_kernel<<<dim3(DD/128, MM/128, 1), 256>>>(out, 3);
}

// round 7
// speedup vs baseline: 3.6899x; 1.3549x over previous
#include <cuda_runtime.h>
#include <cuda_bf16.h>
#include <cstdint>

#define BB 4
#define TT 2048
#define DD 1024
#define HH 16
#define SS 64
#define MM (BB*TT)
#define K3 3072          // [hi | lo | hi] segments of K=1024
#define EBN 2208         // ebias table size (index = d + 128)

// ---------------- device scratch (static, allocation-free) ----------------
__device__ float g_absmax[8];
__device__ __nv_bfloat16 g_Qh[(size_t)BB*HH*TT*SS];
__device__ __nv_bfloat16 g_Kh[(size_t)BB*HH*TT*SS];
__device__ __nv_bfloat16 g_Vh[(size_t)BB*HH*TT*SS], g_Vl[(size_t)BB*HH*TT*SS];
__device__ __nv_bfloat16 g_A3[(size_t)MM*K3];       // split activations (x, then attn out)
__device__ __nv_bfloat16 g_W3[(size_t)4*DD*K3];     // split weights (q,k,v,o)
__device__ float g_ebias[EBN];

// ---------------- prep ----------------
__global__ void zero_absmax_kernel() {
    if (threadIdx.x < 8) g_absmax[threadIdx.x] = 0.0f;
}

__global__ void absmax_all_kernel(const float* __restrict__ wq, const float* __restrict__ wk,
                                  const float* __restrict__ wv, const float* __restrict__ wo,
                                  const float* __restrict__ wu, const float* __restrict__ wsv) {
    int slot = blockIdx.y;
    const float* w = (slot == 0) ? wq : (slot == 1) ? wk : (slot == 2) ? wv
                   : (slot == 3) ? wo : (slot == 4) ? wu : wsv;
    int n = (slot < 4) ? DD * DD : SS * SS;
    float m = 0.0f;
    for (int i = blockIdx.x * blockDim.x + threadIdx.x; i < n; i += gridDim.x * blockDim.x)
        m = fmaxf(m, fabsf(w[i]));
    #pragma unroll
    for (int o = 16; o > 0; o >>= 1) m = fmaxf(m, __shfl_xor_sync(0xffffffffu, m, o));
    __shared__ float sm[8];
    int lane = threadIdx.x & 31, wid = threadIdx.x >> 5;
    if (lane == 0) sm[wid] = m;
    __syncthreads();
    if (wid == 0) {
        int nw = blockDim.x >> 5;
        m = (lane < nw) ? sm[lane] : 0.0f;
        #pragma unroll
        for (int o = 4; o > 0; o >>= 1) m = fmaxf(m, __shfl_xor_sync(0xffffffffu, m, o));
        if (lane == 0) atomicMax((int*)&g_absmax[slot], __float_as_int(m));
    }
}

__global__ void build_ebias_kernel(const float* __restrict__ ps) {
    int i = blockIdx.x * 256 + threadIdx.x;
    if (i >= EBN) return;
    float v = 0.0f;
    if (i >= 128 && i < 128 + 2048) {
        int d = i - 128;
        float bias = (d == 0) ? 1.0f : (float)min(__ffs(d) - 1, 16) * 0.0625f;
        v = __expf(ps[0] * bias);
    }
    g_ebias[i] = v;
}

// ---------------- PTX helpers ----------------
__device__ __forceinline__ void cp16(void* dst, const void* src) {
    unsigned d = (unsigned)__cvta_generic_to_shared(dst);
    asm volatile("cp.async.cg.shared.global [%0], [%1], 16;\n" :: "r"(d), "l"(src));
}
#define LDM4(R, PTR) do { \
    unsigned _a = (unsigned)__cvta_generic_to_shared(PTR); \
    asm volatile("ldmatrix.sync.aligned.m8n8.x4.shared.b16 {%0,%1,%2,%3}, [%4];" \
        : "=r"((R)[0]), "=r"((R)[1]), "=r"((R)[2]), "=r"((R)[3]) : "r"(_a)); \
} while (0)
#define LDM4T(R, PTR) do { \
    unsigned _a = (unsigned)__cvta_generic_to_shared(PTR); \
    asm volatile("ldmatrix.sync.aligned.m8n8.x4.trans.shared.b16 {%0,%1,%2,%3}, [%4];" \
        : "=r"((R)[0]), "=r"((R)[1]), "=r"((R)[2]), "=r"((R)[3]) : "r"(_a)); \
} while (0)
#define MMA16816(C, A, B0, B1) \
    asm volatile("mma.sync.aligned.m16n8k16.row.col.f32.bf16.bf16.f32 " \
        "{%0,%1,%2,%3}, {%4,%5,%6,%7}, {%8,%9}, {%0,%1,%2,%3};" \
        : "+f"((C)[0]), "+f"((C)[1]), "+f"((C)[2]), "+f"((C)[3]) \
        : "r"((A)[0]), "r"((A)[1]), "r"((A)[2]), "r"((A)[3]), "r"(B0), "r"(B1))
#define SWZ(row, ch) ((ch) ^ (((row) >> 1) & 3))
#define SWZ8(row, ch) (((ch) ^ ((row) & 7)) << 3)

__device__ __forceinline__ uint32_t prmt_hi(uint32_t a, uint32_t b) {
    uint32_t r;
    asm("prmt.b32 %0, %1, %2, 0x7632;" : "=r"(r) : "r"(a), "r"(b));
    return r;
}
__device__ __forceinline__ uint32_t pack_bf16x2(float lo, float hi) {
    uint32_t r;
    asm("cvt.rn.bf16x2.f32 %0, %1, %2;" : "=r"(r) : "f"(hi), "f"(lo));
    return r;
}
__device__ __forceinline__ float exp2p(float y) {   // fast 2^y, fma/alu only
    y = fmaxf(y, -125.0f);
    float z = y + 12582912.0f;
    float f = y - (z - 12582912.0f);
    int e = __float_as_int(z) << 23;
    float r = 0.0013333558146f;
    r = fmaf(r, f, 0.0096181291076f);
    r = fmaf(r, f, 0.055504108664f);
    r = fmaf(r, f, 0.24022650696f);
    r = fmaf(r, f, 0.69314718056f);
    r = fmaf(r, f, 1.0f);
    return __int_as_float(__float_as_int(r) + e);
}
__device__ __forceinline__ void emit_hl(__nv_bfloat16* dh, __nv_bfloat16* dl, float f0, float f1) {
    uint32_t u0 = __float_as_uint(f0), u1 = __float_as_uint(f1);
    *(uint32_t*)dh = prmt_hi(u0, u1);
    *(uint32_t*)dl = pack_bf16x2(f0 - __uint_as_float(u0 & 0xffff0000u),
                                 f1 - __uint_as_float(u1 & 0xffff0000u));
}
// [hi | lo | hi] into an A3-style row (stride 1024 between segments)
__device__ __forceinline__ void store3(__nv_bfloat16* p, float f0, float f1) {
    uint32_t u0 = __float_as_uint(f0), u1 = __float_as_uint(f1);
    uint32_t hi = prmt_hi(u0, u1);
    uint32_t lo = pack_bf16x2(f0 - __uint_as_float(u0 & 0xffff0000u),
                              f1 - __uint_as_float(u1 & 0xffff0000u));
    *(uint32_t*)p = hi;
    *(uint32_t*)(p + 2048) = hi;
    *(uint32_t*)(p + 1024) = lo;
}
// [hi | hi | lo] into a W3 row
__device__ __forceinline__ void storeW3(__nv_bfloat16* p, float f0, float f1) {
    uint32_t u0 = __float_as_uint(f0), u1 = __float_as_uint(f1);
    uint32_t hi = prmt_hi(u0, u1);
    uint32_t lo = pack_bf16x2(f0 - __uint_as_float(u0 & 0xffff0000u),
                              f1 - __uint_as_float(u1 & 0xffff0000u));
    *(uint32_t*)p = hi;
    *(uint32_t*)(p + 1024) = hi;
    *(uint32_t*)(p + 2048) = lo;
}
__device__ __forceinline__ float quant6(float w, float sc) {
    float q = rintf(w / sc);
    return fminf(fmaxf(q, -31.0f), 31.0f) * sc;
}

// ---------------- compose (stalk-fold) + quant + split, fused ----------------
// grid (8 kchunks, 16 heads, 2 which), 256 threads
__global__ __launch_bounds__(256) void compose_split_kernel(
        const float* __restrict__ wq, const float* __restrict__ wk,
        const float* __restrict__ wu, const float* __restrict__ wsv) {
    __shared__ float ws[64][64];
    __shared__ float wb[64][128];
    const int which = blockIdx.z, h = blockIdx.y, kc = blockIdx.x;
    const float* wsmall = which ? wsv : wu;
    const float* wbig   = which ? wk  : wq;
    const float scb = g_absmax[which ? 1 : 0] / 31.0f + 1e-8f;
    const float scs = g_absmax[which ? 5 : 4] / 31.0f + 1e-8f;
    const int tid = threadIdx.x;

    for (int idx = tid; idx < 4096; idx += 256)
        ws[idx >> 6][idx & 63] = quant6(wsmall[idx], scs);
    for (int idx = tid; idx < 8192; idx += 256) {
        int s = idx >> 7, k = idx & 127;
        wb[s][k] = quant6(wbig[(size_t)(h * 64 + s) * DD + kc * 128 + k], scb);
    }
    __syncthreads();

    const int tx = tid & 31, ty = tid >> 5;
    const int k0 = tx * 4, sp0 = ty * 8;
    float acc[8][4];
    #pragma unroll
    for (int i = 0; i < 8; i++)
        #pragma unroll
        for (int j = 0; j < 4; j++) acc[i][j] = 0.0f;
    #pragma unroll 8
    for (int s = 0; s < 64; s++) {
        float4 b = *(const float4*)&wb[s][k0];
        #pragma unroll
        for (int i = 0; i < 8; i++) {
            float a = ws[sp0 + i][s];
            acc[i][0] = fmaf(a, b.x, acc[i][0]);
            acc[i][1] = fmaf(a, b.y, acc[i][1]);
            acc[i][2] = fmaf(a, b.z, acc[i][2]);
            acc[i][3] = fmaf(a, b.w, acc[i][3]);
        }
    }
    __nv_bfloat16* o = g_W3 + (size_t)which * DD * K3;
    #pragma unroll
    for (int i = 0; i < 8; i++) {
        __nv_bfloat16* p = o + (size_t)(h * 64 + sp0 + i) * K3 + kc * 128 + k0;
        storeW3(p, acc[i][0], acc[i][1]);
        storeW3(p + 2, acc[i][2], acc[i][3]);
    }
}

// ---------------- wv/wo: quant + split (raw input) ----------------
__global__ void split_w_vo_kernel(const float* __restrict__ wv, const float* __restrict__ wo) {
    int dst = 2 + blockIdx.y;
    const float* src = blockIdx.y ? wo : wv;
    float sc = g_absmax[dst] / 31.0f + 1e-8f;
    int i = blockIdx.x * 256 + threadIdx.x;
    int row = i >> 8;
    int k4 = (i & 255) * 4;
    float4 v = *(const float4*)(src + (size_t)row * DD + k4);
    v.x = quant6(v.x, sc); v.y = quant6(v.y, sc);
    v.z = quant6(v.z, sc); v.w = quant6(v.w, sc);
    __nv_bfloat16* o = g_W3 + (size_t)dst * DD * K3 + (size_t)row * K3 + k4;
    storeW3(o, v.x, v.y);
    storeW3(o + 2, v.z, v.w);
}

// ---------------- x -> A3 [hi|lo|hi] ----------------
__global__ void split_act_kernel(const float* __restrict__ src) {
    int i = blockIdx.x * 256 + threadIdx.x;
    int row = i >> 8;
    int k4 = (i & 255) * 4;
    float4 v = *(const float4*)(src + (size_t)row * DD + k4);
    __nv_bfloat16* o = g_A3 + (size_t)row * K3 + k4;
    store3(o, v.x, v.y);
    store3(o + 2, v.z, v.w);
}

// ---------------- bf16 tensor-core GEMM:  C[M,N] = A3 @ W3^T ----------------
__global__ __launch_bounds__(256, 2) void gemm_bf16_kernel(float* __restrict__ ext_out,
                                                           int base_which, int nc) {
    __shared__ alignas(16) __nv_bfloat16 As[2][128 * 32];
    __shared__ alignas(16) __nv_bfloat16 Bs[2][128 * 32];

    const int which = base_which + blockIdx.z;
    const __nv_bfloat16* __restrict__ Wg = g_W3 + (size_t)which * DD * K3;
    const int tid = threadIdx.x;
    const int lane = tid & 31, wid = tid >> 5;
    const int warp_m = wid >> 1, warp_n = wid & 1;
    const int m0 = blockIdx.y * 128;
    const int n0 = blockIdx.x * 128;

    const __nv_bfloat16* Ag = g_A3 + (size_t)m0 * K3;
    const __nv_bfloat16* Bg = Wg + (size_t)n0 * K3;

    float c[2][4][2][4];
    #pragma unroll
    for (int i = 0; i < 2; i++)
        #pragma unroll
        for (int g = 0; g < 4; g++)
            #pragma unroll
            for (int j = 0; j < 2; j++)
                #pragma unroll
                for (int q = 0; q < 4; q++) c[i][g][j][q] = 0.0f;

    int ld_row[2], ld_ch[2];
    #pragma unroll
    for (int p = 0; p < 2; p++) {
        int e = tid + p * 256;
        ld_row[p] = e >> 2;
        ld_ch[p] = e & 3;
    }

    #pragma unroll
    for (int p = 0; p < 2; p++) {
        int row = ld_row[p], ch = ld_ch[p];
        int so = row * 32 + SWZ(row, ch) * 8;
        cp16(&As[0][so], Ag + (size_t)row * K3 + ch * 8);
        cp16(&Bs[0][so], Bg + (size_t)row * K3 + ch * 8);
    }
    asm volatile("cp.async.commit_group;");

    for (int kc = 0; kc < nc; kc++) {
        if (kc + 1 < nc) {
            int s = (kc + 1) & 1;
            int koff = (kc + 1) * 32;
            #pragma unroll
            for (int p = 0; p < 2; p++) {
                int row = ld_row[p], ch = ld_ch[p];
                int so = row * 32 + SWZ(row, ch) * 8;
                cp16(&As[s][so], Ag + (size_t)row * K3 + koff + ch * 8);
                cp16(&Bs[s][so], Bg + (size_t)row * K3 + koff + ch * 8);
            }
            asm volatile("cp.async.commit_group;");
            asm volatile("cp.async.wait_group 1;");
        } else {
            asm volatile("cp.async.wait_group 0;");
        }
        __syncthreads();

        const __nv_bfloat16* Asb = As[kc & 1];
        const __nv_bfloat16* Bsb = Bs[kc & 1];

        #pragma unroll
        for (int kk = 0; kk < 2; kk++) {
            uint32_t af[2][4], bf[4][4];
            #pragma unroll
            for (int i = 0; i < 2; i++) {
                int row = warp_m * 32 + i * 16 + (lane & 15);
                int ch = kk * 2 + (lane >> 4);
                LDM4(af[i], Asb + row * 32 + SWZ(row, ch) * 8);
            }
            #pragma unroll
            for (int g = 0; g < 4; g++) {
                int row = warp_n * 64 + g * 16 + (lane & 7) + ((lane >> 4) << 3);
                int ch = kk * 2 + ((lane >> 3) & 1);
                LDM4(bf[g], Bsb + row * 32 + SWZ(row, ch) * 8);
            }
            #pragma unroll
            for (int i = 0; i < 2; i++)
                #pragma unroll
                for (int g = 0; g < 4; g++) {
                    MMA16816(c[i][g][0], af[i], bf[g][0], bf[g][1]);
                    MMA16816(c[i][g][1], af[i], bf[g][2], bf[g][3]);
                }
        }
        __syncthreads();
    }

    // epilogue
    #pragma unroll
    for (int i = 0; i < 2; i++)
        #pragma unroll
        for (int g = 0; g < 4; g++)
            #pragma unroll
            for (int j = 0; j < 2; j++) {
                int rr = m0 + warp_m * 32 + i * 16 + (lane >> 2);
                int cc = n0 + warp_n * 64 + g * 16 + j * 8 + ((lane & 3) << 1);
                if (which < 2) {           // Q/K: hi only
                    __nv_bfloat16* dh = (which == 0) ? g_Qh : g_Kh;
                    int b = rr >> 11, t = rr & 2047;
                    int hh = cc >> 6, s2 = cc & 63;
                    size_t off = ((size_t)(b * HH + hh) * TT + t) * SS + s2;
                    *(uint32_t*)(dh + off) = prmt_hi(__float_as_uint(c[i][g][j][0]),
                                                     __float_as_uint(c[i][g][j][1]));
                    *(uint32_t*)(dh + off + 8 * SS) = prmt_hi(__float_as_uint(c[i][g][j][2]),
                                                              __float_as_uint(c[i][g][j][3]));
                } else if (which == 2) {   // V: hi + lo
                    int b = rr >> 11, t = rr & 2047;
                    int hh = cc >> 6, s2 = cc & 63;
                    size_t off = ((size_t)(b * HH + hh) * TT + t) * SS + s2;
                    emit_hl(g_Vh + off, g_Vl + off, c[i][g][j][0], c[i][g][j][1]);
                    emit_hl(g_Vh + off + 8 * SS, g_Vl + off + 8 * SS, c[i][g][j][2], c[i][g][j][3]);
                } else {                   // final output fp32
                    *(float2*)(ext_out + (size_t)rr * DD + cc) =
                        make_float2(c[i][g][j][0], c[i][g][j][1]);
                    *(float2*)(ext_out + (size_t)(rr + 8) * DD + cc) =
                        make_float2(c[i][g][j][2], c[i][g][j][3]);
                }
            }
}

// ---------------- tensor-core flash attention (128-row q tiles) ----------------
#define CLOG2E 0.18033688011112042f   // 0.125 * log2(e)

__global__ __launch_bounds__(256, 2) void attn_tc_kernel() {
    extern __shared__ __nv_bfloat16 smraw[];   // [2 stages][3 arrays: Kh,Vh,Vl][64*64]
    const int tid = threadIdx.x, lane = tid & 31, warp = tid >> 5;
    const int qt = blockIdx.x, bh = blockIdx.y;
    const size_t bhbase = (size_t)bh * TT * SS;

    // ---- stage Q hi (128x64 = 1024 x 16B) into arrays 0,1 ----
    {
        const __nv_bfloat16* src = g_Qh + bhbase + (size_t)qt * 128 * 64;
        #pragma unroll
        for (int i = 0; i < 4; i++) {                 // 4 iters = 1024 chunks
            int idx = tid + 256 * i;                  // 0..1023
            int r = idx >> 3, ch = idx & 7;           // r in [0,128)
            int a = r >> 6, rl = r & 63;
            cp16(smraw + a * 4096 + rl * 64 + SWZ8(rl, ch), src + r * 64 + ch * 8);
        }
    }
    asm volatile("cp.async.commit_group;");
    asm volatile("cp.async.wait_group 0;");
    __syncthreads();

    uint32_t qh[4][4];
    {
        int r = warp * 16 + (lane & 15);
        int a = r >> 6, rl = r & 63;
        #pragma unroll
        for (int kk = 0; kk < 4; kk++) {
            int ch = kk * 2 + (lane >> 4);
            LDM4(qh[kk], smraw + a * 4096 + rl * 64 + SWZ8(rl, ch));
        }
    }
    __syncthreads();

    float oc[8][4];
    #pragma unroll
    for (int j = 0; j < 8; j++)
        #pragma unroll
        for (int q = 0; q < 4; q++) oc[j][q] = 0.0f;
    float m0 = -1e30f, m1 = -1e30f, l0 = 0.0f, l1 = 0.0f;

    const int rg = lane >> 2;
    const int cb = (lane & 3) << 1;
    const int brow = (lane & 7) + ((lane >> 4) << 3);
    const int bchx = (lane >> 3) & 1;
    const int vrow16 = ((lane >> 3) & 1) * 8 + (lane & 7);
    const int vchh = lane >> 4;
    const int ktmax = 2 * qt + 1;

    const __nv_bfloat16* kvsrc[3] = {g_Kh + bhbase, g_Vh + bhbase, g_Vl + bhbase};

    #define LOAD_KV(KT, ST) do { \
        _Pragma("unroll") \
        for (int _i = 0; _i < 6; _i++) { \
            int _g = tid + 256 * _i;           /* 0..1535 */ \
            int _arr = _g >> 9, _idx = _g & 511; \
            int _r = _idx >> 3, _ch = _idx & 7; \
            cp16(smraw + ((ST) * 3 + _arr) * 4096 + _r * 64 + SWZ8(_r, _ch), \
                 kvsrc[_arr] + (size_t)(KT) * 4096 + _r * 64 + _ch * 8); \
        } \
        asm volatile("cp.async.commit_group;"); \
    } while (0)

    LOAD_KV(0, 0);

    for (int kt = 0; kt <= ktmax; kt++) {
        const int st = kt & 1;
        if (kt < ktmax) {
            LOAD_KV(kt + 1, st ^ 1);
            asm volatile("cp.async.wait_group 1;");
        } else {
            asm volatile("cp.async.wait_group 0;");
        }
        __syncthreads();

        if (qt * 128 + warp * 16 + 15 >= kt * 64) {
            const __nv_bfloat16* Kh_ = smraw + (st * 3 + 0) * 4096;
            const __nv_bfloat16* Vh_ = smraw + (st * 3 + 1) * 4096;
            const __nv_bfloat16* Vl_ = smraw + (st * 3 + 2) * 4096;

            // ---- S = Q K^T (1-term bf16) ----
            float sc[8][4];
            #pragma unroll
            for (int j = 0; j < 8; j++)
                #pragma unroll
                for (int q = 0; q < 4; q++) sc[j][q] = 0.0f;
            #pragma unroll
            for (int g = 0; g < 4; g++) {
                int row = g * 16 + brow;
                #pragma unroll
                for (int kk = 0; kk < 4; kk++) {
                    int ch = kk * 2 + bchx;
                    uint32_t bh4[4];
                    LDM4(bh4, &Kh_[row * 64 + SWZ8(row, ch)]);
                    MMA16816(sc[2*g],   qh[kk], bh4[0], bh4[1]);
                    MMA16816(sc[2*g+1], qh[kk], bh4[2], bh4[3]);
                }
            }

            // ---- softmax ----
            float mx0 = -1e30f, mx1 = -1e30f;
            #pragma unroll
            for (int j = 0; j < 8; j++) {
                mx0 = fmaxf(mx0, fmaxf(sc[j][0], sc[j][1]));
                mx1 = fmaxf(mx1, fmaxf(sc[j][2], sc[j][3]));
            }
            mx0 = fmaxf(mx0, __shfl_xor_sync(0xffffffffu, mx0, 1));
            mx0 = fmaxf(mx0, __shfl_xor_sync(0xffffffffu, mx0, 2));
            mx1 = fmaxf(mx1, __shfl_xor_sync(0xffffffffu, mx1, 1));
            mx1 = fmaxf(mx1, __shfl_xor_sync(0xffffffffu, mx1, 2));
            float mn0 = fmaxf(m0, mx0 * CLOG2E);
            float mn1 = fmaxf(m1, mx1 * CLOG2E);
            float a0 = exp2p(m0 - mn0), a1 = exp2p(m1 - mn1);
            m0 = mn0; m1 = mn1;

            int base0 = qt * 128 + warp * 16 + rg - kt * 64 + 128;
            int base1 = base0 + 8;
            float ls0 = 0.0f, ls1 = 0.0f;
            #pragma unroll
            for (int j = 0; j < 8; j++) {
                int c0 = j * 8 + cb;
                float e0 = exp2p(fmaf(sc[j][0], CLOG2E, -mn0)) * __ldg(&g_ebias[base0 - c0]);
                float e1 = exp2p(fmaf(sc[j][1], CLOG2E, -mn0)) * __ldg(&g_ebias[base0 - c0 - 1]);
                float e2 = exp2p(fmaf(sc[j][2], CLOG2E, -mn1)) * __ldg(&g_ebias[base1 - c0]);
                float e3 = exp2p(fmaf(sc[j][3], CLOG2E, -mn1)) * __ldg(&g_ebias[base1 - c0 - 1]);
                sc[j][0] = e0; sc[j][1] = e1; sc[j][2] = e2; sc[j][3] = e3;
                ls0 += e0 + e1; ls1 += e2 + e3;
            }
            ls0 += __shfl_xor_sync(0xffffffffu, ls0, 1);
            ls0 += __shfl_xor_sync(0xffffffffu, ls0, 2);
            ls1 += __shfl_xor_sync(0xffffffffu, ls1, 1);
            ls1 += __shfl_xor_sync(0xffffffffu, ls1, 2);
            l0 = l0 * a0 + ls0;
            l1 = l1 * a1 + ls1;
            #pragma unroll
            for (int j = 0; j < 8; j++) {
                oc[j][0] *= a0; oc[j][1] *= a0; oc[j][2] *= a1; oc[j][3] *= a1;
            }

            // ---- repack P (C-frag -> A-frag, hi/lo) ----
            uint32_t pah[4][4], pal[4][4];
            #pragma unroll
            for (int kk = 0; kk < 4; kk++) {
                #pragma unroll
                for (int half = 0; half < 2; half++) {
                    int j = 2 * kk + half;
                    uint32_t u0 = __float_as_uint(sc[j][0]), u1 = __float_as_uint(sc[j][1]);
                    uint32_t u2 = __float_as_uint(sc[j][2]), u3 = __float_as_uint(sc[j][3]);
                    pah[kk][half * 2]     = prmt_hi(u0, u1);
                    pah[kk][half * 2 + 1] = prmt_hi(u2, u3);
                    float p0 = sc[j][0] - __uint_as_float(u0 & 0xffff0000u);
                    float p1 = sc[j][1] - __uint_as_float(u1 & 0xffff0000u);
                    float p2 = sc[j][2] - __uint_as_float(u2 & 0xffff0000u);
                    float p3 = sc[j][3] - __uint_as_float(u3 & 0xffff0000u);
                    pal[kk][half * 2]     = pack_bf16x2(p0, p1);
                    pal[kk][half * 2 + 1] = pack_bf16x2(p2, p3);
                }
            }

            // ---- O += P V (3-term; V row-major via ldmatrix.trans) ----
            #pragma unroll
            for (int g = 0; g < 4; g++) {
                int ch = 2 * g + vchh;
                #pragma unroll
                for (int kk = 0; kk < 4; kk++) {
                    int row = kk * 16 + vrow16;
                    uint32_t vh4[4], vl4[4];
                    LDM4T(vh4, &Vh_[row * 64 + SWZ8(row, ch)]);
                    MMA16816(oc[2*g],   pah[kk], vh4[0], vh4[1]);
                    MMA16816(oc[2*g+1], pah[kk], vh4[2], vh4[3]);
                    MMA16816(oc[2*g],   pal[kk], vh4[0], vh4[1]);
                    MMA16816(oc[2*g+1], pal[kk], vh4[2], vh4[3]);
                    LDM4T(vl4, &Vl_[row * 64 + SWZ8(row, ch)]);
                    MMA16816(oc[2*g],   pah[kk], vl4[0], vl4[1]);
                    MMA16816(oc[2*g+1], pah[kk], vl4[2], vl4[3]);
                }
            }
        }
        __syncthreads();
    }

    // ---- epilogue: write split [hi|lo|hi] rows of A3 directly ----
    float inv0 = 1.0f / l0, inv1 = 1.0f / l1;
    int b = bh >> 4, hh = bh & 15;
    int t0 = qt * 128 + warp * 16 + rg;
    __nv_bfloat16* rowp = g_A3 + (size_t)(b * TT + t0) * K3 + hh * 64 + cb;
    #pragma unroll
    for (int j = 0; j < 8; j++) {
        store3(rowp + j * 8, oc[j][0] * inv0, oc[j][1] * inv0);
        store3(rowp + (size_t)8 * K3 + j * 8, oc[j][2] * inv1, oc[j][3] * inv1);
    }
}

// ---------------- launch ----------------
extern "C" void kernel_launch(void* const* d_in, const int* in_sizes, int n_in,
                              void* d_out, int out_size) {
    const float* x   = (const float*)d_in[0];
    const float* wq  = (const float*)d_in[1];
    const float* wk  = (const float*)d_in[2];
    const float* wv  = (const float*)d_in[3];
    const float* wo  = (const float*)d_in[4];
    const float* wu  = (const float*)d_in[5];
    const float* wsv = (const float*)d_in[6];
    const float* ps  = (const float*)d_in[7];
    float* out = (float*)d_out;

    static int smem_set = 0;
    if (!smem_set) {
        cudaFuncSetAttribute(attn_tc_kernel, cudaFuncAttributeMaxDynamicSharedMemorySize, 49152);
        smem_set = 1;
    }

    zero_absmax_kernel<<<1, 32>>>();
    absmax_all_kernel<<<dim3(64, 6), 256>>>(wq, wk, wv, wo, wu, wsv);
    build_ebias_kernel<<<9, 256>>>(ps);
    compose_split_kernel<<<dim3(8, 16, 2), 256>>>(wq, wk, wu, wsv);
    split_w_vo_kernel<<<dim3(DD*DD/1024, 2), 256>>>(wv, wo);
    split_act_kernel<<<MM*DD/1024, 256>>>(x);
    gemm_bf16_kernel<<<dim3(DD/128, MM/128, 2), 256>>>(nullptr, 0, 32);   // Q,K: 1-term
    gemm_bf16_kernel<<<dim3(DD/128, MM/128, 1), 256>>>(nullptr, 2, 96);   // V: 3-term
    attn_tc_kernel<<<dim3(TT/128, BB*HH), 256, 49152>>>();
    gemm_bf16_kernel<<<dim3(DD/128, MM/128, 1), 256>>>(out, 3, 96);       // O: 3-term
}

// round 10
// speedup vs baseline: 4.1659x; 1.1290x over previous
#include <cuda_runtime.h>
#include <cuda_bf16.h>
#include <cstdint>

#define BB 4
#define TT 2048
#define DD 1024
#define HH 16
#define SS 64
#define MM (BB*TT)
#define K3 3072          // [hi | lo | hi] segments of K=1024
#define EBN 2208         // ebias table size (index = d + 128)

// ---------------- device scratch (static, allocation-free) ----------------
__device__ float g_absmax[8];
__device__ __nv_bfloat16 g_Qh[(size_t)BB*HH*TT*SS];
__device__ __nv_bfloat16 g_Kh[(size_t)BB*HH*TT*SS];
__device__ __nv_bfloat16 g_Vh[(size_t)BB*HH*TT*SS], g_Vl[(size_t)BB*HH*TT*SS];
__device__ __nv_bfloat16 g_A3[(size_t)MM*K3];       // split activations (x, then attn out)
__device__ __nv_bfloat16 g_W3[(size_t)4*DD*K3];     // split weights (q,k,v,o)
__device__ float g_ebias[EBN];

// ---------------- prep ----------------
__global__ void zero_absmax_kernel() {
    if (threadIdx.x < 8) g_absmax[threadIdx.x] = 0.0f;
}

__global__ void absmax_all_kernel(const float* __restrict__ wq, const float* __restrict__ wk,
                                  const float* __restrict__ wv, const float* __restrict__ wo,
                                  const float* __restrict__ wu, const float* __restrict__ wsv) {
    int slot = blockIdx.y;
    const float* w = (slot == 0) ? wq : (slot == 1) ? wk : (slot == 2) ? wv
                   : (slot == 3) ? wo : (slot == 4) ? wu : wsv;
    int n = (slot < 4) ? DD * DD : SS * SS;
    float m = 0.0f;
    for (int i = blockIdx.x * blockDim.x + threadIdx.x; i < n; i += gridDim.x * blockDim.x)
        m = fmaxf(m, fabsf(w[i]));
    #pragma unroll
    for (int o = 16; o > 0; o >>= 1) m = fmaxf(m, __shfl_xor_sync(0xffffffffu, m, o));
    __shared__ float sm[8];
    int lane = threadIdx.x & 31, wid = threadIdx.x >> 5;
    if (lane == 0) sm[wid] = m;
    __syncthreads();
    if (wid == 0) {
        int nw = blockDim.x >> 5;
        m = (lane < nw) ? sm[lane] : 0.0f;
        #pragma unroll
        for (int o = 4; o > 0; o >>= 1) m = fmaxf(m, __shfl_xor_sync(0xffffffffu, m, o));
        if (lane == 0) atomicMax((int*)&g_absmax[slot], __float_as_int(m));
    }
}

__global__ void build_ebias_kernel(const float* __restrict__ ps) {
    int i = blockIdx.x * 256 + threadIdx.x;
    if (i >= EBN) return;
    float v = 0.0f;
    if (i >= 128 && i < 128 + 2048) {
        int d = i - 128;
        float bias = (d == 0) ? 1.0f : (float)min(__ffs(d) - 1, 16) * 0.0625f;
        v = __expf(ps[0] * bias);
    }
    g_ebias[i] = v;
}

// ---------------- PTX helpers ----------------
__device__ __forceinline__ void cp16(void* dst, const void* src) {
    unsigned d = (unsigned)__cvta_generic_to_shared(dst);
    asm volatile("cp.async.cg.shared.global [%0], [%1], 16;\n" :: "r"(d), "l"(src));
}
#define LDM4(R, PTR) do { \
    unsigned _a = (unsigned)__cvta_generic_to_shared(PTR); \
    asm volatile("ldmatrix.sync.aligned.m8n8.x4.shared.b16 {%0,%1,%2,%3}, [%4];" \
        : "=r"((R)[0]), "=r"((R)[1]), "=r"((R)[2]), "=r"((R)[3]) : "r"(_a)); \
} while (0)
#define LDM4T(R, PTR) do { \
    unsigned _a = (unsigned)__cvta_generic_to_shared(PTR); \
    asm volatile("ldmatrix.sync.aligned.m8n8.x4.trans.shared.b16 {%0,%1,%2,%3}, [%4];" \
        : "=r"((R)[0]), "=r"((R)[1]), "=r"((R)[2]), "=r"((R)[3]) : "r"(_a)); \
} while (0)
#define MMA16816(C, A, B0, B1) \
    asm volatile("mma.sync.aligned.m16n8k16.row.col.f32.bf16.bf16.f32 " \
        "{%0,%1,%2,%3}, {%4,%5,%6,%7}, {%8,%9}, {%0,%1,%2,%3};" \
        : "+f"((C)[0]), "+f"((C)[1]), "+f"((C)[2]), "+f"((C)[3]) \
        : "r"((A)[0]), "r"((A)[1]), "r"((A)[2]), "r"((A)[3]), "r"(B0), "r"(B1))
#define SWZ(row, ch) ((ch) ^ (((row) >> 1) & 3))
#define SWZ8(row, ch) (((ch) ^ ((row) & 7)) << 3)

__device__ __forceinline__ uint32_t prmt_hi(uint32_t a, uint32_t b) {
    uint32_t r;
    asm("prmt.b32 %0, %1, %2, 0x7632;" : "=r"(r) : "r"(a), "r"(b));
    return r;
}
__device__ __forceinline__ uint32_t pack_bf16x2(float lo, float hi) {
    uint32_t r;
    asm("cvt.rn.bf16x2.f32 %0, %1, %2;" : "=r"(r) : "f"(hi), "f"(lo));
    return r;
}
__device__ __forceinline__ float exp2p(float y) {   // fast 2^y, fma/alu only
    y = fmaxf(y, -125.0f);
    float z = y + 12582912.0f;
    float f = y - (z - 12582912.0f);
    int e = __float_as_int(z) << 23;
    float r = 0.0013333558146f;
    r = fmaf(r, f, 0.0096181291076f);
    r = fmaf(r, f, 0.055504108664f);
    r = fmaf(r, f, 0.24022650696f);
    r = fmaf(r, f, 0.69314718056f);
    r = fmaf(r, f, 1.0f);
    return __int_as_float(__float_as_int(r) + e);
}
__device__ __forceinline__ void emit_hl(__nv_bfloat16* dh, __nv_bfloat16* dl, float f0, float f1) {
    uint32_t u0 = __float_as_uint(f0), u1 = __float_as_uint(f1);
    *(uint32_t*)dh = prmt_hi(u0, u1);
    *(uint32_t*)dl = pack_bf16x2(f0 - __uint_as_float(u0 & 0xffff0000u),
                                 f1 - __uint_as_float(u1 & 0xffff0000u));
}
// [hi | lo | hi] into an A3-style row (stride 1024 between segments)
__device__ __forceinline__ void store3(__nv_bfloat16* p, float f0, float f1) {
    uint32_t u0 = __float_as_uint(f0), u1 = __float_as_uint(f1);
    uint32_t hi = prmt_hi(u0, u1);
    uint32_t lo = pack_bf16x2(f0 - __uint_as_float(u0 & 0xffff0000u),
                              f1 - __uint_as_float(u1 & 0xffff0000u));
    *(uint32_t*)p = hi;
    *(uint32_t*)(p + 2048) = hi;
    *(uint32_t*)(p + 1024) = lo;
}
// [hi | hi | lo] into a W3 row
__device__ __forceinline__ void storeW3(__nv_bfloat16* p, float f0, float f1) {
    uint32_t u0 = __float_as_uint(f0), u1 = __float_as_uint(f1);
    uint32_t hi = prmt_hi(u0, u1);
    uint32_t lo = pack_bf16x2(f0 - __uint_as_float(u0 & 0xffff0000u),
                              f1 - __uint_as_float(u1 & 0xffff0000u));
    *(uint32_t*)p = hi;
    *(uint32_t*)(p + 1024) = hi;
    *(uint32_t*)(p + 2048) = lo;
}
__device__ __forceinline__ float quant6(float w, float sc) {
    float q = rintf(w / sc);
    return fminf(fmaxf(q, -31.0f), 31.0f) * sc;
}

// ---------------- compose (stalk-fold) + quant + split, fused ----------------
// grid (8 kchunks, 16 heads, 2 which), 256 threads
__global__ __launch_bounds__(256) void compose_split_kernel(
        const float* __restrict__ wq, const float* __restrict__ wk,
        const float* __restrict__ wu, const float* __restrict__ wsv) {
    __shared__ float ws[64][64];
    __shared__ float wb[64][128];
    const int which = blockIdx.z, h = blockIdx.y, kc = blockIdx.x;
    const float* wsmall = which ? wsv : wu;
    const float* wbig   = which ? wk  : wq;
    const float scb = g_absmax[which ? 1 : 0] / 31.0f + 1e-8f;
    const float scs = g_absmax[which ? 5 : 4] / 31.0f + 1e-8f;
    const int tid = threadIdx.x;

    for (int idx = tid; idx < 4096; idx += 256)
        ws[idx >> 6][idx & 63] = quant6(wsmall[idx], scs);
    for (int idx = tid; idx < 8192; idx += 256) {
        int s = idx >> 7, k = idx & 127;
        wb[s][k] = quant6(wbig[(size_t)(h * 64 + s) * DD + kc * 128 + k], scb);
    }
    __syncthreads();

    const int tx = tid & 31, ty = tid >> 5;
    const int k0 = tx * 4, sp0 = ty * 8;
    float acc[8][4];
    #pragma unroll
    for (int i = 0; i < 8; i++)
        #pragma unroll
        for (int j = 0; j < 4; j++) acc[i][j] = 0.0f;
    #pragma unroll 8
    for (int s = 0; s < 64; s++) {
        float4 b = *(const float4*)&wb[s][k0];
        #pragma unroll
        for (int i = 0; i < 8; i++) {
            float a = ws[sp0 + i][s];
            acc[i][0] = fmaf(a, b.x, acc[i][0]);
            acc[i][1] = fmaf(a, b.y, acc[i][1]);
            acc[i][2] = fmaf(a, b.z, acc[i][2]);
            acc[i][3] = fmaf(a, b.w, acc[i][3]);
        }
    }
    __nv_bfloat16* o = g_W3 + (size_t)which * DD * K3;
    #pragma unroll
    for (int i = 0; i < 8; i++) {
        __nv_bfloat16* p = o + (size_t)(h * 64 + sp0 + i) * K3 + kc * 128 + k0;
        storeW3(p, acc[i][0], acc[i][1]);
        storeW3(p + 2, acc[i][2], acc[i][3]);
    }
}

// ---------------- wv/wo: quant + split (raw input) ----------------
__global__ void split_w_vo_kernel(const float* __restrict__ wv, const float* __restrict__ wo) {
    int dst = 2 + blockIdx.y;
    const float* src = blockIdx.y ? wo : wv;
    float sc = g_absmax[dst] / 31.0f + 1e-8f;
    int i = blockIdx.x * 256 + threadIdx.x;
    int row = i >> 8;
    int k4 = (i & 255) * 4;
    float4 v = *(const float4*)(src + (size_t)row * DD + k4);
    v.x = quant6(v.x, sc); v.y = quant6(v.y, sc);
    v.z = quant6(v.z, sc); v.w = quant6(v.w, sc);
    __nv_bfloat16* o = g_W3 + (size_t)dst * DD * K3 + (size_t)row * K3 + k4;
    storeW3(o, v.x, v.y);
    storeW3(o + 2, v.z, v.w);
}

// ---------------- x -> A3 [hi|lo|hi] ----------------
__global__ void split_act_kernel(const float* __restrict__ src) {
    int i = blockIdx.x * 256 + threadIdx.x;
    int row = i >> 8;
    int k4 = (i & 255) * 4;
    float4 v = *(const float4*)(src + (size_t)row * DD + k4);
    __nv_bfloat16* o = g_A3 + (size_t)row * K3 + k4;
    store3(o, v.x, v.y);
    store3(o + 2, v.z, v.w);
}

// ---------------- bf16 tensor-core GEMM:  C[M,N] = A3 @ W3^T ----------------
// mode 0: fused QKV (z=0 -> V heavy-first, z=1 -> Q, z=2 -> K); mode 1: O
__global__ __launch_bounds__(256, 2) void gemm_bf16_kernel(float* __restrict__ ext_out,
                                                           int mode) {
    int which, nc;
    if (mode == 0) {
        which = (blockIdx.z == 0) ? 2 : (blockIdx.z == 1) ? 0 : 1;
        nc = (which == 2) ? 96 : 32;
    } else {
        which = 3; nc = 96;
    }
    __shared__ alignas(16) __nv_bfloat16 As[2][128 * 32];
    __shared__ alignas(16) __nv_bfloat16 Bs[2][128 * 32];

    const __nv_bfloat16* __restrict__ Wg = g_W3 + (size_t)which * DD * K3;
    const int tid = threadIdx.x;
    const int lane = tid & 31, wid = tid >> 5;
    const int warp_m = wid >> 1, warp_n = wid & 1;
    const int m0 = blockIdx.y * 128;
    const int n0 = blockIdx.x * 128;

    const __nv_bfloat16* Ag = g_A3 + (size_t)m0 * K3;
    const __nv_bfloat16* Bg = Wg + (size_t)n0 * K3;

    float c[2][4][2][4];
    #pragma unroll
    for (int i = 0; i < 2; i++)
        #pragma unroll
        for (int g = 0; g < 4; g++)
            #pragma unroll
            for (int j = 0; j < 2; j++)
                #pragma unroll
                for (int q = 0; q < 4; q++) c[i][g][j][q] = 0.0f;

    int ld_row[2], ld_ch[2];
    #pragma unroll
    for (int p = 0; p < 2; p++) {
        int e = tid + p * 256;
        ld_row[p] = e >> 2;
        ld_ch[p] = e & 3;
    }

    #pragma unroll
    for (int p = 0; p < 2; p++) {
        int row = ld_row[p], ch = ld_ch[p];
        int so = row * 32 + SWZ(row, ch) * 8;
        cp16(&As[0][so], Ag + (size_t)row * K3 + ch * 8);
        cp16(&Bs[0][so], Bg + (size_t)row * K3 + ch * 8);
    }
    asm volatile("cp.async.commit_group;");

    for (int kc = 0; kc < nc; kc++) {
        if (kc + 1 < nc) {
            int s = (kc + 1) & 1;
            int koff = (kc + 1) * 32;
            #pragma unroll
            for (int p = 0; p < 2; p++) {
                int row = ld_row[p], ch = ld_ch[p];
                int so = row * 32 + SWZ(row, ch) * 8;
                cp16(&As[s][so], Ag + (size_t)row * K3 + koff + ch * 8);
                cp16(&Bs[s][so], Bg + (size_t)row * K3 + koff + ch * 8);
            }
            asm volatile("cp.async.commit_group;");
            asm volatile("cp.async.wait_group 1;");
        } else {
            asm volatile("cp.async.wait_group 0;");
        }
        __syncthreads();

        const __nv_bfloat16* Asb = As[kc & 1];
        const __nv_bfloat16* Bsb = Bs[kc & 1];

        #pragma unroll
        for (int kk = 0; kk < 2; kk++) {
            uint32_t af[2][4], bf[4][4];
            #pragma unroll
            for (int i = 0; i < 2; i++) {
                int row = warp_m * 32 + i * 16 + (lane & 15);
                int ch = kk * 2 + (lane >> 4);
                LDM4(af[i], Asb + row * 32 + SWZ(row, ch) * 8);
            }
            #pragma unroll
            for (int g = 0; g < 4; g++) {
                int row = warp_n * 64 + g * 16 + (lane & 7) + ((lane >> 4) << 3);
                int ch = kk * 2 + ((lane >> 3) & 1);
                LDM4(bf[g], Bsb + row * 32 + SWZ(row, ch) * 8);
            }
            #pragma unroll
            for (int i = 0; i < 2; i++)
                #pragma unroll
                for (int g = 0; g < 4; g++) {
                    MMA16816(c[i][g][0], af[i], bf[g][0], bf[g][1]);
                    MMA16816(c[i][g][1], af[i], bf[g][2], bf[g][3]);
                }
        }
        __syncthreads();
    }

    // epilogue
    #pragma unroll
    for (int i = 0; i < 2; i++)
        #pragma unroll
        for (int g = 0; g < 4; g++)
            #pragma unroll
            for (int j = 0; j < 2; j++) {
                int rr = m0 + warp_m * 32 + i * 16 + (lane >> 2);
                int cc = n0 + warp_n * 64 + g * 16 + j * 8 + ((lane & 3) << 1);
                if (which < 2) {           // Q/K: hi only
                    __nv_bfloat16* dh = (which == 0) ? g_Qh : g_Kh;
                    int b = rr >> 11, t = rr & 2047;
                    int hh = cc >> 6, s2 = cc & 63;
                    size_t off = ((size_t)(b * HH + hh) * TT + t) * SS + s2;
                    *(uint32_t*)(dh + off) = prmt_hi(__float_as_uint(c[i][g][j][0]),
                                                     __float_as_uint(c[i][g][j][1]));
                    *(uint32_t*)(dh + off + 8 * SS) = prmt_hi(__float_as_uint(c[i][g][j][2]),
                                                              __float_as_uint(c[i][g][j][3]));
                } else if (which == 2) {   // V: hi + lo
                    int b = rr >> 11, t = rr & 2047;
                    int hh = cc >> 6, s2 = cc & 63;
                    size_t off = ((size_t)(b * HH + hh) * TT + t) * SS + s2;
                    emit_hl(g_Vh + off, g_Vl + off, c[i][g][j][0], c[i][g][j][1]);
                    emit_hl(g_Vh + off + 8 * SS, g_Vl + off + 8 * SS, c[i][g][j][2], c[i][g][j][3]);
                } else {                   // final output fp32
                    *(float2*)(ext_out + (size_t)rr * DD + cc) =
                        make_float2(c[i][g][j][0], c[i][g][j][1]);
                    *(float2*)(ext_out + (size_t)(rr + 8) * DD + cc) =
                        make_float2(c[i][g][j][2], c[i][g][j][3]);
                }
            }
}

// ---------------- tensor-core flash attention (128-row q tiles) ----------------
// grid (64 bh fast, 16 qt slow DESCENDING): heavy q-tiles launch first.
#define CLOG2E 0.18033688011112042f   // 0.125 * log2(e)

__global__ __launch_bounds__(256, 2) void attn_tc_kernel() {
    extern __shared__ __nv_bfloat16 smraw[];   // [2 stages][3 arrays: Kh,Vh,Vl][64*64]
    const int tid = threadIdx.x, lane = tid & 31, warp = tid >> 5;
    const int qt = (int)gridDim.y - 1 - (int)blockIdx.y;   // descending work order
    const int bh = blockIdx.x;
    const size_t bhbase = (size_t)bh * TT * SS;

    // ---- stage Q hi (128x64 = 1024 x 16B) into arrays 0,1 ----
    {
        const __nv_bfloat16* src = g_Qh + bhbase + (size_t)qt * 128 * 64;
        #pragma unroll
        for (int i = 0; i < 4; i++) {                 // 4 iters = 1024 chunks
            int idx = tid + 256 * i;                  // 0..1023
            int r = idx >> 3, ch = idx & 7;           // r in [0,128)
            int a = r >> 6, rl = r & 63;
            cp16(smraw + a * 4096 + rl * 64 + SWZ8(rl, ch), src + r * 64 + ch * 8);
        }
    }
    asm volatile("cp.async.commit_group;");
    asm volatile("cp.async.wait_group 0;");
    __syncthreads();

    uint32_t qh[4][4];
    {
        int r = warp * 16 + (lane & 15);
        int a = r >> 6, rl = r & 63;
        #pragma unroll
        for (int kk = 0; kk < 4; kk++) {
            int ch = kk * 2 + (lane >> 4);
            LDM4(qh[kk], smraw + a * 4096 + rl * 64 + SWZ8(rl, ch));
        }
    }
    __syncthreads();

    float oc[8][4];
    #pragma unroll
    for (int j = 0; j < 8; j++)
        #pragma unroll
        for (int q = 0; q < 4; q++) oc[j][q] = 0.0f;
    float m0 = -1e30f, m1 = -1e30f, l0 = 0.0f, l1 = 0.0f;

    const int rg = lane >> 2;
    const int cb = (lane & 3) << 1;
    const int brow = (lane & 7) + ((lane >> 4) << 3);
    const int bchx = (lane >> 3) & 1;
    const int vrow16 = ((lane >> 3) & 1) * 8 + (lane & 7);
    const int vchh = lane >> 4;
    const int ktmax = 2 * qt + 1;

    const __nv_bfloat16* kvsrc[3] = {g_Kh + bhbase, g_Vh + bhbase, g_Vl + bhbase};

    #define LOAD_KV(KT, ST) do { \
        _Pragma("unroll") \
        for (int _i = 0; _i < 6; _i++) { \
            int _g = tid + 256 * _i;           /* 0..1535 */ \
            int _arr = _g >> 9, _idx = _g & 511; \
            int _r = _idx >> 3, _ch = _idx & 7; \
            cp16(smraw + ((ST) * 3 + _arr) * 4096 + _r * 64 + SWZ8(_r, _ch), \
                 kvsrc[_arr] + (size_t)(KT) * 4096 + _r * 64 + _ch * 8); \
        } \
        asm volatile("cp.async.commit_group;"); \
    } while (0)

    LOAD_KV(0, 0);

    for (int kt = 0; kt <= ktmax; kt++) {
        const int st = kt & 1;
        if (kt < ktmax) {
            LOAD_KV(kt + 1, st ^ 1);
            asm volatile("cp.async.wait_group 1;");
        } else {
            asm volatile("cp.async.wait_group 0;");
        }
        __syncthreads();

        if (qt * 128 + warp * 16 + 15 >= kt * 64) {
            const __nv_bfloat16* Kh_ = smraw + (st * 3 + 0) * 4096;
            const __nv_bfloat16* Vh_ = smraw + (st * 3 + 1) * 4096;
            const __nv_bfloat16* Vl_ = smraw + (st * 3 + 2) * 4096;

            // ---- S = Q K^T (1-term bf16) ----
            float sc[8][4];
            #pragma unroll
            for (int j = 0; j < 8; j++)
                #pragma unroll
                for (int q = 0; q < 4; q++) sc[j][q] = 0.0f;
            #pragma unroll
            for (int g = 0; g < 4; g++) {
                int row = g * 16 + brow;
                #pragma unroll
                for (int kk = 0; kk < 4; kk++) {
                    int ch = kk * 2 + bchx;
                    uint32_t bh4[4];
                    LDM4(bh4, &Kh_[row * 64 + SWZ8(row, ch)]);
                    MMA16816(sc[2*g],   qh[kk], bh4[0], bh4[1]);
                    MMA16816(sc[2*g+1], qh[kk], bh4[2], bh4[3]);
                }
            }

            // ---- softmax ----
            float mx0 = -1e30f, mx1 = -1e30f;
            #pragma unroll
            for (int j = 0; j < 8; j++) {
                mx0 = fmaxf(mx0, fmaxf(sc[j][0], sc[j][1]));
                mx1 = fmaxf(mx1, fmaxf(sc[j][2], sc[j][3]));
            }
            mx0 = fmaxf(mx0, __shfl_xor_sync(0xffffffffu, mx0, 1));
            mx0 = fmaxf(mx0, __shfl_xor_sync(0xffffffffu, mx0, 2));
            mx1 = fmaxf(mx1, __shfl_xor_sync(0xffffffffu, mx1, 1));
            mx1 = fmaxf(mx1, __shfl_xor_sync(0xffffffffu, mx1, 2));
            float mn0 = fmaxf(m0, mx0 * CLOG2E);
            float mn1 = fmaxf(m1, mx1 * CLOG2E);
            float a0 = exp2p(m0 - mn0), a1 = exp2p(m1 - mn1);
            m0 = mn0; m1 = mn1;

            int base0 = qt * 128 + warp * 16 + rg - kt * 64 + 128;
            int base1 = base0 + 8;
            float ls0 = 0.0f, ls1 = 0.0f;
            #pragma unroll
            for (int j = 0; j < 8; j++) {
                int c0 = j * 8 + cb;
                float e0 = exp2p(fmaf(sc[j][0], CLOG2E, -mn0)) * __ldg(&g_ebias[base0 - c0]);
                float e1 = exp2p(fmaf(sc[j][1], CLOG2E, -mn0)) * __ldg(&g_ebias[base0 - c0 - 1]);
                float e2 = exp2p(fmaf(sc[j][2], CLOG2E, -mn1)) * __ldg(&g_ebias[base1 - c0]);
                float e3 = exp2p(fmaf(sc[j][3], CLOG2E, -mn1)) * __ldg(&g_ebias[base1 - c0 - 1]);
                sc[j][0] = e0; sc[j][1] = e1; sc[j][2] = e2; sc[j][3] = e3;
                ls0 += e0 + e1; ls1 += e2 + e3;
            }
            ls0 += __shfl_xor_sync(0xffffffffu, ls0, 1);
            ls0 += __shfl_xor_sync(0xffffffffu, ls0, 2);
            ls1 += __shfl_xor_sync(0xffffffffu, ls1, 1);
            ls1 += __shfl_xor_sync(0xffffffffu, ls1, 2);
            l0 = l0 * a0 + ls0;
            l1 = l1 * a1 + ls1;
            #pragma unroll
            for (int j = 0; j < 8; j++) {
                oc[j][0] *= a0; oc[j][1] *= a0; oc[j][2] *= a1; oc[j][3] *= a1;
            }

            // ---- repack P (C-frag -> A-frag, hi/lo) ----
            uint32_t pah[4][4], pal[4][4];
            #pragma unroll
            for (int kk = 0; kk < 4; kk++) {
                #pragma unroll
                for (int half = 0; half < 2; half++) {
                    int j = 2 * kk + half;
                    uint32_t u0 = __float_as_uint(sc[j][0]), u1 = __float_as_uint(sc[j][1]);
                    uint32_t u2 = __float_as_uint(sc[j][2]), u3 = __float_as_uint(sc[j][3]);
                    pah[kk][half * 2]     = prmt_hi(u0, u1);
                    pah[kk][half * 2 + 1] = prmt_hi(u2, u3);
                    float p0 = sc[j][0] - __uint_as_float(u0 & 0xffff0000u);
                    float p1 = sc[j][1] - __uint_as_float(u1 & 0xffff0000u);
                    float p2 = sc[j][2] - __uint_as_float(u2 & 0xffff0000u);
                    float p3 = sc[j][3] - __uint_as_float(u3 & 0xffff0000u);
                    pal[kk][half * 2]     = pack_bf16x2(p0, p1);
                    pal[kk][half * 2 + 1] = pack_bf16x2(p2, p3);
                }
            }

            // ---- O += P V (3-term; V row-major via ldmatrix.trans) ----
            #pragma unroll
            for (int g = 0; g < 4; g++) {
                int ch = 2 * g + vchh;
                #pragma unroll
                for (int kk = 0; kk < 4; kk++) {
                    int row = kk * 16 + vrow16;
                    uint32_t vh4[4], vl4[4];
                    LDM4T(vh4, &Vh_[row * 64 + SWZ8(row, ch)]);
                    MMA16816(oc[2*g],   pah[kk], vh4[0], vh4[1]);
                    MMA16816(oc[2*g+1], pah[kk], vh4[2], vh4[3]);
                    MMA16816(oc[2*g],   pal[kk], vh4[0], vh4[1]);
                    MMA16816(oc[2*g+1], pal[kk], vh4[2], vh4[3]);
                    LDM4T(vl4, &Vl_[row * 64 + SWZ8(row, ch)]);
                    MMA16816(oc[2*g],   pah[kk], vl4[0], vl4[1]);
                    MMA16816(oc[2*g+1], pah[kk], vl4[2], vl4[3]);
                }
            }
        }
        __syncthreads();
    }

    // ---- epilogue: write split [hi|lo|hi] rows of A3 directly ----
    float inv0 = 1.0f / l0, inv1 = 1.0f / l1;
    int b = bh >> 4, hh = bh & 15;
    int t0 = qt * 128 + warp * 16 + rg;
    __nv_bfloat16* rowp = g_A3 + (size_t)(b * TT + t0) * K3 + hh * 64 + cb;
    #pragma unroll
    for (int j = 0; j < 8; j++) {
        store3(rowp + j * 8, oc[j][0] * inv0, oc[j][1] * inv0);
        store3(rowp + (size_t)8 * K3 + j * 8, oc[j][2] * inv1, oc[j][3] * inv1);
    }
}

// ---------------- launch ----------------
extern "C" void kernel_launch(void* const* d_in, const int* in_sizes, int n_in,
                              void* d_out, int out_size) {
    const float* x   = (const float*)d_in[0];
    const float* wq  = (const float*)d_in[1];
    const float* wk  = (const float*)d_in[2];
    const float* wv  = (const float*)d_in[3];
    const float* wo  = (const float*)d_in[4];
    const float* wu  = (const float*)d_in[5];
    const float* wsv = (const float*)d_in[6];
    const float* ps  = (const float*)d_in[7];
    float* out = (float*)d_out;

    static int smem_set = 0;
    if (!smem_set) {
        cudaFuncSetAttribute(attn_tc_kernel, cudaFuncAttributeMaxDynamicSharedMemorySize, 49152);
        smem_set = 1;
    }

    zero_absmax_kernel<<<1, 32>>>();
    absmax_all_kernel<<<dim3(64, 6), 256>>>(wq, wk, wv, wo, wu, wsv);
    build_ebias_kernel<<<9, 256>>>(ps);
    compose_split_kernel<<<dim3(8, 16, 2), 256>>>(wq, wk, wu, wsv);
    split_w_vo_kernel<<<dim3(DD*DD/1024, 2), 256>>>(wv, wo);
    split_act_kernel<<<MM*DD/1024, 256>>>(x);
    gemm_bf16_kernel<<<dim3(DD/128, MM/128, 3), 256>>>(nullptr, 0);   // fused QKV, V first
    attn_tc_kernel<<<dim3(BB*HH, TT/128), 256, 49152>>>();            // qt slow, descending
    gemm_bf16_kernel<<<dim3(DD/128, MM/128, 1), 256>>>(out, 1);       // O: 3-term
}

// round 12
// speedup vs baseline: 4.9885x; 1.1975x over previous
#include <cuda_runtime.h>
#include <cuda_bf16.h>
#include <cuda_fp16.h>
#include <cstdint>

#define BB 4
#define TT 2048
#define DD 1024
#define HH 16
#define SS 64
#define MM (BB*TT)
#define K3 3072          // [hi | lo | hi] segments of K=1024
#define EBN 2208         // ebias table size (index = d + 128)

// ---------------- device scratch (static, allocation-free) ----------------
__device__ float g_absmax[8];
__device__ __nv_bfloat16 g_Qh[(size_t)BB*HH*TT*SS];
__device__ __nv_bfloat16 g_Kh[(size_t)BB*HH*TT*SS];
__device__ __nv_bfloat16 g_Vh[(size_t)BB*HH*TT*SS], g_Vl[(size_t)BB*HH*TT*SS];
__device__ __nv_bfloat16 g_A3[(size_t)MM*K3];       // split activations (x)
__device__ __nv_bfloat16 g_W3[(size_t)4*DD*K3];     // split weights (q,k,v, [o unused])
__device__ __half g_AO[(size_t)MM*DD];              // attention output, fp16
__device__ __half g_wo_f16[(size_t)DD*DD];          // quantized wo, fp16
__device__ float g_ebias[EBN];

// ---------------- prep ----------------
__global__ void zero_absmax_kernel() {
    if (threadIdx.x < 8) g_absmax[threadIdx.x] = 0.0f;
}

__global__ void absmax_all_kernel(const float* __restrict__ wq, const float* __restrict__ wk,
                                  const float* __restrict__ wv, const float* __restrict__ wo,
                                  const float* __restrict__ wu, const float* __restrict__ wsv) {
    int slot = blockIdx.y;
    const float* w = (slot == 0) ? wq : (slot == 1) ? wk : (slot == 2) ? wv
                   : (slot == 3) ? wo : (slot == 4) ? wu : wsv;
    int n = (slot < 4) ? DD * DD : SS * SS;
    float m = 0.0f;
    for (int i = blockIdx.x * blockDim.x + threadIdx.x; i < n; i += gridDim.x * blockDim.x)
        m = fmaxf(m, fabsf(w[i]));
    #pragma unroll
    for (int o = 16; o > 0; o >>= 1) m = fmaxf(m, __shfl_xor_sync(0xffffffffu, m, o));
    __shared__ float sm[8];
    int lane = threadIdx.x & 31, wid = threadIdx.x >> 5;
    if (lane == 0) sm[wid] = m;
    __syncthreads();
    if (wid == 0) {
        int nw = blockDim.x >> 5;
        m = (lane < nw) ? sm[lane] : 0.0f;
        #pragma unroll
        for (int o = 4; o > 0; o >>= 1) m = fmaxf(m, __shfl_xor_sync(0xffffffffu, m, o));
        if (lane == 0) atomicMax((int*)&g_absmax[slot], __float_as_int(m));
    }
}

__global__ void build_ebias_kernel(const float* __restrict__ ps) {
    int i = blockIdx.x * 256 + threadIdx.x;
    if (i >= EBN) return;
    float v = 0.0f;
    if (i >= 128 && i < 128 + 2048) {
        int d = i - 128;
        float bias = (d == 0) ? 1.0f : (float)min(__ffs(d) - 1, 16) * 0.0625f;
        v = __expf(ps[0] * bias);
    }
    g_ebias[i] = v;
}

// ---------------- PTX helpers ----------------
__device__ __forceinline__ void cp16(void* dst, const void* src) {
    unsigned d = (unsigned)__cvta_generic_to_shared(dst);
    asm volatile("cp.async.cg.shared.global [%0], [%1], 16;\n" :: "r"(d), "l"(src));
}
#define LDM4(R, PTR) do { \
    unsigned _a = (unsigned)__cvta_generic_to_shared(PTR); \
    asm volatile("ldmatrix.sync.aligned.m8n8.x4.shared.b16 {%0,%1,%2,%3}, [%4];" \
        : "=r"((R)[0]), "=r"((R)[1]), "=r"((R)[2]), "=r"((R)[3]) : "r"(_a)); \
} while (0)
#define LDM4T(R, PTR) do { \
    unsigned _a = (unsigned)__cvta_generic_to_shared(PTR); \
    asm volatile("ldmatrix.sync.aligned.m8n8.x4.trans.shared.b16 {%0,%1,%2,%3}, [%4];" \
        : "=r"((R)[0]), "=r"((R)[1]), "=r"((R)[2]), "=r"((R)[3]) : "r"(_a)); \
} while (0)
#define MMA16816(C, A, B0, B1) \
    asm volatile("mma.sync.aligned.m16n8k16.row.col.f32.bf16.bf16.f32 " \
        "{%0,%1,%2,%3}, {%4,%5,%6,%7}, {%8,%9}, {%0,%1,%2,%3};" \
        : "+f"((C)[0]), "+f"((C)[1]), "+f"((C)[2]), "+f"((C)[3]) \
        : "r"((A)[0]), "r"((A)[1]), "r"((A)[2]), "r"((A)[3]), "r"(B0), "r"(B1))
#define MMAF16(C, A, B0, B1) \
    asm volatile("mma.sync.aligned.m16n8k16.row.col.f32.f16.f16.f32 " \
        "{%0,%1,%2,%3}, {%4,%5,%6,%7}, {%8,%9}, {%0,%1,%2,%3};" \
        : "+f"((C)[0]), "+f"((C)[1]), "+f"((C)[2]), "+f"((C)[3]) \
        : "r"((A)[0]), "r"((A)[1]), "r"((A)[2]), "r"((A)[3]), "r"(B0), "r"(B1))
#define SWZ(row, ch) ((ch) ^ (((row) >> 1) & 3))
#define SWZ8(row, ch) (((ch) ^ ((row) & 7)) << 3)

__device__ __forceinline__ uint32_t prmt_hi(uint32_t a, uint32_t b) {
    uint32_t r;
    asm("prmt.b32 %0, %1, %2, 0x7632;" : "=r"(r) : "r"(a), "r"(b));
    return r;
}
__device__ __forceinline__ uint32_t pack_bf16x2(float lo, float hi) {
    uint32_t r;
    asm("cvt.rn.bf16x2.f32 %0, %1, %2;" : "=r"(r) : "f"(hi), "f"(lo));
    return r;
}
__device__ __forceinline__ uint32_t pack_f16x2(float lo, float hi) {
    uint32_t r;
    asm("cvt.rn.f16x2.f32 %0, %1, %2;" : "=r"(r) : "f"(hi), "f"(lo));
    return r;
}
__device__ __forceinline__ float exp2p(float y) {   // fast 2^y, fma/alu only
    y = fmaxf(y, -125.0f);
    float z = y + 12582912.0f;
    float f = y - (z - 12582912.0f);
    int e = __float_as_int(z) << 23;
    float r = 0.0013333558146f;
    r = fmaf(r, f, 0.0096181291076f);
    r = fmaf(r, f, 0.055504108664f);
    r = fmaf(r, f, 0.24022650696f);
    r = fmaf(r, f, 0.69314718056f);
    r = fmaf(r, f, 1.0f);
    return __int_as_float(__float_as_int(r) + e);
}
__device__ __forceinline__ void emit_hl(__nv_bfloat16* dh, __nv_bfloat16* dl, float f0, float f1) {
    uint32_t u0 = __float_as_uint(f0), u1 = __float_as_uint(f1);
    *(uint32_t*)dh = prmt_hi(u0, u1);
    *(uint32_t*)dl = pack_bf16x2(f0 - __uint_as_float(u0 & 0xffff0000u),
                                 f1 - __uint_as_float(u1 & 0xffff0000u));
}
// [hi | lo | hi] into an A3-style row (stride 1024 between segments)
__device__ __forceinline__ void store3(__nv_bfloat16* p, float f0, float f1) {
    uint32_t u0 = __float_as_uint(f0), u1 = __float_as_uint(f1);
    uint32_t hi = prmt_hi(u0, u1);
    uint32_t lo = pack_bf16x2(f0 - __uint_as_float(u0 & 0xffff0000u),
                              f1 - __uint_as_float(u1 & 0xffff0000u));
    *(uint32_t*)p = hi;
    *(uint32_t*)(p + 2048) = hi;
    *(uint32_t*)(p + 1024) = lo;
}
// [hi | hi | lo] into a W3 row
__device__ __forceinline__ void storeW3(__nv_bfloat16* p, float f0, float f1) {
    uint32_t u0 = __float_as_uint(f0), u1 = __float_as_uint(f1);
    uint32_t hi = prmt_hi(u0, u1);
    uint32_t lo = pack_bf16x2(f0 - __uint_as_float(u0 & 0xffff0000u),
                              f1 - __uint_as_float(u1 & 0xffff0000u));
    *(uint32_t*)p = hi;
    *(uint32_t*)(p + 1024) = hi;
    *(uint32_t*)(p + 2048) = lo;
}
__device__ __forceinline__ float quant6(float w, float sc) {
    float q = rintf(w / sc);
    return fminf(fmaxf(q, -31.0f), 31.0f) * sc;
}

// ---------------- compose (stalk-fold) + quant + split, fused ----------------
__global__ __launch_bounds__(256) void compose_split_kernel(
        const float* __restrict__ wq, const float* __restrict__ wk,
        const float* __restrict__ wu, const float* __restrict__ wsv) {
    __shared__ float ws[64][64];
    __shared__ float wb[64][128];
    const int which = blockIdx.z, h = blockIdx.y, kc = blockIdx.x;
    const float* wsmall = which ? wsv : wu;
    const float* wbig   = which ? wk  : wq;
    const float scb = g_absmax[which ? 1 : 0] / 31.0f + 1e-8f;
    const float scs = g_absmax[which ? 5 : 4] / 31.0f + 1e-8f;
    const int tid = threadIdx.x;

    for (int idx = tid; idx < 4096; idx += 256)
        ws[idx >> 6][idx & 63] = quant6(wsmall[idx], scs);
    for (int idx = tid; idx < 8192; idx += 256) {
        int s = idx >> 7, k = idx & 127;
        wb[s][k] = quant6(wbig[(size_t)(h * 64 + s) * DD + kc * 128 + k], scb);
    }
    __syncthreads();

    const int tx = tid & 31, ty = tid >> 5;
    const int k0 = tx * 4, sp0 = ty * 8;
    float acc[8][4];
    #pragma unroll
    for (int i = 0; i < 8; i++)
        #pragma unroll
        for (int j = 0; j < 4; j++) acc[i][j] = 0.0f;
    #pragma unroll 8
    for (int s = 0; s < 64; s++) {
        float4 b = *(const float4*)&wb[s][k0];
        #pragma unroll
        for (int i = 0; i < 8; i++) {
            float a = ws[sp0 + i][s];
            acc[i][0] = fmaf(a, b.x, acc[i][0]);
            acc[i][1] = fmaf(a, b.y, acc[i][1]);
            acc[i][2] = fmaf(a, b.z, acc[i][2]);
            acc[i][3] = fmaf(a, b.w, acc[i][3]);
        }
    }
    __nv_bfloat16* o = g_W3 + (size_t)which * DD * K3;
    #pragma unroll
    for (int i = 0; i < 8; i++) {
        __nv_bfloat16* p = o + (size_t)(h * 64 + sp0 + i) * K3 + kc * 128 + k0;
        storeW3(p, acc[i][0], acc[i][1]);
        storeW3(p + 2, acc[i][2], acc[i][3]);
    }
}

// ---------------- wv -> W3 3-term; wo -> fp16 ----------------
__global__ void split_w_vo_kernel(const float* __restrict__ wv, const float* __restrict__ wo) {
    int is_o = blockIdx.y;
    const float* src = is_o ? wo : wv;
    float sc = g_absmax[2 + is_o] / 31.0f + 1e-8f;
    int i = blockIdx.x * 256 + threadIdx.x;
    int row = i >> 8;
    int k4 = (i & 255) * 4;
    float4 v = *(const float4*)(src + (size_t)row * DD + k4);
    v.x = quant6(v.x, sc); v.y = quant6(v.y, sc);
    v.z = quant6(v.z, sc); v.w = quant6(v.w, sc);
    if (is_o) {
        __half* o = g_wo_f16 + (size_t)row * DD + k4;
        *(uint32_t*)o = pack_f16x2(v.x, v.y);
        *(uint32_t*)(o + 2) = pack_f16x2(v.z, v.w);
    } else {
        __nv_bfloat16* o = g_W3 + (size_t)2 * DD * K3 + (size_t)row * K3 + k4;
        storeW3(o, v.x, v.y);
        storeW3(o + 2, v.z, v.w);
    }
}

// ---------------- x -> A3 [hi|lo|hi] ----------------
__global__ void split_act_kernel(const float* __restrict__ src) {
    int i = blockIdx.x * 256 + threadIdx.x;
    int row = i >> 8;
    int k4 = (i & 255) * 4;
    float4 v = *(const float4*)(src + (size_t)row * DD + k4);
    __nv_bfloat16* o = g_A3 + (size_t)row * K3 + k4;
    store3(o, v.x, v.y);
    store3(o + 2, v.z, v.w);
}

// ---------------- bf16 tensor-core GEMM: QKV (z=0 -> V nc=96 heavy-first; Q,K nc=32) ----
__global__ __launch_bounds__(256, 2) void gemm_bf16_kernel() {
    const int which = (blockIdx.z == 0) ? 2 : (blockIdx.z == 1) ? 0 : 1;
    const int nc = (which == 2) ? 96 : 32;
    __shared__ alignas(16) __nv_bfloat16 As[2][128 * 32];
    __shared__ alignas(16) __nv_bfloat16 Bs[2][128 * 32];

    const __nv_bfloat16* __restrict__ Wg = g_W3 + (size_t)which * DD * K3;
    const int tid = threadIdx.x;
    const int lane = tid & 31, wid = tid >> 5;
    const int warp_m = wid >> 1, warp_n = wid & 1;
    const int m0 = blockIdx.y * 128;
    const int n0 = blockIdx.x * 128;

    const __nv_bfloat16* Ag = g_A3 + (size_t)m0 * K3;
    const __nv_bfloat16* Bg = Wg + (size_t)n0 * K3;

    float c[2][4][2][4];
    #pragma unroll
    for (int i = 0; i < 2; i++)
        #pragma unroll
        for (int g = 0; g < 4; g++)
            #pragma unroll
            for (int j = 0; j < 2; j++)
                #pragma unroll
                for (int q = 0; q < 4; q++) c[i][g][j][q] = 0.0f;

    int ld_row[2], ld_ch[2];
    #pragma unroll
    for (int p = 0; p < 2; p++) {
        int e = tid + p * 256;
        ld_row[p] = e >> 2;
        ld_ch[p] = e & 3;
    }

    #pragma unroll
    for (int p = 0; p < 2; p++) {
        int row = ld_row[p], ch = ld_ch[p];
        int so = row * 32 + SWZ(row, ch) * 8;
        cp16(&As[0][so], Ag + (size_t)row * K3 + ch * 8);
        cp16(&Bs[0][so], Bg + (size_t)row * K3 + ch * 8);
    }
    asm volatile("cp.async.commit_group;");

    for (int kc = 0; kc < nc; kc++) {
        if (kc + 1 < nc) {
            int s = (kc + 1) & 1;
            int koff = (kc + 1) * 32;
            #pragma unroll
            for (int p = 0; p < 2; p++) {
                int row = ld_row[p], ch = ld_ch[p];
                int so = row * 32 + SWZ(row, ch) * 8;
                cp16(&As[s][so], Ag + (size_t)row * K3 + koff + ch * 8);
                cp16(&Bs[s][so], Bg + (size_t)row * K3 + koff + ch * 8);
            }
            asm volatile("cp.async.commit_group;");
            asm volatile("cp.async.wait_group 1;");
        } else {
            asm volatile("cp.async.wait_group 0;");
        }
        __syncthreads();

        const __nv_bfloat16* Asb = As[kc & 1];
        const __nv_bfloat16* Bsb = Bs[kc & 1];

        #pragma unroll
        for (int kk = 0; kk < 2; kk++) {
            uint32_t af[2][4], bf[4][4];
            #pragma unroll
            for (int i = 0; i < 2; i++) {
                int row = warp_m * 32 + i * 16 + (lane & 15);
                int ch = kk * 2 + (lane >> 4);
                LDM4(af[i], Asb + row * 32 + SWZ(row, ch) * 8);
            }
            #pragma unroll
            for (int g = 0; g < 4; g++) {
                int row = warp_n * 64 + g * 16 + (lane & 7) + ((lane >> 4) << 3);
                int ch = kk * 2 + ((lane >> 3) & 1);
                LDM4(bf[g], Bsb + row * 32 + SWZ(row, ch) * 8);
            }
            #pragma unroll
            for (int i = 0; i < 2; i++)
                #pragma unroll
                for (int g = 0; g < 4; g++) {
                    MMA16816(c[i][g][0], af[i], bf[g][0], bf[g][1]);
                    MMA16816(c[i][g][1], af[i], bf[g][2], bf[g][3]);
                }
        }
        __syncthreads();
    }

    // epilogue
    #pragma unroll
    for (int i = 0; i < 2; i++)
        #pragma unroll
        for (int g = 0; g < 4; g++)
            #pragma unroll
            for (int j = 0; j < 2; j++) {
                int rr = m0 + warp_m * 32 + i * 16 + (lane >> 2);
                int cc = n0 + warp_n * 64 + g * 16 + j * 8 + ((lane & 3) << 1);
                int b = rr >> 11, t = rr & 2047;
                int hh = cc >> 6, s2 = cc & 63;
                size_t off = ((size_t)(b * HH + hh) * TT + t) * SS + s2;
                if (which < 2) {           // Q/K: hi only
                    __nv_bfloat16* dh = (which == 0) ? g_Qh : g_Kh;
                    *(uint32_t*)(dh + off) = pack_bf16x2(c[i][g][j][0], c[i][g][j][1]);
                    *(uint32_t*)(dh + off + 8 * SS) = pack_bf16x2(c[i][g][j][2], c[i][g][j][3]);
                } else {                   // V: hi + lo
                    emit_hl(g_Vh + off, g_Vl + off, c[i][g][j][0], c[i][g][j][1]);
                    emit_hl(g_Vh + off + 8 * SS, g_Vl + off + 8 * SS, c[i][g][j][2], c[i][g][j][3]);
                }
            }
}

// ---------------- fp16 O GEMM: out[M,D] = AO[M,D] @ wo_f16[D,D]^T ----------------
__global__ __launch_bounds__(256, 2) void gemm_o_f16_kernel(float* __restrict__ ext_out) {
    __shared__ alignas(16) __half As[2][128 * 32];
    __shared__ alignas(16) __half Bs[2][128 * 32];

    const int tid = threadIdx.x;
    const int lane = tid & 31, wid = tid >> 5;
    const int warp_m = wid >> 1, warp_n = wid & 1;
    const int m0 = blockIdx.y * 128;
    const int n0 = blockIdx.x * 128;

    const __half* Ag = g_AO + (size_t)m0 * DD;
    const __half* Bg = g_wo_f16 + (size_t)n0 * DD;

    float c[2][4][2][4];
    #pragma unroll
    for (int i = 0; i < 2; i++)
        #pragma unroll
        for (int g = 0; g < 4; g++)
            #pragma unroll
            for (int j = 0; j < 2; j++)
                #pragma unroll
                for (int q = 0; q < 4; q++) c[i][g][j][q] = 0.0f;

    int ld_row[2], ld_ch[2];
    #pragma unroll
    for (int p = 0; p < 2; p++) {
        int e = tid + p * 256;
        ld_row[p] = e >> 2;
        ld_ch[p] = e & 3;
    }
    const int nc = DD / 32;   // 32

    #pragma unroll
    for (int p = 0; p < 2; p++) {
        int row = ld_row[p], ch = ld_ch[p];
        int so = row * 32 + SWZ(row, ch) * 8;
        cp16(&As[0][so], Ag + (size_t)row * DD + ch * 8);
        cp16(&Bs[0][so], Bg + (size_t)row * DD + ch * 8);
    }
    asm volatile("cp.async.commit_group;");

    for (int kc = 0; kc < nc; kc++) {
        if (kc + 1 < nc) {
            int s = (kc + 1) & 1;
            int koff = (kc + 1) * 32;
            #pragma unroll
            for (int p = 0; p < 2; p++) {
                int row = ld_row[p], ch = ld_ch[p];
                int so = row * 32 + SWZ(row, ch) * 8;
                cp16(&As[s][so], Ag + (size_t)row * DD + koff + ch * 8);
                cp16(&Bs[s][so], Bg + (size_t)row * DD + koff + ch * 8);
            }
            asm volatile("cp.async.commit_group;");
            asm volatile("cp.async.wait_group 1;");
        } else {
            asm volatile("cp.async.wait_group 0;");
        }
        __syncthreads();

        const __half* Asb = As[kc & 1];
        const __half* Bsb = Bs[kc & 1];

        #pragma unroll
        for (int kk = 0; kk < 2; kk++) {
            uint32_t af[2][4], bf[4][4];
            #pragma unroll
            for (int i = 0; i < 2; i++) {
                int row = warp_m * 32 + i * 16 + (lane & 15);
                int ch = kk * 2 + (lane >> 4);
                LDM4(af[i], Asb + row * 32 + SWZ(row, ch) * 8);
            }
            #pragma unroll
            for (int g = 0; g < 4; g++) {
                int row = warp_n * 64 + g * 16 + (lane & 7) + ((lane >> 4) << 3);
                int ch = kk * 2 + ((lane >> 3) & 1);
                LDM4(bf[g], Bsb + row * 32 + SWZ(row, ch) * 8);
            }
            #pragma unroll
            for (int i = 0; i < 2; i++)
                #pragma unroll
                for (int g = 0; g < 4; g++) {
                    MMAF16(c[i][g][0], af[i], bf[g][0], bf[g][1]);
                    MMAF16(c[i][g][1], af[i], bf[g][2], bf[g][3]);
                }
        }
        __syncthreads();
    }

    #pragma unroll
    for (int i = 0; i < 2; i++)
        #pragma unroll
        for (int g = 0; g < 4; g++)
            #pragma unroll
            for (int j = 0; j < 2; j++) {
                int rr = m0 + warp_m * 32 + i * 16 + (lane >> 2);
                int cc = n0 + warp_n * 64 + g * 16 + j * 8 + ((lane & 3) << 1);
                *(float2*)(ext_out + (size_t)rr * DD + cc) =
                    make_float2(c[i][g][j][0], c[i][g][j][1]);
                *(float2*)(ext_out + (size_t)(rr + 8) * DD + cc) =
                    make_float2(c[i][g][j][2], c[i][g][j][3]);
            }
}

// ---------------- tensor-core flash attention (128-row q tiles) ----------------
// grid (64 bh fast, 16 qt slow DESCENDING): heavy q-tiles launch first.
#define CLOG2E 0.18033688011112042f   // 0.125 * log2(e)

__global__ __launch_bounds__(256, 2) void attn_tc_kernel() {
    extern __shared__ __nv_bfloat16 smraw[];   // [2 stages][3 arrays: Kh,Vh,Vl][64*64]
    const int tid = threadIdx.x, lane = tid & 31, warp = tid >> 5;
    const int qt = (int)gridDim.y - 1 - (int)blockIdx.y;   // descending work order
    const int bh = blockIdx.x;
    const size_t bhbase = (size_t)bh * TT * SS;

    // ---- stage Q hi (128x64 = 1024 x 16B) into arrays 0,1 ----
    {
        const __nv_bfloat16* src = g_Qh + bhbase + (size_t)qt * 128 * 64;
        #pragma unroll
        for (int i = 0; i < 4; i++) {
            int idx = tid + 256 * i;                  // 0..1023
            int r = idx >> 3, ch = idx & 7;           // r in [0,128)
            int a = r >> 6, rl = r & 63;
            cp16(smraw + a * 4096 + rl * 64 + SWZ8(rl, ch), src + r * 64 + ch * 8);
        }
    }
    asm volatile("cp.async.commit_group;");
    asm volatile("cp.async.wait_group 0;");
    __syncthreads();

    uint32_t qh[4][4];
    {
        int r = warp * 16 + (lane & 15);
        int a = r >> 6, rl = r & 63;
        #pragma unroll
        for (int kk = 0; kk < 4; kk++) {
            int ch = kk * 2 + (lane >> 4);
            LDM4(qh[kk], smraw + a * 4096 + rl * 64 + SWZ8(rl, ch));
        }
    }
    __syncthreads();

    float oc[8][4];
    #pragma unroll
    for (int j = 0; j < 8; j++)
        #pragma unroll
        for (int q = 0; q < 4; q++) oc[j][q] = 0.0f;
    float m0 = -1e30f, m1 = -1e30f, l0 = 0.0f, l1 = 0.0f;

    const int rg = lane >> 2;
    const int cb = (lane & 3) << 1;
    const int brow = (lane & 7) + ((lane >> 4) << 3);
    const int bchx = (lane >> 3) & 1;
    const int vrow16 = ((lane >> 3) & 1) * 8 + (lane & 7);
    const int vchh = lane >> 4;
    const int ktmax = 2 * qt + 1;

    const __nv_bfloat16* kvsrc[3] = {g_Kh + bhbase, g_Vh + bhbase, g_Vl + bhbase};

    #define LOAD_KV(KT, ST) do { \
        _Pragma("unroll") \
        for (int _i = 0; _i < 6; _i++) { \
            int _g = tid + 256 * _i;           /* 0..1535 */ \
            int _arr = _g >> 9, _idx = _g & 511; \
            int _r = _idx >> 3, _ch = _idx & 7; \
            cp16(smraw + ((ST) * 3 + _arr) * 4096 + _r * 64 + SWZ8(_r, _ch), \
                 kvsrc[_arr] + (size_t)(KT) * 4096 + _r * 64 + _ch * 8); \
        } \
        asm volatile("cp.async.commit_group;"); \
    } while (0)

    LOAD_KV(0, 0);

    for (int kt = 0; kt <= ktmax; kt++) {
        const int st = kt & 1;
        if (kt < ktmax) {
            LOAD_KV(kt + 1, st ^ 1);
            asm volatile("cp.async.wait_group 1;");
        } else {
            asm volatile("cp.async.wait_group 0;");
        }
        __syncthreads();

        if (qt * 128 + warp * 16 + 15 >= kt * 64) {
            const __nv_bfloat16* Kh_ = smraw + (st * 3 + 0) * 4096;
            const __nv_bfloat16* Vh_ = smraw + (st * 3 + 1) * 4096;
            const __nv_bfloat16* Vl_ = smraw + (st * 3 + 2) * 4096;

            // ---- S = Q K^T (1-term bf16) ----
            float sc[8][4];
            #pragma unroll
            for (int j = 0; j < 8; j++)
                #pragma unroll
                for (int q = 0; q < 4; q++) sc[j][q] = 0.0f;
            #pragma unroll
            for (int g = 0; g < 4; g++) {
                int row = g * 16 + brow;
                #pragma unroll
                for (int kk = 0; kk < 4; kk++) {
                    int ch = kk * 2 + bchx;
                    uint32_t bh4[4];
                    LDM4(bh4, &Kh_[row * 64 + SWZ8(row, ch)]);
                    MMA16816(sc[2*g],   qh[kk], bh4[0], bh4[1]);
                    MMA16816(sc[2*g+1], qh[kk], bh4[2], bh4[3]);
                }
            }

            // ---- softmax ----
            float mx0 = -1e30f, mx1 = -1e30f;
            #pragma unroll
            for (int j = 0; j < 8; j++) {
                mx0 = fmaxf(mx0, fmaxf(sc[j][0], sc[j][1]));
                mx1 = fmaxf(mx1, fmaxf(sc[j][2], sc[j][3]));
            }
            mx0 = fmaxf(mx0, __shfl_xor_sync(0xffffffffu, mx0, 1));
            mx0 = fmaxf(mx0, __shfl_xor_sync(0xffffffffu, mx0, 2));
            mx1 = fmaxf(mx1, __shfl_xor_sync(0xffffffffu, mx1, 1));
            mx1 = fmaxf(mx1, __shfl_xor_sync(0xffffffffu, mx1, 2));
            float mn0 = fmaxf(m0, mx0 * CLOG2E);
            float mn1 = fmaxf(m1, mx1 * CLOG2E);
            float a0 = exp2p(m0 - mn0), a1 = exp2p(m1 - mn1);
            m0 = mn0; m1 = mn1;

            int base0 = qt * 128 + warp * 16 + rg - kt * 64 + 128;
            int base1 = base0 + 8;
            float ls0 = 0.0f, ls1 = 0.0f;
            #pragma unroll
            for (int j = 0; j < 8; j++) {
                int c0 = j * 8 + cb;
                float e0 = exp2p(fmaf(sc[j][0], CLOG2E, -mn0)) * __ldg(&g_ebias[base0 - c0]);
                float e1 = exp2p(fmaf(sc[j][1], CLOG2E, -mn0)) * __ldg(&g_ebias[base0 - c0 - 1]);
                float e2 = exp2p(fmaf(sc[j][2], CLOG2E, -mn1)) * __ldg(&g_ebias[base1 - c0]);
                float e3 = exp2p(fmaf(sc[j][3], CLOG2E, -mn1)) * __ldg(&g_ebias[base1 - c0 - 1]);
                sc[j][0] = e0; sc[j][1] = e1; sc[j][2] = e2; sc[j][3] = e3;
                ls0 += e0 + e1; ls1 += e2 + e3;
            }
            ls0 += __shfl_xor_sync(0xffffffffu, ls0, 1);
            ls0 += __shfl_xor_sync(0xffffffffu, ls0, 2);
            ls1 += __shfl_xor_sync(0xffffffffu, ls1, 1);
            ls1 += __shfl_xor_sync(0xffffffffu, ls1, 2);
            l0 = l0 * a0 + ls0;
            l1 = l1 * a1 + ls1;
            #pragma unroll
            for (int j = 0; j < 8; j++) {
                oc[j][0] *= a0; oc[j][1] *= a0; oc[j][2] *= a1; oc[j][3] *= a1;
            }

            // ---- repack P (C-frag -> A-frag, hi/lo) ----
            uint32_t pah[4][4], pal[4][4];
            #pragma unroll
            for (int kk = 0; kk < 4; kk++) {
                #pragma unroll
                for (int half = 0; half < 2; half++) {
                    int j = 2 * kk + half;
                    uint32_t u0 = __float_as_uint(sc[j][0]), u1 = __float_as_uint(sc[j][1]);
                    uint32_t u2 = __float_as_uint(sc[j][2]), u3 = __float_as_uint(sc[j][3]);
                    pah[kk][half * 2]     = prmt_hi(u0, u1);
                    pah[kk][half * 2 + 1] = prmt_hi(u2, u3);
                    float p0 = sc[j][0] - __uint_as_float(u0 & 0xffff0000u);
                    float p1 = sc[j][1] - __uint_as_float(u1 & 0xffff0000u);
                    float p2 = sc[j][2] - __uint_as_float(u2 & 0xffff0000u);
                    float p3 = sc[j][3] - __uint_as_float(u3 & 0xffff0000u);
                    pal[kk][half * 2]     = pack_bf16x2(p0, p1);
                    pal[kk][half * 2 + 1] = pack_bf16x2(p2, p3);
                }
            }

            // ---- O += P V (3-term; V row-major via ldmatrix.trans) ----
            #pragma unroll
            for (int g = 0; g < 4; g++) {
                int ch = 2 * g + vchh;
                #pragma unroll
                for (int kk = 0; kk < 4; kk++) {
                    int row = kk * 16 + vrow16;
                    uint32_t vh4[4], vl4[4];
                    LDM4T(vh4, &Vh_[row * 64 + SWZ8(row, ch)]);
                    MMA16816(oc[2*g],   pah[kk], vh4[0], vh4[1]);
                    MMA16816(oc[2*g+1], pah[kk], vh4[2], vh4[3]);
                    MMA16816(oc[2*g],   pal[kk], vh4[0], vh4[1]);
                    MMA16816(oc[2*g+1], pal[kk], vh4[2], vh4[3]);
                    LDM4T(vl4, &Vl_[row * 64 + SWZ8(row, ch)]);
                    MMA16816(oc[2*g],   pah[kk], vl4[0], vl4[1]);
                    MMA16816(oc[2*g+1], pah[kk], vl4[2], vl4[3]);
                }
            }
        }
        __syncthreads();
    }

    // ---- epilogue: write fp16 attention output, row-major [B*T, D] ----
    float inv0 = 1.0f / l0, inv1 = 1.0f / l1;
    int b = bh >> 4, hh = bh & 15;
    int t0 = qt * 128 + warp * 16 + rg;
    __half* rowp = g_AO + (size_t)(b * TT + t0) * DD + hh * 64 + cb;
    #pragma unroll
    for (int j = 0; j < 8; j++) {
        *(uint32_t*)(rowp + j * 8) = pack_f16x2(oc[j][0] * inv0, oc[j][1] * inv0);
        *(uint32_t*)(rowp + (size_t)8 * DD + j * 8) = pack_f16x2(oc[j][2] * inv1, oc[j][3] * inv1);
    }
}

// ---------------- launch ----------------
extern "C" void kernel_launch(void* const* d_in, const int* in_sizes, int n_in,
                              void* d_out, int out_size) {
    const float* x   = (const float*)d_in[0];
    const float* wq  = (const float*)d_in[1];
    const float* wk  = (const float*)d_in[2];
    const float* wv  = (const float*)d_in[3];
    const float* wo  = (const float*)d_in[4];
    const float* wu  = (const float*)d_in[5];
    const float* wsv = (const float*)d_in[6];
    const float* ps  = (const float*)d_in[7];
    float* out = (float*)d_out;

    static int smem_set = 0;
    if (!smem_set) {
        cudaFuncSetAttribute(attn_tc_kernel, cudaFuncAttributeMaxDynamicSharedMemorySize, 49152);
        smem_set = 1;
    }

    zero_absmax_kernel<<<1, 32>>>();
    absmax_all_kernel<<<dim3(64, 6), 256>>>(wq, wk, wv, wo, wu, wsv);
    build_ebias_kernel<<<9, 256>>>(ps);
    compose_split_kernel<<<dim3(8, 16, 2), 256>>>(wq, wk, wu, wsv);
    split_w_vo_kernel<<<dim3(DD*DD/1024, 2), 256>>>(wv, wo);
    split_act_kernel<<<MM*DD/1024, 256>>>(x);
    gemm_bf16_kernel<<<dim3(DD/128, MM/128, 3), 256>>>();             // QKV, V heavy-first
    attn_tc_kernel<<<dim3(BB*HH, TT/128), 256, 49152>>>();            // qt slow, descending
    gemm_o_f16_kernel<<<dim3(DD/128, MM/128), 256>>>(out);            // O: fp16 1-term
}

// round 13
// speedup vs baseline: 5.2698x; 1.0564x over previous
#include <cuda_runtime.h>
#include <cuda_bf16.h>
#include <cuda_fp16.h>
#include <cstdint>

#define BB 4
#define TT 2048
#define DD 1024
#define HH 16
#define SS 64
#define MM (BB*TT)
#define K3 3072          // [hi | lo | hi] segments of K=1024
#define EBN 2208         // ebias table size (index = d + 128)

// ---------------- device scratch (static, allocation-free) ----------------
__device__ float g_absmax[8];
__device__ __nv_bfloat16 g_Qh[(size_t)BB*HH*TT*SS];
__device__ __nv_bfloat16 g_Kh[(size_t)BB*HH*TT*SS];
__device__ __half g_Vh[(size_t)BB*HH*TT*SS], g_Vl[(size_t)BB*HH*TT*SS];  // fp16 split V
__device__ __nv_bfloat16 g_A3[(size_t)MM*K3];       // split activations (x)
__device__ __nv_bfloat16 g_W3[(size_t)4*DD*K3];     // split weights (q,k,v)
__device__ __half g_AO[(size_t)MM*DD];              // attention output, fp16
__device__ __half g_wo_f16[(size_t)DD*DD];          // quantized wo, fp16
__device__ float g_ebias[EBN];

// ---------------- prep ----------------
__global__ void zero_absmax_kernel() {
    if (threadIdx.x < 8) g_absmax[threadIdx.x] = 0.0f;
}

__global__ void absmax_all_kernel(const float* __restrict__ wq, const float* __restrict__ wk,
                                  const float* __restrict__ wv, const float* __restrict__ wo,
                                  const float* __restrict__ wu, const float* __restrict__ wsv) {
    int slot = blockIdx.y;
    const float* w = (slot == 0) ? wq : (slot == 1) ? wk : (slot == 2) ? wv
                   : (slot == 3) ? wo : (slot == 4) ? wu : wsv;
    int n = (slot < 4) ? DD * DD : SS * SS;
    float m = 0.0f;
    for (int i = blockIdx.x * blockDim.x + threadIdx.x; i < n; i += gridDim.x * blockDim.x)
        m = fmaxf(m, fabsf(w[i]));
    #pragma unroll
    for (int o = 16; o > 0; o >>= 1) m = fmaxf(m, __shfl_xor_sync(0xffffffffu, m, o));
    __shared__ float sm[8];
    int lane = threadIdx.x & 31, wid = threadIdx.x >> 5;
    if (lane == 0) sm[wid] = m;
    __syncthreads();
    if (wid == 0) {
        int nw = blockDim.x >> 5;
        m = (lane < nw) ? sm[lane] : 0.0f;
        #pragma unroll
        for (int o = 4; o > 0; o >>= 1) m = fmaxf(m, __shfl_xor_sync(0xffffffffu, m, o));
        if (lane == 0) atomicMax((int*)&g_absmax[slot], __float_as_int(m));
    }
}

__global__ void build_ebias_kernel(const float* __restrict__ ps) {
    int i = blockIdx.x * 256 + threadIdx.x;
    if (i >= EBN) return;
    float v = 0.0f;
    if (i >= 128 && i < 128 + 2048) {
        int d = i - 128;
        float bias = (d == 0) ? 1.0f : (float)min(__ffs(d) - 1, 16) * 0.0625f;
        v = __expf(ps[0] * bias);
    }
    g_ebias[i] = v;
}

// ---------------- PTX helpers ----------------
__device__ __forceinline__ void cp16(void* dst, const void* src) {
    unsigned d = (unsigned)__cvta_generic_to_shared(dst);
    asm volatile("cp.async.cg.shared.global [%0], [%1], 16;\n" :: "r"(d), "l"(src));
}
#define LDM4(R, PTR) do { \
    unsigned _a = (unsigned)__cvta_generic_to_shared(PTR); \
    asm volatile("ldmatrix.sync.aligned.m8n8.x4.shared.b16 {%0,%1,%2,%3}, [%4];" \
        : "=r"((R)[0]), "=r"((R)[1]), "=r"((R)[2]), "=r"((R)[3]) : "r"(_a)); \
} while (0)
#define LDM4T(R, PTR) do { \
    unsigned _a = (unsigned)__cvta_generic_to_shared(PTR); \
    asm volatile("ldmatrix.sync.aligned.m8n8.x4.trans.shared.b16 {%0,%1,%2,%3}, [%4];" \
        : "=r"((R)[0]), "=r"((R)[1]), "=r"((R)[2]), "=r"((R)[3]) : "r"(_a)); \
} while (0)
#define MMA16816(C, A, B0, B1) \
    asm volatile("mma.sync.aligned.m16n8k16.row.col.f32.bf16.bf16.f32 " \
        "{%0,%1,%2,%3}, {%4,%5,%6,%7}, {%8,%9}, {%0,%1,%2,%3};" \
        : "+f"((C)[0]), "+f"((C)[1]), "+f"((C)[2]), "+f"((C)[3]) \
        : "r"((A)[0]), "r"((A)[1]), "r"((A)[2]), "r"((A)[3]), "r"(B0), "r"(B1))
#define MMAF16(C, A, B0, B1) \
    asm volatile("mma.sync.aligned.m16n8k16.row.col.f32.f16.f16.f32 " \
        "{%0,%1,%2,%3}, {%4,%5,%6,%7}, {%8,%9}, {%0,%1,%2,%3};" \
        : "+f"((C)[0]), "+f"((C)[1]), "+f"((C)[2]), "+f"((C)[3]) \
        : "r"((A)[0]), "r"((A)[1]), "r"((A)[2]), "r"((A)[3]), "r"(B0), "r"(B1))
#define SWZ(row, ch) ((ch) ^ (((row) >> 1) & 3))
#define SWZ8(row, ch) (((ch) ^ ((row) & 7)) << 3)

__device__ __forceinline__ uint32_t prmt_hi(uint32_t a, uint32_t b) {
    uint32_t r;
    asm("prmt.b32 %0, %1, %2, 0x7632;" : "=r"(r) : "r"(a), "r"(b));
    return r;
}
__device__ __forceinline__ uint32_t pack_bf16x2(float lo, float hi) {
    uint32_t r;
    asm("cvt.rn.bf16x2.f32 %0, %1, %2;" : "=r"(r) : "f"(hi), "f"(lo));
    return r;
}
__device__ __forceinline__ uint32_t pack_f16x2(float lo, float hi) {
    uint32_t r;
    asm("cvt.rn.f16x2.f32 %0, %1, %2;" : "=r"(r) : "f"(hi), "f"(lo));
    return r;
}
__device__ __forceinline__ float exp2p(float y) {   // fast 2^y, fma/alu only
    y = fmaxf(y, -125.0f);
    float z = y + 12582912.0f;
    float f = y - (z - 12582912.0f);
    int e = __float_as_int(z) << 23;
    float r = 0.0013333558146f;
    r = fmaf(r, f, 0.0096181291076f);
    r = fmaf(r, f, 0.055504108664f);
    r = fmaf(r, f, 0.24022650696f);
    r = fmaf(r, f, 0.69314718056f);
    r = fmaf(r, f, 1.0f);
    return __int_as_float(__float_as_int(r) + e);
}
// fp16 hi/lo split (RN hi + exact fp16 residual)
__device__ __forceinline__ void emit_hl_f16(__half* dh, __half* dl, float f0, float f1) {
    uint32_t h = pack_f16x2(f0, f1);
    __half2 hv = *(__half2*)&h;
    float r0 = f0 - __half2float(__low2half(hv));
    float r1 = f1 - __half2float(__high2half(hv));
    *(uint32_t*)dh = h;
    *(uint32_t*)dl = pack_f16x2(r0, r1);
}
// [hi | lo | hi] into an A3-style row (stride 1024 between segments)
__device__ __forceinline__ void store3(__nv_bfloat16* p, float f0, float f1) {
    uint32_t u0 = __float_as_uint(f0), u1 = __float_as_uint(f1);
    uint32_t hi = prmt_hi(u0, u1);
    uint32_t lo = pack_bf16x2(f0 - __uint_as_float(u0 & 0xffff0000u),
                              f1 - __uint_as_float(u1 & 0xffff0000u));
    *(uint32_t*)p = hi;
    *(uint32_t*)(p + 2048) = hi;
    *(uint32_t*)(p + 1024) = lo;
}
// [hi | hi | lo] into a W3 row
__device__ __forceinline__ void storeW3(__nv_bfloat16* p, float f0, float f1) {
    uint32_t u0 = __float_as_uint(f0), u1 = __float_as_uint(f1);
    uint32_t hi = prmt_hi(u0, u1);
    uint32_t lo = pack_bf16x2(f0 - __uint_as_float(u0 & 0xffff0000u),
                              f1 - __uint_as_float(u1 & 0xffff0000u));
    *(uint32_t*)p = hi;
    *(uint32_t*)(p + 1024) = hi;
    *(uint32_t*)(p + 2048) = lo;
}
__device__ __forceinline__ float quant6(float w, float sc) {
    float q = rintf(w / sc);
    return fminf(fmaxf(q, -31.0f), 31.0f) * sc;
}

// ---------------- compose (stalk-fold) + quant + split, fused ----------------
__global__ __launch_bounds__(256) void compose_split_kernel(
        const float* __restrict__ wq, const float* __restrict__ wk,
        const float* __restrict__ wu, const float* __restrict__ wsv) {
    __shared__ float ws[64][64];
    __shared__ float wb[64][128];
    const int which = blockIdx.z, h = blockIdx.y, kc = blockIdx.x;
    const float* wsmall = which ? wsv : wu;
    const float* wbig   = which ? wk  : wq;
    const float scb = g_absmax[which ? 1 : 0] / 31.0f + 1e-8f;
    const float scs = g_absmax[which ? 5 : 4] / 31.0f + 1e-8f;
    const int tid = threadIdx.x;

    for (int idx = tid; idx < 4096; idx += 256)
        ws[idx >> 6][idx & 63] = quant6(wsmall[idx], scs);
    for (int idx = tid; idx < 8192; idx += 256) {
        int s = idx >> 7, k = idx & 127;
        wb[s][k] = quant6(wbig[(size_t)(h * 64 + s) * DD + kc * 128 + k], scb);
    }
    __syncthreads();

    const int tx = tid & 31, ty = tid >> 5;
    const int k0 = tx * 4, sp0 = ty * 8;
    float acc[8][4];
    #pragma unroll
    for (int i = 0; i < 8; i++)
        #pragma unroll
        for (int j = 0; j < 4; j++) acc[i][j] = 0.0f;
    #pragma unroll 8
    for (int s = 0; s < 64; s++) {
        float4 b = *(const float4*)&wb[s][k0];
        #pragma unroll
        for (int i = 0; i < 8; i++) {
            float a = ws[sp0 + i][s];
            acc[i][0] = fmaf(a, b.x, acc[i][0]);
            acc[i][1] = fmaf(a, b.y, acc[i][1]);
            acc[i][2] = fmaf(a, b.z, acc[i][2]);
            acc[i][3] = fmaf(a, b.w, acc[i][3]);
        }
    }
    __nv_bfloat16* o = g_W3 + (size_t)which * DD * K3;
    #pragma unroll
    for (int i = 0; i < 8; i++) {
        __nv_bfloat16* p = o + (size_t)(h * 64 + sp0 + i) * K3 + kc * 128 + k0;
        storeW3(p, acc[i][0], acc[i][1]);
        storeW3(p + 2, acc[i][2], acc[i][3]);
    }
}

// ---------------- wv -> W3 3-term; wo -> fp16 ----------------
__global__ void split_w_vo_kernel(const float* __restrict__ wv, const float* __restrict__ wo) {
    int is_o = blockIdx.y;
    const float* src = is_o ? wo : wv;
    float sc = g_absmax[2 + is_o] / 31.0f + 1e-8f;
    int i = blockIdx.x * 256 + threadIdx.x;
    int row = i >> 8;
    int k4 = (i & 255) * 4;
    float4 v = *(const float4*)(src + (size_t)row * DD + k4);
    v.x = quant6(v.x, sc); v.y = quant6(v.y, sc);
    v.z = quant6(v.z, sc); v.w = quant6(v.w, sc);
    if (is_o) {
        __half* o = g_wo_f16 + (size_t)row * DD + k4;
        *(uint32_t*)o = pack_f16x2(v.x, v.y);
        *(uint32_t*)(o + 2) = pack_f16x2(v.z, v.w);
    } else {
        __nv_bfloat16* o = g_W3 + (size_t)2 * DD * K3 + (size_t)row * K3 + k4;
        storeW3(o, v.x, v.y);
        storeW3(o + 2, v.z, v.w);
    }
}

// ---------------- x -> A3 [hi|lo|hi] ----------------
__global__ void split_act_kernel(const float* __restrict__ src) {
    int i = blockIdx.x * 256 + threadIdx.x;
    int row = i >> 8;
    int k4 = (i & 255) * 4;
    float4 v = *(const float4*)(src + (size_t)row * DD + k4);
    __nv_bfloat16* o = g_A3 + (size_t)row * K3 + k4;
    store3(o, v.x, v.y);
    store3(o + 2, v.z, v.w);
}

// ---------------- bf16 tensor-core GEMM: QKV (z=0 -> V nc=96 heavy-first; Q,K nc=32) ----
__global__ __launch_bounds__(256, 2) void gemm_bf16_kernel() {
    const int which = (blockIdx.z == 0) ? 2 : (blockIdx.z == 1) ? 0 : 1;
    const int nc = (which == 2) ? 96 : 32;
    __shared__ alignas(16) __nv_bfloat16 As[2][128 * 32];
    __shared__ alignas(16) __nv_bfloat16 Bs[2][128 * 32];

    const __nv_bfloat16* __restrict__ Wg = g_W3 + (size_t)which * DD * K3;
    const int tid = threadIdx.x;
    const int lane = tid & 31, wid = tid >> 5;
    const int warp_m = wid >> 1, warp_n = wid & 1;
    const int m0 = blockIdx.y * 128;
    const int n0 = blockIdx.x * 128;

    const __nv_bfloat16* Ag = g_A3 + (size_t)m0 * K3;
    const __nv_bfloat16* Bg = Wg + (size_t)n0 * K3;

    float c[2][4][2][4];
    #pragma unroll
    for (int i = 0; i < 2; i++)
        #pragma unroll
        for (int g = 0; g < 4; g++)
            #pragma unroll
            for (int j = 0; j < 2; j++)
                #pragma unroll
                for (int q = 0; q < 4; q++) c[i][g][j][q] = 0.0f;

    int ld_row[2], ld_ch[2];
    #pragma unroll
    for (int p = 0; p < 2; p++) {
        int e = tid + p * 256;
        ld_row[p] = e >> 2;
        ld_ch[p] = e & 3;
    }

    #pragma unroll
    for (int p = 0; p < 2; p++) {
        int row = ld_row[p], ch = ld_ch[p];
        int so = row * 32 + SWZ(row, ch) * 8;
        cp16(&As[0][so], Ag + (size_t)row * K3 + ch * 8);
        cp16(&Bs[0][so], Bg + (size_t)row * K3 + ch * 8);
    }
    asm volatile("cp.async.commit_group;");

    for (int kc = 0; kc < nc; kc++) {
        if (kc + 1 < nc) {
            int s = (kc + 1) & 1;
            int koff = (kc + 1) * 32;
            #pragma unroll
            for (int p = 0; p < 2; p++) {
                int row = ld_row[p], ch = ld_ch[p];
                int so = row * 32 + SWZ(row, ch) * 8;
                cp16(&As[s][so], Ag + (size_t)row * K3 + koff + ch * 8);
                cp16(&Bs[s][so], Bg + (size_t)row * K3 + koff + ch * 8);
            }
            asm volatile("cp.async.commit_group;");
            asm volatile("cp.async.wait_group 1;");
        } else {
            asm volatile("cp.async.wait_group 0;");
        }
        __syncthreads();

        const __nv_bfloat16* Asb = As[kc & 1];
        const __nv_bfloat16* Bsb = Bs[kc & 1];

        #pragma unroll
        for (int kk = 0; kk < 2; kk++) {
            uint32_t af[2][4], bf[4][4];
            #pragma unroll
            for (int i = 0; i < 2; i++) {
                int row = warp_m * 32 + i * 16 + (lane & 15);
                int ch = kk * 2 + (lane >> 4);
                LDM4(af[i], Asb + row * 32 + SWZ(row, ch) * 8);
            }
            #pragma unroll
            for (int g = 0; g < 4; g++) {
                int row = warp_n * 64 + g * 16 + (lane & 7) + ((lane >> 4) << 3);
                int ch = kk * 2 + ((lane >> 3) & 1);
                LDM4(bf[g], Bsb + row * 32 + SWZ(row, ch) * 8);
            }
            #pragma unroll
            for (int i = 0; i < 2; i++)
                #pragma unroll
                for (int g = 0; g < 4; g++) {
                    MMA16816(c[i][g][0], af[i], bf[g][0], bf[g][1]);
                    MMA16816(c[i][g][1], af[i], bf[g][2], bf[g][3]);
                }
        }
        __syncthreads();
    }

    // epilogue
    #pragma unroll
    for (int i = 0; i < 2; i++)
        #pragma unroll
        for (int g = 0; g < 4; g++)
            #pragma unroll
            for (int j = 0; j < 2; j++) {
                int rr = m0 + warp_m * 32 + i * 16 + (lane >> 2);
                int cc = n0 + warp_n * 64 + g * 16 + j * 8 + ((lane & 3) << 1);
                int b = rr >> 11, t = rr & 2047;
                int hh = cc >> 6, s2 = cc & 63;
                size_t off = ((size_t)(b * HH + hh) * TT + t) * SS + s2;
                if (which < 2) {           // Q/K: bf16 rounded
                    __nv_bfloat16* dh = (which == 0) ? g_Qh : g_Kh;
                    *(uint32_t*)(dh + off) = pack_bf16x2(c[i][g][j][0], c[i][g][j][1]);
                    *(uint32_t*)(dh + off + 8 * SS) = pack_bf16x2(c[i][g][j][2], c[i][g][j][3]);
                } else {                   // V: fp16 hi + lo
                    emit_hl_f16(g_Vh + off, g_Vl + off, c[i][g][j][0], c[i][g][j][1]);
                    emit_hl_f16(g_Vh + off + 8 * SS, g_Vl + off + 8 * SS, c[i][g][j][2], c[i][g][j][3]);
                }
            }
}

// ---------------- fp16 O GEMM: out[M,D] = AO[M,D] @ wo_f16[D,D]^T ----------------
__global__ __launch_bounds__(256, 2) void gemm_o_f16_kernel(float* __restrict__ ext_out) {
    __shared__ alignas(16) __half As[2][128 * 32];
    __shared__ alignas(16) __half Bs[2][128 * 32];

    const int tid = threadIdx.x;
    const int lane = tid & 31, wid = tid >> 5;
    const int warp_m = wid >> 1, warp_n = wid & 1;
    const int m0 = blockIdx.y * 128;
    const int n0 = blockIdx.x * 128;

    const __half* Ag = g_AO + (size_t)m0 * DD;
    const __half* Bg = g_wo_f16 + (size_t)n0 * DD;

    float c[2][4][2][4];
    #pragma unroll
    for (int i = 0; i < 2; i++)
        #pragma unroll
        for (int g = 0; g < 4; g++)
            #pragma unroll
            for (int j = 0; j < 2; j++)
                #pragma unroll
                for (int q = 0; q < 4; q++) c[i][g][j][q] = 0.0f;

    int ld_row[2], ld_ch[2];
    #pragma unroll
    for (int p = 0; p < 2; p++) {
        int e = tid + p * 256;
        ld_row[p] = e >> 2;
        ld_ch[p] = e & 3;
    }
    const int nc = DD / 32;   // 32

    #pragma unroll
    for (int p = 0; p < 2; p++) {
        int row = ld_row[p], ch = ld_ch[p];
        int so = row * 32 + SWZ(row, ch) * 8;
        cp16(&As[0][so], Ag + (size_t)row * DD + ch * 8);
        cp16(&Bs[0][so], Bg + (size_t)row * DD + ch * 8);
    }
    asm volatile("cp.async.commit_group;");

    for (int kc = 0; kc < nc; kc++) {
        if (kc + 1 < nc) {
            int s = (kc + 1) & 1;
            int koff = (kc + 1) * 32;
            #pragma unroll
            for (int p = 0; p < 2; p++) {
                int row = ld_row[p], ch = ld_ch[p];
                int so = row * 32 + SWZ(row, ch) * 8;
                cp16(&As[s][so], Ag + (size_t)row * DD + koff + ch * 8);
                cp16(&Bs[s][so], Bg + (size_t)row * DD + koff + ch * 8);
            }
            asm volatile("cp.async.commit_group;");
            asm volatile("cp.async.wait_group 1;");
        } else {
            asm volatile("cp.async.wait_group 0;");
        }
        __syncthreads();

        const __half* Asb = As[kc & 1];
        const __half* Bsb = Bs[kc & 1];

        #pragma unroll
        for (int kk = 0; kk < 2; kk++) {
            uint32_t af[2][4], bf[4][4];
            #pragma unroll
            for (int i = 0; i < 2; i++) {
                int row = warp_m * 32 + i * 16 + (lane & 15);
                int ch = kk * 2 + (lane >> 4);
                LDM4(af[i], Asb + row * 32 + SWZ(row, ch) * 8);
            }
            #pragma unroll
            for (int g = 0; g < 4; g++) {
                int row = warp_n * 64 + g * 16 + (lane & 7) + ((lane >> 4) << 3);
                int ch = kk * 2 + ((lane >> 3) & 1);
                LDM4(bf[g], Bsb + row * 32 + SWZ(row, ch) * 8);
            }
            #pragma unroll
            for (int i = 0; i < 2; i++)
                #pragma unroll
                for (int g = 0; g < 4; g++) {
                    MMAF16(c[i][g][0], af[i], bf[g][0], bf[g][1]);
                    MMAF16(c[i][g][1], af[i], bf[g][2], bf[g][3]);
                }
        }
        __syncthreads();
    }

    #pragma unroll
    for (int i = 0; i < 2; i++)
        #pragma unroll
        for (int g = 0; g < 4; g++)
            #pragma unroll
            for (int j = 0; j < 2; j++) {
                int rr = m0 + warp_m * 32 + i * 16 + (lane >> 2);
                int cc = n0 + warp_n * 64 + g * 16 + j * 8 + ((lane & 3) << 1);
                *(float2*)(ext_out + (size_t)rr * DD + cc) =
                    make_float2(c[i][g][j][0], c[i][g][j][1]);
                *(float2*)(ext_out + (size_t)(rr + 8) * DD + cc) =
                    make_float2(c[i][g][j][2], c[i][g][j][3]);
            }
}

// ---------------- tensor-core flash attention (128-row q tiles) ----------------
// grid (64 bh fast, 16 qt slow DESCENDING): heavy q-tiles launch first.
#define CLOG2E 0.18033688011112042f   // 0.125 * log2(e)

__global__ __launch_bounds__(256, 2) void attn_tc_kernel() {
    extern __shared__ __nv_bfloat16 smraw[];   // [2 stages][3 arrays: Kh(bf16),Vh(f16),Vl(f16)][64*64]
    const int tid = threadIdx.x, lane = tid & 31, warp = tid >> 5;
    const int qt = (int)gridDim.y - 1 - (int)blockIdx.y;   // descending work order
    const int bh = blockIdx.x;
    const size_t bhbase = (size_t)bh * TT * SS;

    // ---- stage Q hi (128x64 = 1024 x 16B) into arrays 0,1 ----
    {
        const __nv_bfloat16* src = g_Qh + bhbase + (size_t)qt * 128 * 64;
        #pragma unroll
        for (int i = 0; i < 4; i++) {
            int idx = tid + 256 * i;                  // 0..1023
            int r = idx >> 3, ch = idx & 7;           // r in [0,128)
            int a = r >> 6, rl = r & 63;
            cp16(smraw + a * 4096 + rl * 64 + SWZ8(rl, ch), src + r * 64 + ch * 8);
        }
    }
    asm volatile("cp.async.commit_group;");
    asm volatile("cp.async.wait_group 0;");
    __syncthreads();

    uint32_t qh[4][4];
    {
        int r = warp * 16 + (lane & 15);
        int a = r >> 6, rl = r & 63;
        #pragma unroll
        for (int kk = 0; kk < 4; kk++) {
            int ch = kk * 2 + (lane >> 4);
            LDM4(qh[kk], smraw + a * 4096 + rl * 64 + SWZ8(rl, ch));
        }
    }
    __syncthreads();

    float oc[8][4];
    #pragma unroll
    for (int j = 0; j < 8; j++)
        #pragma unroll
        for (int q = 0; q < 4; q++) oc[j][q] = 0.0f;
    float m0 = -1e30f, m1 = -1e30f, l0 = 0.0f, l1 = 0.0f;

    const int rg = lane >> 2;
    const int cb = (lane & 3) << 1;
    const int brow = (lane & 7) + ((lane >> 4) << 3);
    const int bchx = (lane >> 3) & 1;
    const int vrow16 = ((lane >> 3) & 1) * 8 + (lane & 7);
    const int vchh = lane >> 4;
    const int ktmax = 2 * qt + 1;

    // all three arrays are 2-byte elements; treat uniformly as bf16* for copies
    const __nv_bfloat16* kvsrc[3] = {g_Kh + bhbase,
                                     (const __nv_bfloat16*)(g_Vh + bhbase),
                                     (const __nv_bfloat16*)(g_Vl + bhbase)};

    #define LOAD_KV(KT, ST) do { \
        _Pragma("unroll") \
        for (int _i = 0; _i < 6; _i++) { \
            int _g = tid + 256 * _i;           /* 0..1535 */ \
            int _arr = _g >> 9, _idx = _g & 511; \
            int _r = _idx >> 3, _ch = _idx & 7; \
            cp16(smraw + ((ST) * 3 + _arr) * 4096 + _r * 64 + SWZ8(_r, _ch), \
                 kvsrc[_arr] + (size_t)(KT) * 4096 + _r * 64 + _ch * 8); \
        } \
        asm volatile("cp.async.commit_group;"); \
    } while (0)

    LOAD_KV(0, 0);

    for (int kt = 0; kt <= ktmax; kt++) {
        const int st = kt & 1;
        if (kt < ktmax) {
            LOAD_KV(kt + 1, st ^ 1);
            asm volatile("cp.async.wait_group 1;");
        } else {
            asm volatile("cp.async.wait_group 0;");
        }
        __syncthreads();

        if (qt * 128 + warp * 16 + 15 >= kt * 64) {
            const __nv_bfloat16* Kh_ = smraw + (st * 3 + 0) * 4096;
            const __nv_bfloat16* Vh_ = smraw + (st * 3 + 1) * 4096;   // fp16 bits
            const __nv_bfloat16* Vl_ = smraw + (st * 3 + 2) * 4096;   // fp16 bits

            // ---- S = Q K^T (1-term bf16) ----
            float sc[8][4];
            #pragma unroll
            for (int j = 0; j < 8; j++)
                #pragma unroll
                for (int q = 0; q < 4; q++) sc[j][q] = 0.0f;
            #pragma unroll
            for (int g = 0; g < 4; g++) {
                int row = g * 16 + brow;
                #pragma unroll
                for (int kk = 0; kk < 4; kk++) {
                    int ch = kk * 2 + bchx;
                    uint32_t bh4[4];
                    LDM4(bh4, &Kh_[row * 64 + SWZ8(row, ch)]);
                    MMA16816(sc[2*g],   qh[kk], bh4[0], bh4[1]);
                    MMA16816(sc[2*g+1], qh[kk], bh4[2], bh4[3]);
                }
            }

            // ---- softmax ----
            float mx0 = -1e30f, mx1 = -1e30f;
            #pragma unroll
            for (int j = 0; j < 8; j++) {
                mx0 = fmaxf(mx0, fmaxf(sc[j][0], sc[j][1]));
                mx1 = fmaxf(mx1, fmaxf(sc[j][2], sc[j][3]));
            }
            mx0 = fmaxf(mx0, __shfl_xor_sync(0xffffffffu, mx0, 1));
            mx0 = fmaxf(mx0, __shfl_xor_sync(0xffffffffu, mx0, 2));
            mx1 = fmaxf(mx1, __shfl_xor_sync(0xffffffffu, mx1, 1));
            mx1 = fmaxf(mx1, __shfl_xor_sync(0xffffffffu, mx1, 2));
            float mn0 = fmaxf(m0, mx0 * CLOG2E);
            float mn1 = fmaxf(m1, mx1 * CLOG2E);
            float a0 = exp2p(m0 - mn0), a1 = exp2p(m1 - mn1);
            m0 = mn0; m1 = mn1;

            int base0 = qt * 128 + warp * 16 + rg - kt * 64 + 128;
            int base1 = base0 + 8;
            float ls0 = 0.0f, ls1 = 0.0f;
            #pragma unroll
            for (int j = 0; j < 8; j++) {
                int c0 = j * 8 + cb;
                float e0 = exp2p(fmaf(sc[j][0], CLOG2E, -mn0)) * __ldg(&g_ebias[base0 - c0]);
                float e1 = exp2p(fmaf(sc[j][1], CLOG2E, -mn0)) * __ldg(&g_ebias[base0 - c0 - 1]);
                float e2 = exp2p(fmaf(sc[j][2], CLOG2E, -mn1)) * __ldg(&g_ebias[base1 - c0]);
                float e3 = exp2p(fmaf(sc[j][3], CLOG2E, -mn1)) * __ldg(&g_ebias[base1 - c0 - 1]);
                sc[j][0] = e0; sc[j][1] = e1; sc[j][2] = e2; sc[j][3] = e3;
                ls0 += e0 + e1; ls1 += e2 + e3;
            }
            ls0 += __shfl_xor_sync(0xffffffffu, ls0, 1);
            ls0 += __shfl_xor_sync(0xffffffffu, ls0, 2);
            ls1 += __shfl_xor_sync(0xffffffffu, ls1, 1);
            ls1 += __shfl_xor_sync(0xffffffffu, ls1, 2);
            l0 = l0 * a0 + ls0;
            l1 = l1 * a1 + ls1;
            #pragma unroll
            for (int j = 0; j < 8; j++) {
                oc[j][0] *= a0; oc[j][1] *= a0; oc[j][2] *= a1; oc[j][3] *= a1;
            }

            // ---- repack P (C-frag -> A-frag, RN fp16) ----
            uint32_t pah[4][4];
            #pragma unroll
            for (int kk = 0; kk < 4; kk++) {
                #pragma unroll
                for (int half = 0; half < 2; half++) {
                    int j = 2 * kk + half;
                    pah[kk][half * 2]     = pack_f16x2(sc[j][0], sc[j][1]);
                    pah[kk][half * 2 + 1] = pack_f16x2(sc[j][2], sc[j][3]);
                }
            }

            // ---- O += P V (2-term fp16; V row-major via ldmatrix.trans) ----
            #pragma unroll
            for (int g = 0; g < 4; g++) {
                int ch = 2 * g + vchh;
                #pragma unroll
                for (int kk = 0; kk < 4; kk++) {
                    int row = kk * 16 + vrow16;
                    uint32_t vh4[4], vl4[4];
                    LDM4T(vh4, &Vh_[row * 64 + SWZ8(row, ch)]);
                    MMAF16(oc[2*g],   pah[kk], vh4[0], vh4[1]);
                    MMAF16(oc[2*g+1], pah[kk], vh4[2], vh4[3]);
                    LDM4T(vl4, &Vl_[row * 64 + SWZ8(row, ch)]);
                    MMAF16(oc[2*g],   pah[kk], vl4[0], vl4[1]);
                    MMAF16(oc[2*g+1], pah[kk], vl4[2], vl4[3]);
                }
            }
        }
        __syncthreads();
    }

    // ---- epilogue: write fp16 attention output, row-major [B*T, D] ----
    float inv0 = 1.0f / l0, inv1 = 1.0f / l1;
    int b = bh >> 4, hh = bh & 15;
    int t0 = qt * 128 + warp * 16 + rg;
    __half* rowp = g_AO + (size_t)(b * TT + t0) * DD + hh * 64 + cb;
    #pragma unroll
    for (int j = 0; j < 8; j++) {
        *(uint32_t*)(rowp + j * 8) = pack_f16x2(oc[j][0] * inv0, oc[j][1] * inv0);
        *(uint32_t*)(rowp + (size_t)8 * DD + j * 8) = pack_f16x2(oc[j][2] * inv1, oc[j][3] * inv1);
    }
}

// ---------------- launch ----------------
extern "C" void kernel_launch(void* const* d_in, const int* in_sizes, int n_in,
                              void* d_out, int out_size) {
    const float* x   = (const float*)d_in[0];
    const float* wq  = (const float*)d_in[1];
    const float* wk  = (const float*)d_in[2];
    const float* wv  = (const float*)d_in[3];
    const float* wo  = (const float*)d_in[4];
    const float* wu  = (const float*)d_in[5];
    const float* wsv = (const float*)d_in[6];
    const float* ps  = (const float*)d_in[7];
    float* out = (float*)d_out;

    static int smem_set = 0;
    if (!smem_set) {
        cudaFuncSetAttribute(attn_tc_kernel, cudaFuncAttributeMaxDynamicSharedMemorySize, 49152);
        smem_set = 1;
    }

    zero_absmax_kernel<<<1, 32>>>();
    absmax_all_kernel<<<dim3(64, 6), 256>>>(wq, wk, wv, wo, wu, wsv);
    build_ebias_kernel<<<9, 256>>>(ps);
    compose_split_kernel<<<dim3(8, 16, 2), 256>>>(wq, wk, wu, wsv);
    split_w_vo_kernel<<<dim3(DD*DD/1024, 2), 256>>>(wv, wo);
    split_act_kernel<<<MM*DD/1024, 256>>>(x);
    gemm_bf16_kernel<<<dim3(DD/128, MM/128, 3), 256>>>();             // QKV, V heavy-first
    attn_tc_kernel<<<dim3(BB*HH, TT/128), 256, 49152>>>();            // qt slow, descending
    gemm_o_f16_kernel<<<dim3(DD/128, MM/128), 256>>>(out);            // O: fp16 1-term
}

// round 14
// speedup vs baseline: 5.6765x; 1.0772x over previous
#include <cuda_runtime.h>
#include <cuda_bf16.h>
#include <cuda_fp16.h>
#include <cstdint>

#define BB 4
#define TT 2048
#define DD 1024
#define HH 16
#define SS 64
#define MM (BB*TT)
#define K2 2048          // [hi | lo] fp16 segments of K=1024
#define EBN 2208         // ebias table size (index = d + 128)

// ---------------- device scratch (static, allocation-free) ----------------
__device__ float g_absmax[8];
__device__ __half g_Qh[(size_t)BB*HH*TT*SS];
__device__ __half g_Kh[(size_t)BB*HH*TT*SS];
__device__ __half g_Vh[(size_t)BB*HH*TT*SS], g_Vl[(size_t)BB*HH*TT*SS];
__device__ __half g_A2[(size_t)MM*K2];              // split activations (x), fp16 [hi|lo]
__device__ __half g_W2[(size_t)3*DD*K2];            // weights (q,k,v) fp16, duplicated [w|w]
__device__ __half g_AO[(size_t)MM*DD];              // attention output, fp16
__device__ __half g_wo_f16[(size_t)DD*DD];          // quantized wo, fp16
__device__ float g_ebias[EBN];

// ---------------- prep ----------------
__global__ void zero_absmax_kernel() {
    if (threadIdx.x < 8) g_absmax[threadIdx.x] = 0.0f;
}

__global__ void absmax_all_kernel(const float* __restrict__ wq, const float* __restrict__ wk,
                                  const float* __restrict__ wv, const float* __restrict__ wo,
                                  const float* __restrict__ wu, const float* __restrict__ wsv) {
    int slot = blockIdx.y;
    const float* w = (slot == 0) ? wq : (slot == 1) ? wk : (slot == 2) ? wv
                   : (slot == 3) ? wo : (slot == 4) ? wu : wsv;
    int n = (slot < 4) ? DD * DD : SS * SS;
    float m = 0.0f;
    for (int i = blockIdx.x * blockDim.x + threadIdx.x; i < n; i += gridDim.x * blockDim.x)
        m = fmaxf(m, fabsf(w[i]));
    #pragma unroll
    for (int o = 16; o > 0; o >>= 1) m = fmaxf(m, __shfl_xor_sync(0xffffffffu, m, o));
    __shared__ float sm[8];
    int lane = threadIdx.x & 31, wid = threadIdx.x >> 5;
    if (lane == 0) sm[wid] = m;
    __syncthreads();
    if (wid == 0) {
        int nw = blockDim.x >> 5;
        m = (lane < nw) ? sm[lane] : 0.0f;
        #pragma unroll
        for (int o = 4; o > 0; o >>= 1) m = fmaxf(m, __shfl_xor_sync(0xffffffffu, m, o));
        if (lane == 0) atomicMax((int*)&g_absmax[slot], __float_as_int(m));
    }
}

__global__ void build_ebias_kernel(const float* __restrict__ ps) {
    int i = blockIdx.x * 256 + threadIdx.x;
    if (i >= EBN) return;
    float v = 0.0f;
    if (i >= 128 && i < 128 + 2048) {
        int d = i - 128;
        float bias = (d == 0) ? 1.0f : (float)min(__ffs(d) - 1, 16) * 0.0625f;
        v = __expf(ps[0] * bias);
    }
    g_ebias[i] = v;
}

// ---------------- PTX helpers ----------------
__device__ __forceinline__ void cp16(void* dst, const void* src) {
    unsigned d = (unsigned)__cvta_generic_to_shared(dst);
    asm volatile("cp.async.cg.shared.global [%0], [%1], 16;\n" :: "r"(d), "l"(src));
}
#define LDM4(R, PTR) do { \
    unsigned _a = (unsigned)__cvta_generic_to_shared(PTR); \
    asm volatile("ldmatrix.sync.aligned.m8n8.x4.shared.b16 {%0,%1,%2,%3}, [%4];" \
        : "=r"((R)[0]), "=r"((R)[1]), "=r"((R)[2]), "=r"((R)[3]) : "r"(_a)); \
} while (0)
#define LDM4T(R, PTR) do { \
    unsigned _a = (unsigned)__cvta_generic_to_shared(PTR); \
    asm volatile("ldmatrix.sync.aligned.m8n8.x4.trans.shared.b16 {%0,%1,%2,%3}, [%4];" \
        : "=r"((R)[0]), "=r"((R)[1]), "=r"((R)[2]), "=r"((R)[3]) : "r"(_a)); \
} while (0)
#define MMAF16(C, A, B0, B1) \
    asm volatile("mma.sync.aligned.m16n8k16.row.col.f32.f16.f16.f32 " \
        "{%0,%1,%2,%3}, {%4,%5,%6,%7}, {%8,%9}, {%0,%1,%2,%3};" \
        : "+f"((C)[0]), "+f"((C)[1]), "+f"((C)[2]), "+f"((C)[3]) \
        : "r"((A)[0]), "r"((A)[1]), "r"((A)[2]), "r"((A)[3]), "r"(B0), "r"(B1))
#define SWZ(row, ch) ((ch) ^ (((row) >> 1) & 3))
#define SWZ8(row, ch) (((ch) ^ ((row) & 7)) << 3)

__device__ __forceinline__ uint32_t pack_f16x2(float lo, float hi) {
    uint32_t r;
    asm("cvt.rn.f16x2.f32 %0, %1, %2;" : "=r"(r) : "f"(hi), "f"(lo));
    return r;
}
__device__ __forceinline__ float exp2p(float y) {   // fast 2^y, fma/alu only
    y = fmaxf(y, -125.0f);
    float z = y + 12582912.0f;
    float f = y - (z - 12582912.0f);
    int e = __float_as_int(z) << 23;
    float r = 0.0013333558146f;
    r = fmaf(r, f, 0.0096181291076f);
    r = fmaf(r, f, 0.055504108664f);
    r = fmaf(r, f, 0.24022650696f);
    r = fmaf(r, f, 0.69314718056f);
    r = fmaf(r, f, 1.0f);
    return __int_as_float(__float_as_int(r) + e);
}
// fp16 hi/lo split (RN hi + fp16 residual); dh/dl may be strided apart
__device__ __forceinline__ void emit_hl_f16(__half* dh, __half* dl, float f0, float f1) {
    uint32_t h = pack_f16x2(f0, f1);
    __half2 hv = *(__half2*)&h;
    float r0 = f0 - __half2float(__low2half(hv));
    float r1 = f1 - __half2float(__high2half(hv));
    *(uint32_t*)dh = h;
    *(uint32_t*)dl = pack_f16x2(r0, r1);
}
// duplicate fp16 pair into [w|w] W2 row
__device__ __forceinline__ void storeW2(__half* p, float f0, float f1) {
    uint32_t h = pack_f16x2(f0, f1);
    *(uint32_t*)p = h;
    *(uint32_t*)(p + 1024) = h;
}
__device__ __forceinline__ float quant6(float w, float sc) {
    float q = rintf(w / sc);
    return fminf(fmaxf(q, -31.0f), 31.0f) * sc;
}

// ---------------- compose (stalk-fold) + quant + fp16 store, fused ----------------
__global__ __launch_bounds__(256) void compose_split_kernel(
        const float* __restrict__ wq, const float* __restrict__ wk,
        const float* __restrict__ wu, const float* __restrict__ wsv) {
    __shared__ float ws[64][64];
    __shared__ float wb[64][128];
    const int which = blockIdx.z, h = blockIdx.y, kc = blockIdx.x;
    const float* wsmall = which ? wsv : wu;
    const float* wbig   = which ? wk  : wq;
    const float scb = g_absmax[which ? 1 : 0] / 31.0f + 1e-8f;
    const float scs = g_absmax[which ? 5 : 4] / 31.0f + 1e-8f;
    const int tid = threadIdx.x;

    for (int idx = tid; idx < 4096; idx += 256)
        ws[idx >> 6][idx & 63] = quant6(wsmall[idx], scs);
    for (int idx = tid; idx < 8192; idx += 256) {
        int s = idx >> 7, k = idx & 127;
        wb[s][k] = quant6(wbig[(size_t)(h * 64 + s) * DD + kc * 128 + k], scb);
    }
    __syncthreads();

    const int tx = tid & 31, ty = tid >> 5;
    const int k0 = tx * 4, sp0 = ty * 8;
    float acc[8][4];
    #pragma unroll
    for (int i = 0; i < 8; i++)
        #pragma unroll
        for (int j = 0; j < 4; j++) acc[i][j] = 0.0f;
    #pragma unroll 8
    for (int s = 0; s < 64; s++) {
        float4 b = *(const float4*)&wb[s][k0];
        #pragma unroll
        for (int i = 0; i < 8; i++) {
            float a = ws[sp0 + i][s];
            acc[i][0] = fmaf(a, b.x, acc[i][0]);
            acc[i][1] = fmaf(a, b.y, acc[i][1]);
            acc[i][2] = fmaf(a, b.z, acc[i][2]);
            acc[i][3] = fmaf(a, b.w, acc[i][3]);
        }
    }
    __half* o = g_W2 + (size_t)which * DD * K2;
    #pragma unroll
    for (int i = 0; i < 8; i++) {
        __half* p = o + (size_t)(h * 64 + sp0 + i) * K2 + kc * 128 + k0;
        storeW2(p, acc[i][0], acc[i][1]);
        storeW2(p + 2, acc[i][2], acc[i][3]);
    }
}

// ---------------- wv -> W2 [w|w]; wo -> fp16 ----------------
__global__ void split_w_vo_kernel(const float* __restrict__ wv, const float* __restrict__ wo) {
    int is_o = blockIdx.y;
    const float* src = is_o ? wo : wv;
    float sc = g_absmax[2 + is_o] / 31.0f + 1e-8f;
    int i = blockIdx.x * 256 + threadIdx.x;
    int row = i >> 8;
    int k4 = (i & 255) * 4;
    float4 v = *(const float4*)(src + (size_t)row * DD + k4);
    v.x = quant6(v.x, sc); v.y = quant6(v.y, sc);
    v.z = quant6(v.z, sc); v.w = quant6(v.w, sc);
    if (is_o) {
        __half* o = g_wo_f16 + (size_t)row * DD + k4;
        *(uint32_t*)o = pack_f16x2(v.x, v.y);
        *(uint32_t*)(o + 2) = pack_f16x2(v.z, v.w);
    } else {
        __half* o = g_W2 + (size_t)2 * DD * K2 + (size_t)row * K2 + k4;
        storeW2(o, v.x, v.y);
        storeW2(o + 2, v.z, v.w);
    }
}

// ---------------- x -> A2 fp16 [hi|lo] ----------------
__global__ void split_act_kernel(const float* __restrict__ src) {
    int i = blockIdx.x * 256 + threadIdx.x;
    int row = i >> 8;
    int k4 = (i & 255) * 4;
    float4 v = *(const float4*)(src + (size_t)row * DD + k4);
    __half* o = g_A2 + (size_t)row * K2 + k4;
    emit_hl_f16(o, o + 1024, v.x, v.y);
    emit_hl_f16(o + 2, o + 1026, v.z, v.w);
}

// ---------------- fp16 tensor-core GEMM: QKV (z=0 -> V nc=64 heavy-first; Q,K nc=32) ----
__global__ __launch_bounds__(256, 2) void gemm_qkv_f16_kernel() {
    const int which = (blockIdx.z == 0) ? 2 : (blockIdx.z == 1) ? 0 : 1;
    const int nc = (which == 2) ? 64 : 32;
    __shared__ alignas(16) __half As[2][128 * 32];
    __shared__ alignas(16) __half Bs[2][128 * 32];

    const __half* __restrict__ Wg = g_W2 + (size_t)which * DD * K2;
    const int tid = threadIdx.x;
    const int lane = tid & 31, wid = tid >> 5;
    const int warp_m = wid >> 1, warp_n = wid & 1;
    const int m0 = blockIdx.y * 128;
    const int n0 = blockIdx.x * 128;

    const __half* Ag = g_A2 + (size_t)m0 * K2;
    const __half* Bg = Wg + (size_t)n0 * K2;

    float c[2][4][2][4];
    #pragma unroll
    for (int i = 0; i < 2; i++)
        #pragma unroll
        for (int g = 0; g < 4; g++)
            #pragma unroll
            for (int j = 0; j < 2; j++)
                #pragma unroll
                for (int q = 0; q < 4; q++) c[i][g][j][q] = 0.0f;

    int ld_row[2], ld_ch[2];
    #pragma unroll
    for (int p = 0; p < 2; p++) {
        int e = tid + p * 256;
        ld_row[p] = e >> 2;
        ld_ch[p] = e & 3;
    }

    #pragma unroll
    for (int p = 0; p < 2; p++) {
        int row = ld_row[p], ch = ld_ch[p];
        int so = row * 32 + SWZ(row, ch) * 8;
        cp16(&As[0][so], Ag + (size_t)row * K2 + ch * 8);
        cp16(&Bs[0][so], Bg + (size_t)row * K2 + ch * 8);
    }
    asm volatile("cp.async.commit_group;");

    for (int kc = 0; kc < nc; kc++) {
        if (kc + 1 < nc) {
            int s = (kc + 1) & 1;
            int koff = (kc + 1) * 32;
            #pragma unroll
            for (int p = 0; p < 2; p++) {
                int row = ld_row[p], ch = ld_ch[p];
                int so = row * 32 + SWZ(row, ch) * 8;
                cp16(&As[s][so], Ag + (size_t)row * K2 + koff + ch * 8);
                cp16(&Bs[s][so], Bg + (size_t)row * K2 + koff + ch * 8);
            }
            asm volatile("cp.async.commit_group;");
            asm volatile("cp.async.wait_group 1;");
        } else {
            asm volatile("cp.async.wait_group 0;");
        }
        __syncthreads();

        const __half* Asb = As[kc & 1];
        const __half* Bsb = Bs[kc & 1];

        #pragma unroll
        for (int kk = 0; kk < 2; kk++) {
            uint32_t af[2][4], bf[4][4];
            #pragma unroll
            for (int i = 0; i < 2; i++) {
                int row = warp_m * 32 + i * 16 + (lane & 15);
                int ch = kk * 2 + (lane >> 4);
                LDM4(af[i], Asb + row * 32 + SWZ(row, ch) * 8);
            }
            #pragma unroll
            for (int g = 0; g < 4; g++) {
                int row = warp_n * 64 + g * 16 + (lane & 7) + ((lane >> 4) << 3);
                int ch = kk * 2 + ((lane >> 3) & 1);
                LDM4(bf[g], Bsb + row * 32 + SWZ(row, ch) * 8);
            }
            #pragma unroll
            for (int i = 0; i < 2; i++)
                #pragma unroll
                for (int g = 0; g < 4; g++) {
                    MMAF16(c[i][g][0], af[i], bf[g][0], bf[g][1]);
                    MMAF16(c[i][g][1], af[i], bf[g][2], bf[g][3]);
                }
        }
        __syncthreads();
    }

    // epilogue
    #pragma unroll
    for (int i = 0; i < 2; i++)
        #pragma unroll
        for (int g = 0; g < 4; g++)
            #pragma unroll
            for (int j = 0; j < 2; j++) {
                int rr = m0 + warp_m * 32 + i * 16 + (lane >> 2);
                int cc = n0 + warp_n * 64 + g * 16 + j * 8 + ((lane & 3) << 1);
                int b = rr >> 11, t = rr & 2047;
                int hh = cc >> 6, s2 = cc & 63;
                size_t off = ((size_t)(b * HH + hh) * TT + t) * SS + s2;
                if (which < 2) {           // Q/K: fp16 RN
                    __half* dh = (which == 0) ? g_Qh : g_Kh;
                    *(uint32_t*)(dh + off) = pack_f16x2(c[i][g][j][0], c[i][g][j][1]);
                    *(uint32_t*)(dh + off + 8 * SS) = pack_f16x2(c[i][g][j][2], c[i][g][j][3]);
                } else {                   // V: fp16 hi + lo
                    emit_hl_f16(g_Vh + off, g_Vl + off, c[i][g][j][0], c[i][g][j][1]);
                    emit_hl_f16(g_Vh + off + 8 * SS, g_Vl + off + 8 * SS, c[i][g][j][2], c[i][g][j][3]);
                }
            }
}

// ---------------- fp16 O GEMM: out[M,D] = AO[M,D] @ wo_f16[D,D]^T ----------------
__global__ __launch_bounds__(256, 2) void gemm_o_f16_kernel(float* __restrict__ ext_out) {
    __shared__ alignas(16) __half As[2][128 * 32];
    __shared__ alignas(16) __half Bs[2][128 * 32];

    const int tid = threadIdx.x;
    const int lane = tid & 31, wid = tid >> 5;
    const int warp_m = wid >> 1, warp_n = wid & 1;
    const int m0 = blockIdx.y * 128;
    const int n0 = blockIdx.x * 128;

    const __half* Ag = g_AO + (size_t)m0 * DD;
    const __half* Bg = g_wo_f16 + (size_t)n0 * DD;

    float c[2][4][2][4];
    #pragma unroll
    for (int i = 0; i < 2; i++)
        #pragma unroll
        for (int g = 0; g < 4; g++)
            #pragma unroll
            for (int j = 0; j < 2; j++)
                #pragma unroll
                for (int q = 0; q < 4; q++) c[i][g][j][q] = 0.0f;

    int ld_row[2], ld_ch[2];
    #pragma unroll
    for (int p = 0; p < 2; p++) {
        int e = tid + p * 256;
        ld_row[p] = e >> 2;
        ld_ch[p] = e & 3;
    }
    const int nc = DD / 32;   // 32

    #pragma unroll
    for (int p = 0; p < 2; p++) {
        int row = ld_row[p], ch = ld_ch[p];
        int so = row * 32 + SWZ(row, ch) * 8;
        cp16(&As[0][so], Ag + (size_t)row * DD + ch * 8);
        cp16(&Bs[0][so], Bg + (size_t)row * DD + ch * 8);
    }
    asm volatile("cp.async.commit_group;");

    for (int kc = 0; kc < nc; kc++) {
        if (kc + 1 < nc) {
            int s = (kc + 1) & 1;
            int koff = (kc + 1) * 32;
            #pragma unroll
            for (int p = 0; p < 2; p++) {
                int row = ld_row[p], ch = ld_ch[p];
                int so = row * 32 + SWZ(row, ch) * 8;
                cp16(&As[s][so], Ag + (size_t)row * DD + koff + ch * 8);
                cp16(&Bs[s][so], Bg + (size_t)row * DD + koff + ch * 8);
            }
            asm volatile("cp.async.commit_group;");
            asm volatile("cp.async.wait_group 1;");
        } else {
            asm volatile("cp.async.wait_group 0;");
        }
        __syncthreads();

        const __half* Asb = As[kc & 1];
        const __half* Bsb = Bs[kc & 1];

        #pragma unroll
        for (int kk = 0; kk < 2; kk++) {
            uint32_t af[2][4], bf[4][4];
            #pragma unroll
            for (int i = 0; i < 2; i++) {
                int row = warp_m * 32 + i * 16 + (lane & 15);
                int ch = kk * 2 + (lane >> 4);
                LDM4(af[i], Asb + row * 32 + SWZ(row, ch) * 8);
            }
            #pragma unroll
            for (int g = 0; g < 4; g++) {
                int row = warp_n * 64 + g * 16 + (lane & 7) + ((lane >> 4) << 3);
                int ch = kk * 2 + ((lane >> 3) & 1);
                LDM4(bf[g], Bsb + row * 32 + SWZ(row, ch) * 8);
            }
            #pragma unroll
            for (int i = 0; i < 2; i++)
                #pragma unroll
                for (int g = 0; g < 4; g++) {
                    MMAF16(c[i][g][0], af[i], bf[g][0], bf[g][1]);
                    MMAF16(c[i][g][1], af[i], bf[g][2], bf[g][3]);
                }
        }
        __syncthreads();
    }

    #pragma unroll
    for (int i = 0; i < 2; i++)
        #pragma unroll
        for (int g = 0; g < 4; g++)
            #pragma unroll
            for (int j = 0; j < 2; j++) {
                int rr = m0 + warp_m * 32 + i * 16 + (lane >> 2);
                int cc = n0 + warp_n * 64 + g * 16 + j * 8 + ((lane & 3) << 1);
                *(float2*)(ext_out + (size_t)rr * DD + cc) =
                    make_float2(c[i][g][j][0], c[i][g][j][1]);
                *(float2*)(ext_out + (size_t)(rr + 8) * DD + cc) =
                    make_float2(c[i][g][j][2], c[i][g][j][3]);
            }
}

// ---------------- tensor-core flash attention (128-row q tiles, all fp16) ----------------
// grid (64 bh fast, 16 qt slow DESCENDING): heavy q-tiles launch first.
#define CLOG2E 0.18033688011112042f   // 0.125 * log2(e)

__global__ __launch_bounds__(256, 2) void attn_tc_kernel() {
    extern __shared__ __half smraw[];   // [2 stages][3 arrays: Kh,Vh,Vl][64*64]
    const int tid = threadIdx.x, lane = tid & 31, warp = tid >> 5;
    const int qt = (int)gridDim.y - 1 - (int)blockIdx.y;   // descending work order
    const int bh = blockIdx.x;
    const size_t bhbase = (size_t)bh * TT * SS;

    // ---- stage Q (128x64 = 1024 x 16B) into arrays 0,1 ----
    {
        const __half* src = g_Qh + bhbase + (size_t)qt * 128 * 64;
        #pragma unroll
        for (int i = 0; i < 4; i++) {
            int idx = tid + 256 * i;                  // 0..1023
            int r = idx >> 3, ch = idx & 7;           // r in [0,128)
            int a = r >> 6, rl = r & 63;
            cp16(smraw + a * 4096 + rl * 64 + SWZ8(rl, ch), src + r * 64 + ch * 8);
        }
    }
    asm volatile("cp.async.commit_group;");
    asm volatile("cp.async.wait_group 0;");
    __syncthreads();

    uint32_t qh[4][4];
    {
        int r = warp * 16 + (lane & 15);
        int a = r >> 6, rl = r & 63;
        #pragma unroll
        for (int kk = 0; kk < 4; kk++) {
            int ch = kk * 2 + (lane >> 4);
            LDM4(qh[kk], smraw + a * 4096 + rl * 64 + SWZ8(rl, ch));
        }
    }
    __syncthreads();

    float oc[8][4];
    #pragma unroll
    for (int j = 0; j < 8; j++)
        #pragma unroll
        for (int q = 0; q < 4; q++) oc[j][q] = 0.0f;
    float m0 = -1e30f, m1 = -1e30f, l0 = 0.0f, l1 = 0.0f;

    const int rg = lane >> 2;
    const int cb = (lane & 3) << 1;
    const int brow = (lane & 7) + ((lane >> 4) << 3);
    const int bchx = (lane >> 3) & 1;
    const int vrow16 = ((lane >> 3) & 1) * 8 + (lane & 7);
    const int vchh = lane >> 4;
    const int ktmax = 2 * qt + 1;

    const __half* kvsrc[3] = {g_Kh + bhbase, g_Vh + bhbase, g_Vl + bhbase};

    #define LOAD_KV(KT, ST) do { \
        _Pragma("unroll") \
        for (int _i = 0; _i < 6; _i++) { \
            int _g = tid + 256 * _i;           /* 0..1535 */ \
            int _arr = _g >> 9, _idx = _g & 511; \
            int _r = _idx >> 3, _ch = _idx & 7; \
            cp16(smraw + ((ST) * 3 + _arr) * 4096 + _r * 64 + SWZ8(_r, _ch), \
                 kvsrc[_arr] + (size_t)(KT) * 4096 + _r * 64 + _ch * 8); \
        } \
        asm volatile("cp.async.commit_group;"); \
    } while (0)

    LOAD_KV(0, 0);

    for (int kt = 0; kt <= ktmax; kt++) {
        const int st = kt & 1;
        if (kt < ktmax) {
            LOAD_KV(kt + 1, st ^ 1);
            asm volatile("cp.async.wait_group 1;");
        } else {
            asm volatile("cp.async.wait_group 0;");
        }
        __syncthreads();

        if (qt * 128 + warp * 16 + 15 >= kt * 64) {
            const __half* Kh_ = smraw + (st * 3 + 0) * 4096;
            const __half* Vh_ = smraw + (st * 3 + 1) * 4096;
            const __half* Vl_ = smraw + (st * 3 + 2) * 4096;

            // ---- S = Q K^T (fp16) ----
            float sc[8][4];
            #pragma unroll
            for (int j = 0; j < 8; j++)
                #pragma unroll
                for (int q = 0; q < 4; q++) sc[j][q] = 0.0f;
            #pragma unroll
            for (int g = 0; g < 4; g++) {
                int row = g * 16 + brow;
                #pragma unroll
                for (int kk = 0; kk < 4; kk++) {
                    int ch = kk * 2 + bchx;
                    uint32_t bh4[4];
                    LDM4(bh4, &Kh_[row * 64 + SWZ8(row, ch)]);
                    MMAF16(sc[2*g],   qh[kk], bh4[0], bh4[1]);
                    MMAF16(sc[2*g+1], qh[kk], bh4[2], bh4[3]);
                }
            }

            // ---- softmax ----
            float mx0 = -1e30f, mx1 = -1e30f;
            #pragma unroll
            for (int j = 0; j < 8; j++) {
                mx0 = fmaxf(mx0, fmaxf(sc[j][0], sc[j][1]));
                mx1 = fmaxf(mx1, fmaxf(sc[j][2], sc[j][3]));
            }
            mx0 = fmaxf(mx0, __shfl_xor_sync(0xffffffffu, mx0, 1));
            mx0 = fmaxf(mx0, __shfl_xor_sync(0xffffffffu, mx0, 2));
            mx1 = fmaxf(mx1, __shfl_xor_sync(0xffffffffu, mx1, 1));
            mx1 = fmaxf(mx1, __shfl_xor_sync(0xffffffffu, mx1, 2));
            float mn0 = fmaxf(m0, mx0 * CLOG2E);
            float mn1 = fmaxf(m1, mx1 * CLOG2E);
            float a0 = exp2p(m0 - mn0), a1 = exp2p(m1 - mn1);
            m0 = mn0; m1 = mn1;

            int base0 = qt * 128 + warp * 16 + rg - kt * 64 + 128;
            int base1 = base0 + 8;
            float ls0 = 0.0f, ls1 = 0.0f;
            #pragma unroll
            for (int j = 0; j < 8; j++) {
                int c0 = j * 8 + cb;
                float e0 = exp2p(fmaf(sc[j][0], CLOG2E, -mn0)) * __ldg(&g_ebias[base0 - c0]);
                float e1 = exp2p(fmaf(sc[j][1], CLOG2E, -mn0)) * __ldg(&g_ebias[base0 - c0 - 1]);
                float e2 = exp2p(fmaf(sc[j][2], CLOG2E, -mn1)) * __ldg(&g_ebias[base1 - c0]);
                float e3 = exp2p(fmaf(sc[j][3], CLOG2E, -mn1)) * __ldg(&g_ebias[base1 - c0 - 1]);
                sc[j][0] = e0; sc[j][1] = e1; sc[j][2] = e2; sc[j][3] = e3;
                ls0 += e0 + e1; ls1 += e2 + e3;
            }
            ls0 += __shfl_xor_sync(0xffffffffu, ls0, 1);
            ls0 += __shfl_xor_sync(0xffffffffu, ls0, 2);
            ls1 += __shfl_xor_sync(0xffffffffu, ls1, 1);
            ls1 += __shfl_xor_sync(0xffffffffu, ls1, 2);
            l0 = l0 * a0 + ls0;
            l1 = l1 * a1 + ls1;
            #pragma unroll
            for (int j = 0; j < 8; j++) {
                oc[j][0] *= a0; oc[j][1] *= a0; oc[j][2] *= a1; oc[j][3] *= a1;
            }

            // ---- repack P (C-frag -> A-frag, RN fp16) ----
            uint32_t pah[4][4];
            #pragma unroll
            for (int kk = 0; kk < 4; kk++) {
                #pragma unroll
                for (int half = 0; half < 2; half++) {
                    int j = 2 * kk + half;
                    pah[kk][half * 2]     = pack_f16x2(sc[j][0], sc[j][1]);
                    pah[kk][half * 2 + 1] = pack_f16x2(sc[j][2], sc[j][3]);
                }
            }

            // ---- O += P V (2-term fp16; V row-major via ldmatrix.trans) ----
            #pragma unroll
            for (int g = 0; g < 4; g++) {
                int ch = 2 * g + vchh;
                #pragma unroll
                for (int kk = 0; kk < 4; kk++) {
                    int row = kk * 16 + vrow16;
                    uint32_t vh4[4], vl4[4];
                    LDM4T(vh4, &Vh_[row * 64 + SWZ8(row, ch)]);
                    MMAF16(oc[2*g],   pah[kk], vh4[0], vh4[1]);
                    MMAF16(oc[2*g+1], pah[kk], vh4[2], vh4[3]);
                    LDM4T(vl4, &Vl_[row * 64 + SWZ8(row, ch)]);
                    MMAF16(oc[2*g],   pah[kk], vl4[0], vl4[1]);
                    MMAF16(oc[2*g+1], pah[kk], vl4[2], vl4[3]);
                }
            }
        }
        __syncthreads();
    }

    // ---- epilogue: write fp16 attention output, row-major [B*T, D] ----
    float inv0 = 1.0f / l0, inv1 = 1.0f / l1;
    int b = bh >> 4, hh = bh & 15;
    int t0 = qt * 128 + warp * 16 + rg;
    __half* rowp = g_AO + (size_t)(b * TT + t0) * DD + hh * 64 + cb;
    #pragma unroll
    for (int j = 0; j < 8; j++) {
        *(uint32_t*)(rowp + j * 8) = pack_f16x2(oc[j][0] * inv0, oc[j][1] * inv0);
        *(uint32_t*)(rowp + (size_t)8 * DD + j * 8) = pack_f16x2(oc[j][2] * inv1, oc[j][3] * inv1);
    }
}

// ---------------- launch ----------------
extern "C" void kernel_launch(void* const* d_in, const int* in_sizes, int n_in,
                              void* d_out, int out_size) {
    const float* x   = (const float*)d_in[0];
    const float* wq  = (const float*)d_in[1];
    const float* wk  = (const float*)d_in[2];
    const float* wv  = (const float*)d_in[3];
    const float* wo  = (const float*)d_in[4];
    const float* wu  = (const float*)d_in[5];
    const float* wsv = (const float*)d_in[6];
    const float* ps  = (const float*)d_in[7];
    float* out = (float*)d_out;

    static int smem_set = 0;
    if (!smem_set) {
        cudaFuncSetAttribute(attn_tc_kernel, cudaFuncAttributeMaxDynamicSharedMemorySize, 49152);
        smem_set = 1;
    }

    zero_absmax_kernel<<<1, 32>>>();
    absmax_all_kernel<<<dim3(64, 6), 256>>>(wq, wk, wv, wo, wu, wsv);
    build_ebias_kernel<<<9, 256>>>(ps);
    compose_split_kernel<<<dim3(8, 16, 2), 256>>>(wq, wk, wu, wsv);
    split_w_vo_kernel<<<dim3(DD*DD/1024, 2), 256>>>(wv, wo);
    split_act_kernel<<<MM*DD/1024, 256>>>(x);
    gemm_qkv_f16_kernel<<<dim3(DD/128, MM/128, 3), 256>>>();          // QKV fp16, V heavy-first
    attn_tc_kernel<<<dim3(BB*HH, TT/128), 256, 49152>>>();            // qt slow, descending
    gemm_o_f16_kernel<<<dim3(DD/128, MM/128), 256>>>(out);            // O: fp16 1-term
}

// round 15
// speedup vs baseline: 6.2027x; 1.0927x over previous
#include <cuda_runtime.h>
#include <cuda_bf16.h>
#include <cuda_fp16.h>
#include <cstdint>

#define BB 4
#define TT 2048
#define DD 1024
#define HH 16
#define SS 64
#define MM (BB*TT)
#define K2 2048          // [hi | lo] fp16 segments of K=1024
#define EBN 2208         // ebias table size (index = d + 128)

// ---------------- device scratch (static, allocation-free) ----------------
__device__ float g_absmax[8];
__device__ __half g_Qh[(size_t)BB*HH*TT*SS];
__device__ __half g_Kh[(size_t)BB*HH*TT*SS];
__device__ __half g_Vh[(size_t)BB*HH*TT*SS];
__device__ __half g_A2[(size_t)MM*K2];              // split activations (x), fp16 [hi|lo]
__device__ __half g_W2[(size_t)3*DD*K2];            // weights (q,k,v) fp16, duplicated [w|w]
__device__ __half g_AO[(size_t)MM*DD];              // attention output, fp16
__device__ __half g_wo_f16[(size_t)DD*DD];          // quantized wo, fp16
__device__ float g_ebias[EBN];

// ---------------- prep ----------------
__global__ void zero_absmax_kernel() {
    if (threadIdx.x < 8) g_absmax[threadIdx.x] = 0.0f;
}

__global__ void absmax_all_kernel(const float* __restrict__ wq, const float* __restrict__ wk,
                                  const float* __restrict__ wv, const float* __restrict__ wo,
                                  const float* __restrict__ wu, const float* __restrict__ wsv) {
    int slot = blockIdx.y;
    const float* w = (slot == 0) ? wq : (slot == 1) ? wk : (slot == 2) ? wv
                   : (slot == 3) ? wo : (slot == 4) ? wu : wsv;
    int n = (slot < 4) ? DD * DD : SS * SS;
    float m = 0.0f;
    for (int i = blockIdx.x * blockDim.x + threadIdx.x; i < n; i += gridDim.x * blockDim.x)
        m = fmaxf(m, fabsf(w[i]));
    #pragma unroll
    for (int o = 16; o > 0; o >>= 1) m = fmaxf(m, __shfl_xor_sync(0xffffffffu, m, o));
    __shared__ float sm[8];
    int lane = threadIdx.x & 31, wid = threadIdx.x >> 5;
    if (lane == 0) sm[wid] = m;
    __syncthreads();
    if (wid == 0) {
        int nw = blockDim.x >> 5;
        m = (lane < nw) ? sm[lane] : 0.0f;
        #pragma unroll
        for (int o = 4; o > 0; o >>= 1) m = fmaxf(m, __shfl_xor_sync(0xffffffffu, m, o));
        if (lane == 0) atomicMax((int*)&g_absmax[slot], __float_as_int(m));
    }
}

__global__ void build_ebias_kernel(const float* __restrict__ ps) {
    int i = blockIdx.x * 256 + threadIdx.x;
    if (i >= EBN) return;
    float v = 0.0f;
    if (i >= 128 && i < 128 + 2048) {
        int d = i - 128;
        float bias = (d == 0) ? 1.0f : (float)min(__ffs(d) - 1, 16) * 0.0625f;
        v = __expf(ps[0] * bias);
    }
    g_ebias[i] = v;
}

// ---------------- PTX helpers ----------------
__device__ __forceinline__ void cp16(void* dst, const void* src) {
    unsigned d = (unsigned)__cvta_generic_to_shared(dst);
    asm volatile("cp.async.cg.shared.global [%0], [%1], 16;\n" :: "r"(d), "l"(src));
}
#define LDM4(R, PTR) do { \
    unsigned _a = (unsigned)__cvta_generic_to_shared(PTR); \
    asm volatile("ldmatrix.sync.aligned.m8n8.x4.shared.b16 {%0,%1,%2,%3}, [%4];" \
        : "=r"((R)[0]), "=r"((R)[1]), "=r"((R)[2]), "=r"((R)[3]) : "r"(_a)); \
} while (0)
#define LDM4T(R, PTR) do { \
    unsigned _a = (unsigned)__cvta_generic_to_shared(PTR); \
    asm volatile("ldmatrix.sync.aligned.m8n8.x4.trans.shared.b16 {%0,%1,%2,%3}, [%4];" \
        : "=r"((R)[0]), "=r"((R)[1]), "=r"((R)[2]), "=r"((R)[3]) : "r"(_a)); \
} while (0)
#define MMAF16(C, A, B0, B1) \
    asm volatile("mma.sync.aligned.m16n8k16.row.col.f32.f16.f16.f32 " \
        "{%0,%1,%2,%3}, {%4,%5,%6,%7}, {%8,%9}, {%0,%1,%2,%3};" \
        : "+f"((C)[0]), "+f"((C)[1]), "+f"((C)[2]), "+f"((C)[3]) \
        : "r"((A)[0]), "r"((A)[1]), "r"((A)[2]), "r"((A)[3]), "r"(B0), "r"(B1))
#define SWZ(row, ch) ((ch) ^ (((row) >> 1) & 3))
#define SWZ8(row, ch) (((ch) ^ ((row) & 7)) << 3)

__device__ __forceinline__ uint32_t pack_f16x2(float lo, float hi) {
    uint32_t r;
    asm("cvt.rn.f16x2.f32 %0, %1, %2;" : "=r"(r) : "f"(hi), "f"(lo));
    return r;
}
__device__ __forceinline__ float exp2p(float y) {   // fast 2^y, fma/alu only
    y = fmaxf(y, -125.0f);
    float z = y + 12582912.0f;
    float f = y - (z - 12582912.0f);
    int e = __float_as_int(z) << 23;
    float r = 0.0013333558146f;
    r = fmaf(r, f, 0.0096181291076f);
    r = fmaf(r, f, 0.055504108664f);
    r = fmaf(r, f, 0.24022650696f);
    r = fmaf(r, f, 0.69314718056f);
    r = fmaf(r, f, 1.0f);
    return __int_as_float(__float_as_int(r) + e);
}
// fp16 hi/lo split (RN hi + fp16 residual); dh/dl may be strided apart
__device__ __forceinline__ void emit_hl_f16(__half* dh, __half* dl, float f0, float f1) {
    uint32_t h = pack_f16x2(f0, f1);
    __half2 hv = *(__half2*)&h;
    float r0 = f0 - __half2float(__low2half(hv));
    float r1 = f1 - __half2float(__high2half(hv));
    *(uint32_t*)dh = h;
    *(uint32_t*)dl = pack_f16x2(r0, r1);
}
// duplicate fp16 pair into [w|w] W2 row
__device__ __forceinline__ void storeW2(__half* p, float f0, float f1) {
    uint32_t h = pack_f16x2(f0, f1);
    *(uint32_t*)p = h;
    *(uint32_t*)(p + 1024) = h;
}
__device__ __forceinline__ float quant6(float w, float sc) {
    float q = rintf(w / sc);
    return fminf(fmaxf(q, -31.0f), 31.0f) * sc;
}

// ---------------- compose (stalk-fold) + quant + fp16 store, fused ----------------
__global__ __launch_bounds__(256) void compose_split_kernel(
        const float* __restrict__ wq, const float* __restrict__ wk,
        const float* __restrict__ wu, const float* __restrict__ wsv) {
    __shared__ float ws[64][64];
    __shared__ float wb[64][128];
    const int which = blockIdx.z, h = blockIdx.y, kc = blockIdx.x;
    const float* wsmall = which ? wsv : wu;
    const float* wbig   = which ? wk  : wq;
    const float scb = g_absmax[which ? 1 : 0] / 31.0f + 1e-8f;
    const float scs = g_absmax[which ? 5 : 4] / 31.0f + 1e-8f;
    const int tid = threadIdx.x;

    for (int idx = tid; idx < 4096; idx += 256)
        ws[idx >> 6][idx & 63] = quant6(wsmall[idx], scs);
    for (int idx = tid; idx < 8192; idx += 256) {
        int s = idx >> 7, k = idx & 127;
        wb[s][k] = quant6(wbig[(size_t)(h * 64 + s) * DD + kc * 128 + k], scb);
    }
    __syncthreads();

    const int tx = tid & 31, ty = tid >> 5;
    const int k0 = tx * 4, sp0 = ty * 8;
    float acc[8][4];
    #pragma unroll
    for (int i = 0; i < 8; i++)
        #pragma unroll
        for (int j = 0; j < 4; j++) acc[i][j] = 0.0f;
    #pragma unroll 8
    for (int s = 0; s < 64; s++) {
        float4 b = *(const float4*)&wb[s][k0];
        #pragma unroll
        for (int i = 0; i < 8; i++) {
            float a = ws[sp0 + i][s];
            acc[i][0] = fmaf(a, b.x, acc[i][0]);
            acc[i][1] = fmaf(a, b.y, acc[i][1]);
            acc[i][2] = fmaf(a, b.z, acc[i][2]);
            acc[i][3] = fmaf(a, b.w, acc[i][3]);
        }
    }
    __half* o = g_W2 + (size_t)which * DD * K2;
    #pragma unroll
    for (int i = 0; i < 8; i++) {
        __half* p = o + (size_t)(h * 64 + sp0 + i) * K2 + kc * 128 + k0;
        storeW2(p, acc[i][0], acc[i][1]);
        storeW2(p + 2, acc[i][2], acc[i][3]);
    }
}

// ---------------- wv -> W2 [w|w]; wo -> fp16 ----------------
__global__ void split_w_vo_kernel(const float* __restrict__ wv, const float* __restrict__ wo) {
    int is_o = blockIdx.y;
    const float* src = is_o ? wo : wv;
    float sc = g_absmax[2 + is_o] / 31.0f + 1e-8f;
    int i = blockIdx.x * 256 + threadIdx.x;
    int row = i >> 8;
    int k4 = (i & 255) * 4;
    float4 v = *(const float4*)(src + (size_t)row * DD + k4);
    v.x = quant6(v.x, sc); v.y = quant6(v.y, sc);
    v.z = quant6(v.z, sc); v.w = quant6(v.w, sc);
    if (is_o) {
        __half* o = g_wo_f16 + (size_t)row * DD + k4;
        *(uint32_t*)o = pack_f16x2(v.x, v.y);
        *(uint32_t*)(o + 2) = pack_f16x2(v.z, v.w);
    } else {
        __half* o = g_W2 + (size_t)2 * DD * K2 + (size_t)row * K2 + k4;
        storeW2(o, v.x, v.y);
        storeW2(o + 2, v.z, v.w);
    }
}

// ---------------- x -> A2 fp16 [hi|lo] ----------------
__global__ void split_act_kernel(const float* __restrict__ src) {
    int i = blockIdx.x * 256 + threadIdx.x;
    int row = i >> 8;
    int k4 = (i & 255) * 4;
    float4 v = *(const float4*)(src + (size_t)row * DD + k4);
    __half* o = g_A2 + (size_t)row * K2 + k4;
    emit_hl_f16(o, o + 1024, v.x, v.y);
    emit_hl_f16(o + 2, o + 1026, v.z, v.w);
}

// ---------------- fp16 tensor-core GEMM: QKV (z=0 -> V nc=64 heavy-first; Q,K nc=32) ----
__global__ __launch_bounds__(256, 2) void gemm_qkv_f16_kernel() {
    const int which = (blockIdx.z == 0) ? 2 : (blockIdx.z == 1) ? 0 : 1;
    const int nc = (which == 2) ? 64 : 32;
    __shared__ alignas(16) __half As[2][128 * 32];
    __shared__ alignas(16) __half Bs[2][128 * 32];

    const __half* __restrict__ Wg = g_W2 + (size_t)which * DD * K2;
    const int tid = threadIdx.x;
    const int lane = tid & 31, wid = tid >> 5;
    const int warp_m = wid >> 1, warp_n = wid & 1;
    const int m0 = blockIdx.y * 128;
    const int n0 = blockIdx.x * 128;

    const __half* Ag = g_A2 + (size_t)m0 * K2;
    const __half* Bg = Wg + (size_t)n0 * K2;

    float c[2][4][2][4];
    #pragma unroll
    for (int i = 0; i < 2; i++)
        #pragma unroll
        for (int g = 0; g < 4; g++)
            #pragma unroll
            for (int j = 0; j < 2; j++)
                #pragma unroll
                for (int q = 0; q < 4; q++) c[i][g][j][q] = 0.0f;

    int ld_row[2], ld_ch[2];
    #pragma unroll
    for (int p = 0; p < 2; p++) {
        int e = tid + p * 256;
        ld_row[p] = e >> 2;
        ld_ch[p] = e & 3;
    }

    #pragma unroll
    for (int p = 0; p < 2; p++) {
        int row = ld_row[p], ch = ld_ch[p];
        int so = row * 32 + SWZ(row, ch) * 8;
        cp16(&As[0][so], Ag + (size_t)row * K2 + ch * 8);
        cp16(&Bs[0][so], Bg + (size_t)row * K2 + ch * 8);
    }
    asm volatile("cp.async.commit_group;");

    for (int kc = 0; kc < nc; kc++) {
        if (kc + 1 < nc) {
            int s = (kc + 1) & 1;
            int koff = (kc + 1) * 32;
            #pragma unroll
            for (int p = 0; p < 2; p++) {
                int row = ld_row[p], ch = ld_ch[p];
                int so = row * 32 + SWZ(row, ch) * 8;
                cp16(&As[s][so], Ag + (size_t)row * K2 + koff + ch * 8);
                cp16(&Bs[s][so], Bg + (size_t)row * K2 + koff + ch * 8);
            }
            asm volatile("cp.async.commit_group;");
            asm volatile("cp.async.wait_group 1;");
        } else {
            asm volatile("cp.async.wait_group 0;");
        }
        __syncthreads();

        const __half* Asb = As[kc & 1];
        const __half* Bsb = Bs[kc & 1];

        #pragma unroll
        for (int kk = 0; kk < 2; kk++) {
            uint32_t af[2][4], bf[4][4];
            #pragma unroll
            for (int i = 0; i < 2; i++) {
                int row = warp_m * 32 + i * 16 + (lane & 15);
                int ch = kk * 2 + (lane >> 4);
                LDM4(af[i], Asb + row * 32 + SWZ(row, ch) * 8);
            }
            #pragma unroll
            for (int g = 0; g < 4; g++) {
                int row = warp_n * 64 + g * 16 + (lane & 7) + ((lane >> 4) << 3);
                int ch = kk * 2 + ((lane >> 3) & 1);
                LDM4(bf[g], Bsb + row * 32 + SWZ(row, ch) * 8);
            }
            #pragma unroll
            for (int i = 0; i < 2; i++)
                #pragma unroll
                for (int g = 0; g < 4; g++) {
                    MMAF16(c[i][g][0], af[i], bf[g][0], bf[g][1]);
                    MMAF16(c[i][g][1], af[i], bf[g][2], bf[g][3]);
                }
        }
        __syncthreads();
    }

    // epilogue: all outputs fp16 RN
    #pragma unroll
    for (int i = 0; i < 2; i++)
        #pragma unroll
        for (int g = 0; g < 4; g++)
            #pragma unroll
            for (int j = 0; j < 2; j++) {
                int rr = m0 + warp_m * 32 + i * 16 + (lane >> 2);
                int cc = n0 + warp_n * 64 + g * 16 + j * 8 + ((lane & 3) << 1);
                int b = rr >> 11, t = rr & 2047;
                int hh = cc >> 6, s2 = cc & 63;
                size_t off = ((size_t)(b * HH + hh) * TT + t) * SS + s2;
                __half* dh = (which == 0) ? g_Qh : (which == 1) ? g_Kh : g_Vh;
                *(uint32_t*)(dh + off) = pack_f16x2(c[i][g][j][0], c[i][g][j][1]);
                *(uint32_t*)(dh + off + 8 * SS) = pack_f16x2(c[i][g][j][2], c[i][g][j][3]);
            }
}

// ---------------- fp16 O GEMM: out[M,D] = AO[M,D] @ wo_f16[D,D]^T ----------------
__global__ __launch_bounds__(256, 2) void gemm_o_f16_kernel(float* __restrict__ ext_out) {
    __shared__ alignas(16) __half As[2][128 * 32];
    __shared__ alignas(16) __half Bs[2][128 * 32];

    const int tid = threadIdx.x;
    const int lane = tid & 31, wid = tid >> 5;
    const int warp_m = wid >> 1, warp_n = wid & 1;
    const int m0 = blockIdx.y * 128;
    const int n0 = blockIdx.x * 128;

    const __half* Ag = g_AO + (size_t)m0 * DD;
    const __half* Bg = g_wo_f16 + (size_t)n0 * DD;

    float c[2][4][2][4];
    #pragma unroll
    for (int i = 0; i < 2; i++)
        #pragma unroll
        for (int g = 0; g < 4; g++)
            #pragma unroll
            for (int j = 0; j < 2; j++)
                #pragma unroll
                for (int q = 0; q < 4; q++) c[i][g][j][q] = 0.0f;

    int ld_row[2], ld_ch[2];
    #pragma unroll
    for (int p = 0; p < 2; p++) {
        int e = tid + p * 256;
        ld_row[p] = e >> 2;
        ld_ch[p] = e & 3;
    }
    const int nc = DD / 32;   // 32

    #pragma unroll
    for (int p = 0; p < 2; p++) {
        int row = ld_row[p], ch = ld_ch[p];
        int so = row * 32 + SWZ(row, ch) * 8;
        cp16(&As[0][so], Ag + (size_t)row * DD + ch * 8);
        cp16(&Bs[0][so], Bg + (size_t)row * DD + ch * 8);
    }
    asm volatile("cp.async.commit_group;");

    for (int kc = 0; kc < nc; kc++) {
        if (kc + 1 < nc) {
            int s = (kc + 1) & 1;
            int koff = (kc + 1) * 32;
            #pragma unroll
            for (int p = 0; p < 2; p++) {
                int row = ld_row[p], ch = ld_ch[p];
                int so = row * 32 + SWZ(row, ch) * 8;
                cp16(&As[s][so], Ag + (size_t)row * DD + koff + ch * 8);
                cp16(&Bs[s][so], Bg + (size_t)row * DD + koff + ch * 8);
            }
            asm volatile("cp.async.commit_group;");
            asm volatile("cp.async.wait_group 1;");
        } else {
            asm volatile("cp.async.wait_group 0;");
        }
        __syncthreads();

        const __half* Asb = As[kc & 1];
        const __half* Bsb = Bs[kc & 1];

        #pragma unroll
        for (int kk = 0; kk < 2; kk++) {
            uint32_t af[2][4], bf[4][4];
            #pragma unroll
            for (int i = 0; i < 2; i++) {
                int row = warp_m * 32 + i * 16 + (lane & 15);
                int ch = kk * 2 + (lane >> 4);
                LDM4(af[i], Asb + row * 32 + SWZ(row, ch) * 8);
            }
            #pragma unroll
            for (int g = 0; g < 4; g++) {
                int row = warp_n * 64 + g * 16 + (lane & 7) + ((lane >> 4) << 3);
                int ch = kk * 2 + ((lane >> 3) & 1);
                LDM4(bf[g], Bsb + row * 32 + SWZ(row, ch) * 8);
            }
            #pragma unroll
            for (int i = 0; i < 2; i++)
                #pragma unroll
                for (int g = 0; g < 4; g++) {
                    MMAF16(c[i][g][0], af[i], bf[g][0], bf[g][1]);
                    MMAF16(c[i][g][1], af[i], bf[g][2], bf[g][3]);
                }
        }
        __syncthreads();
    }

    #pragma unroll
    for (int i = 0; i < 2; i++)
        #pragma unroll
        for (int g = 0; g < 4; g++)
            #pragma unroll
            for (int j = 0; j < 2; j++) {
                int rr = m0 + warp_m * 32 + i * 16 + (lane >> 2);
                int cc = n0 + warp_n * 64 + g * 16 + j * 8 + ((lane & 3) << 1);
                *(float2*)(ext_out + (size_t)rr * DD + cc) =
                    make_float2(c[i][g][j][0], c[i][g][j][1]);
                *(float2*)(ext_out + (size_t)(rr + 8) * DD + cc) =
                    make_float2(c[i][g][j][2], c[i][g][j][3]);
            }
}

// ---------------- tensor-core flash attention (128-row q tiles, fp16, no running max) ----
// Scores are bounded (|exp2 arg| << 1), so softmax needs no max subtraction:
// e = exp2(s*C)*ebias directly; O and l accumulate without rescaling. Exact math.
// grid (64 bh fast, 16 qt slow DESCENDING): heavy q-tiles launch first.
#define CLOG2E 0.18033688011112042f   // 0.125 * log2(e)

__global__ __launch_bounds__(256, 2) void attn_tc_kernel() {
    extern __shared__ __half smraw[];   // [2 stages][2 arrays: Kh,Vh][64*64]
    const int tid = threadIdx.x, lane = tid & 31, warp = tid >> 5;
    const int qt = (int)gridDim.y - 1 - (int)blockIdx.y;   // descending work order
    const int bh = blockIdx.x;
    const size_t bhbase = (size_t)bh * TT * SS;

    // ---- stage Q (128x64 = 1024 x 16B) into arrays 0,1 ----
    {
        const __half* src = g_Qh + bhbase + (size_t)qt * 128 * 64;
        #pragma unroll
        for (int i = 0; i < 4; i++) {
            int idx = tid + 256 * i;                  // 0..1023
            int r = idx >> 3, ch = idx & 7;           // r in [0,128)
            int a = r >> 6, rl = r & 63;
            cp16(smraw + a * 4096 + rl * 64 + SWZ8(rl, ch), src + r * 64 + ch * 8);
        }
    }
    asm volatile("cp.async.commit_group;");
    asm volatile("cp.async.wait_group 0;");
    __syncthreads();

    uint32_t qh[4][4];
    {
        int r = warp * 16 + (lane & 15);
        int a = r >> 6, rl = r & 63;
        #pragma unroll
        for (int kk = 0; kk < 4; kk++) {
            int ch = kk * 2 + (lane >> 4);
            LDM4(qh[kk], smraw + a * 4096 + rl * 64 + SWZ8(rl, ch));
        }
    }
    __syncthreads();

    float oc[8][4];
    #pragma unroll
    for (int j = 0; j < 8; j++)
        #pragma unroll
        for (int q = 0; q < 4; q++) oc[j][q] = 0.0f;
    float l0 = 0.0f, l1 = 0.0f;

    const int rg = lane >> 2;
    const int cb = (lane & 3) << 1;
    const int brow = (lane & 7) + ((lane >> 4) << 3);
    const int bchx = (lane >> 3) & 1;
    const int vrow16 = ((lane >> 3) & 1) * 8 + (lane & 7);
    const int vchh = lane >> 4;
    const int ktmax = 2 * qt + 1;

    const __half* kvsrc[2] = {g_Kh + bhbase, g_Vh + bhbase};

    #define LOAD_KV(KT, ST) do { \
        _Pragma("unroll") \
        for (int _i = 0; _i < 4; _i++) { \
            int _g = tid + 256 * _i;           /* 0..1023 */ \
            int _arr = _g >> 9, _idx = _g & 511; \
            int _r = _idx >> 3, _ch = _idx & 7; \
            cp16(smraw + ((ST) * 2 + _arr) * 4096 + _r * 64 + SWZ8(_r, _ch), \
                 kvsrc[_arr] + (size_t)(KT) * 4096 + _r * 64 + _ch * 8); \
        } \
        asm volatile("cp.async.commit_group;"); \
    } while (0)

    LOAD_KV(0, 0);

    for (int kt = 0; kt <= ktmax; kt++) {
        const int st = kt & 1;
        if (kt < ktmax) {
            LOAD_KV(kt + 1, st ^ 1);
            asm volatile("cp.async.wait_group 1;");
        } else {
            asm volatile("cp.async.wait_group 0;");
        }
        __syncthreads();

        if (qt * 128 + warp * 16 + 15 >= kt * 64) {
            const __half* Kh_ = smraw + (st * 2 + 0) * 4096;
            const __half* Vh_ = smraw + (st * 2 + 1) * 4096;

            // ---- S = Q K^T (fp16) ----
            float sc[8][4];
            #pragma unroll
            for (int j = 0; j < 8; j++)
                #pragma unroll
                for (int q = 0; q < 4; q++) sc[j][q] = 0.0f;
            #pragma unroll
            for (int g = 0; g < 4; g++) {
                int row = g * 16 + brow;
                #pragma unroll
                for (int kk = 0; kk < 4; kk++) {
                    int ch = kk * 2 + bchx;
                    uint32_t bh4[4];
                    LDM4(bh4, &Kh_[row * 64 + SWZ8(row, ch)]);
                    MMAF16(sc[2*g],   qh[kk], bh4[0], bh4[1]);
                    MMAF16(sc[2*g+1], qh[kk], bh4[2], bh4[3]);
                }
            }

            // ---- softmax terms (no max subtraction; scores bounded) ----
            int base0 = qt * 128 + warp * 16 + rg - kt * 64 + 128;
            int base1 = base0 + 8;
            float ls0 = 0.0f, ls1 = 0.0f;
            #pragma unroll
            for (int j = 0; j < 8; j++) {
                int c0 = j * 8 + cb;
                float e0 = exp2p(sc[j][0] * CLOG2E) * __ldg(&g_ebias[base0 - c0]);
                float e1 = exp2p(sc[j][1] * CLOG2E) * __ldg(&g_ebias[base0 - c0 - 1]);
                float e2 = exp2p(sc[j][2] * CLOG2E) * __ldg(&g_ebias[base1 - c0]);
                float e3 = exp2p(sc[j][3] * CLOG2E) * __ldg(&g_ebias[base1 - c0 - 1]);
                sc[j][0] = e0; sc[j][1] = e1; sc[j][2] = e2; sc[j][3] = e3;
                ls0 += e0 + e1; ls1 += e2 + e3;
            }
            l0 += ls0;
            l1 += ls1;

            // ---- repack P (C-frag -> A-frag, RN fp16) ----
            uint32_t pah[4][4];
            #pragma unroll
            for (int kk = 0; kk < 4; kk++) {
                #pragma unroll
                for (int half = 0; half < 2; half++) {
                    int j = 2 * kk + half;
                    pah[kk][half * 2]     = pack_f16x2(sc[j][0], sc[j][1]);
                    pah[kk][half * 2 + 1] = pack_f16x2(sc[j][2], sc[j][3]);
                }
            }

            // ---- O += P V (fp16 1-term; V row-major via ldmatrix.trans) ----
            #pragma unroll
            for (int g = 0; g < 4; g++) {
                int ch = 2 * g + vchh;
                #pragma unroll
                for (int kk = 0; kk < 4; kk++) {
                    int row = kk * 16 + vrow16;
                    uint32_t vh4[4];
                    LDM4T(vh4, &Vh_[row * 64 + SWZ8(row, ch)]);
                    MMAF16(oc[2*g],   pah[kk], vh4[0], vh4[1]);
                    MMAF16(oc[2*g+1], pah[kk], vh4[2], vh4[3]);
                }
            }
        }
        __syncthreads();
    }

    // ---- l reduction across quad + epilogue (fp16 AO) ----
    l0 += __shfl_xor_sync(0xffffffffu, l0, 1);
    l0 += __shfl_xor_sync(0xffffffffu, l0, 2);
    l1 += __shfl_xor_sync(0xffffffffu, l1, 1);
    l1 += __shfl_xor_sync(0xffffffffu, l1, 2);
    float inv0 = 1.0f / l0, inv1 = 1.0f / l1;
    int b = bh >> 4, hh = bh & 15;
    int t0 = qt * 128 + warp * 16 + rg;
    __half* rowp = g_AO + (size_t)(b * TT + t0) * DD + hh * 64 + cb;
    #pragma unroll
    for (int j = 0; j < 8; j++) {
        *(uint32_t*)(rowp + j * 8) = pack_f16x2(oc[j][0] * inv0, oc[j][1] * inv0);
        *(uint32_t*)(rowp + (size_t)8 * DD + j * 8) = pack_f16x2(oc[j][2] * inv1, oc[j][3] * inv1);
    }
}

// ---------------- launch ----------------
extern "C" void kernel_launch(void* const* d_in, const int* in_sizes, int n_in,
                              void* d_out, int out_size) {
    const float* x   = (const float*)d_in[0];
    const float* wq  = (const float*)d_in[1];
    const float* wk  = (const float*)d_in[2];
    const float* wv  = (const float*)d_in[3];
    const float* wo  = (const float*)d_in[4];
    const float* wu  = (const float*)d_in[5];
    const float* wsv = (const float*)d_in[6];
    const float* ps  = (const float*)d_in[7];
    float* out = (float*)d_out;

    static int smem_set = 0;
    if (!smem_set) {
        cudaFuncSetAttribute(attn_tc_kernel, cudaFuncAttributeMaxDynamicSharedMemorySize, 32768);
        smem_set = 1;
    }

    zero_absmax_kernel<<<1, 32>>>();
    absmax_all_kernel<<<dim3(64, 6), 256>>>(wq, wk, wv, wo, wu, wsv);
    build_ebias_kernel<<<9, 256>>>(ps);
    compose_split_kernel<<<dim3(8, 16, 2), 256>>>(wq, wk, wu, wsv);
    split_w_vo_kernel<<<dim3(DD*DD/1024, 2), 256>>>(wv, wo);
    split_act_kernel<<<MM*DD/1024, 256>>>(x);
    gemm_qkv_f16_kernel<<<dim3(DD/128, MM/128, 3), 256>>>();          // QKV fp16, V heavy-first
    attn_tc_kernel<<<dim3(BB*HH, TT/128), 256, 32768>>>();            // qt slow, descending
    gemm_o_f16_kernel<<<dim3(DD/128, MM/128), 256>>>(out);            // O: fp16 1-term
}

// round 16
// speedup vs baseline: 7.1088x; 1.1461x over previous
#include <cuda_runtime.h>
#include <cuda_bf16.h>
#include <cuda_fp16.h>
#include <cstdint>

#define BB 4
#define TT 2048
#define DD 1024
#define HH 16
#define SS 64
#define MM (BB*TT)
#define EBN 2208         // log2-bias table size (index = d + 128)
#define LOG2E 1.4426950408889634f

// ---------------- device scratch (static, allocation-free) ----------------
__device__ float g_absmax[8];
__device__ __half g_Qh[(size_t)BB*HH*TT*SS];
__device__ __half g_Kh[(size_t)BB*HH*TT*SS];
__device__ __half g_Vh[(size_t)BB*HH*TT*SS];
__device__ __half g_Af[(size_t)MM*DD];              // fp16(x)
__device__ __half g_Wf[(size_t)3*DD*DD];            // fp16 quantized weights (q,k,v)
__device__ __half g_AO[(size_t)MM*DD];              // attention output, fp16
__device__ __half g_wo_f16[(size_t)DD*DD];          // quantized wo, fp16
__device__ float g_ebias[EBN];                      // log2-domain bias; -1e30 = masked

// ---------------- prep ----------------
__global__ void zero_absmax_kernel() {
    if (threadIdx.x < 8) g_absmax[threadIdx.x] = 0.0f;
}

__global__ void absmax_all_kernel(const float* __restrict__ wq, const float* __restrict__ wk,
                                  const float* __restrict__ wv, const float* __restrict__ wo,
                                  const float* __restrict__ wu, const float* __restrict__ wsv) {
    int slot = blockIdx.y;
    const float* w = (slot == 0) ? wq : (slot == 1) ? wk : (slot == 2) ? wv
                   : (slot == 3) ? wo : (slot == 4) ? wu : wsv;
    int n = (slot < 4) ? DD * DD : SS * SS;
    float m = 0.0f;
    for (int i = blockIdx.x * blockDim.x + threadIdx.x; i < n; i += gridDim.x * blockDim.x)
        m = fmaxf(m, fabsf(w[i]));
    #pragma unroll
    for (int o = 16; o > 0; o >>= 1) m = fmaxf(m, __shfl_xor_sync(0xffffffffu, m, o));
    __shared__ float sm[8];
    int lane = threadIdx.x & 31, wid = threadIdx.x >> 5;
    if (lane == 0) sm[wid] = m;
    __syncthreads();
    if (wid == 0) {
        int nw = blockDim.x >> 5;
        m = (lane < nw) ? sm[lane] : 0.0f;
        #pragma unroll
        for (int o = 4; o > 0; o >>= 1) m = fmaxf(m, __shfl_xor_sync(0xffffffffu, m, o));
        if (lane == 0) atomicMax((int*)&g_absmax[slot], __float_as_int(m));
    }
}

// log2-domain p-adic bias table: lb[i] = ps * bias(i-128) * log2(e); masked (d<0) -> -1e30
__global__ void build_ebias_kernel(const float* __restrict__ ps) {
    int i = blockIdx.x * 256 + threadIdx.x;
    if (i >= EBN) return;
    float v = -1e30f;
    if (i >= 128 && i < 128 + 2048) {
        int d = i - 128;
        float bias = (d == 0) ? 1.0f : (float)min(__ffs(d) - 1, 16) * 0.0625f;
        v = ps[0] * bias * LOG2E;
    }
    g_ebias[i] = v;
}

// ---------------- PTX helpers ----------------
__device__ __forceinline__ void cp16(void* dst, const void* src) {
    unsigned d = (unsigned)__cvta_generic_to_shared(dst);
    asm volatile("cp.async.cg.shared.global [%0], [%1], 16;\n" :: "r"(d), "l"(src));
}
#define LDM4(R, PTR) do { \
    unsigned _a = (unsigned)__cvta_generic_to_shared(PTR); \
    asm volatile("ldmatrix.sync.aligned.m8n8.x4.shared.b16 {%0,%1,%2,%3}, [%4];" \
        : "=r"((R)[0]), "=r"((R)[1]), "=r"((R)[2]), "=r"((R)[3]) : "r"(_a)); \
} while (0)
#define LDM4T(R, PTR) do { \
    unsigned _a = (unsigned)__cvta_generic_to_shared(PTR); \
    asm volatile("ldmatrix.sync.aligned.m8n8.x4.trans.shared.b16 {%0,%1,%2,%3}, [%4];" \
        : "=r"((R)[0]), "=r"((R)[1]), "=r"((R)[2]), "=r"((R)[3]) : "r"(_a)); \
} while (0)
#define MMAF16(C, A, B0, B1) \
    asm volatile("mma.sync.aligned.m16n8k16.row.col.f32.f16.f16.f32 " \
        "{%0,%1,%2,%3}, {%4,%5,%6,%7}, {%8,%9}, {%0,%1,%2,%3};" \
        : "+f"((C)[0]), "+f"((C)[1]), "+f"((C)[2]), "+f"((C)[3]) \
        : "r"((A)[0]), "r"((A)[1]), "r"((A)[2]), "r"((A)[3]), "r"(B0), "r"(B1))
#define SWZ(row, ch) ((ch) ^ (((row) >> 1) & 3))
#define SWZ8(row, ch) (((ch) ^ ((row) & 7)) << 3)

__device__ __forceinline__ uint32_t pack_f16x2(float lo, float hi) {
    uint32_t r;
    asm("cvt.rn.f16x2.f32 %0, %1, %2;" : "=r"(r) : "f"(hi), "f"(lo));
    return r;
}
__device__ __forceinline__ float exp2p(float y) {   // fast 2^y, fma/alu only
    y = fmaxf(y, -125.0f);
    float z = y + 12582912.0f;
    float f = y - (z - 12582912.0f);
    int e = __float_as_int(z) << 23;
    float r = 0.0013333558146f;
    r = fmaf(r, f, 0.0096181291076f);
    r = fmaf(r, f, 0.055504108664f);
    r = fmaf(r, f, 0.24022650696f);
    r = fmaf(r, f, 0.69314718056f);
    r = fmaf(r, f, 1.0f);
    return __int_as_float(__float_as_int(r) + e);
}
__device__ __forceinline__ float quant6(float w, float sc) {
    float q = rintf(w / sc);
    return fminf(fmaxf(q, -31.0f), 31.0f) * sc;
}

// ---------------- compose (stalk-fold) + quant + fp16 store, fused ----------------
__global__ __launch_bounds__(256) void compose_split_kernel(
        const float* __restrict__ wq, const float* __restrict__ wk,
        const float* __restrict__ wu, const float* __restrict__ wsv) {
    __shared__ float ws[64][64];
    __shared__ float wb[64][128];
    const int which = blockIdx.z, h = blockIdx.y, kc = blockIdx.x;
    const float* wsmall = which ? wsv : wu;
    const float* wbig   = which ? wk  : wq;
    const float scb = g_absmax[which ? 1 : 0] / 31.0f + 1e-8f;
    const float scs = g_absmax[which ? 5 : 4] / 31.0f + 1e-8f;
    const int tid = threadIdx.x;

    for (int idx = tid; idx < 4096; idx += 256)
        ws[idx >> 6][idx & 63] = quant6(wsmall[idx], scs);
    for (int idx = tid; idx < 8192; idx += 256) {
        int s = idx >> 7, k = idx & 127;
        wb[s][k] = quant6(wbig[(size_t)(h * 64 + s) * DD + kc * 128 + k], scb);
    }
    __syncthreads();

    const int tx = tid & 31, ty = tid >> 5;
    const int k0 = tx * 4, sp0 = ty * 8;
    float acc[8][4];
    #pragma unroll
    for (int i = 0; i < 8; i++)
        #pragma unroll
        for (int j = 0; j < 4; j++) acc[i][j] = 0.0f;
    #pragma unroll 8
    for (int s = 0; s < 64; s++) {
        float4 b = *(const float4*)&wb[s][k0];
        #pragma unroll
        for (int i = 0; i < 8; i++) {
            float a = ws[sp0 + i][s];
            acc[i][0] = fmaf(a, b.x, acc[i][0]);
            acc[i][1] = fmaf(a, b.y, acc[i][1]);
            acc[i][2] = fmaf(a, b.z, acc[i][2]);
            acc[i][3] = fmaf(a, b.w, acc[i][3]);
        }
    }
    __half* o = g_Wf + (size_t)which * DD * DD;
    #pragma unroll
    for (int i = 0; i < 8; i++) {
        __half* p = o + (size_t)(h * 64 + sp0 + i) * DD + kc * 128 + k0;
        *(uint32_t*)p = pack_f16x2(acc[i][0], acc[i][1]);
        *(uint32_t*)(p + 2) = pack_f16x2(acc[i][2], acc[i][3]);
    }
}

// ---------------- wv -> Wf; wo -> fp16 ----------------
__global__ void split_w_vo_kernel(const float* __restrict__ wv, const float* __restrict__ wo) {
    int is_o = blockIdx.y;
    const float* src = is_o ? wo : wv;
    float sc = g_absmax[2 + is_o] / 31.0f + 1e-8f;
    int i = blockIdx.x * 256 + threadIdx.x;
    int row = i >> 8;
    int k4 = (i & 255) * 4;
    float4 v = *(const float4*)(src + (size_t)row * DD + k4);
    v.x = quant6(v.x, sc); v.y = quant6(v.y, sc);
    v.z = quant6(v.z, sc); v.w = quant6(v.w, sc);
    __half* o = (is_o ? g_wo_f16 : g_Wf + (size_t)2 * DD * DD) + (size_t)row * DD + k4;
    *(uint32_t*)o = pack_f16x2(v.x, v.y);
    *(uint32_t*)(o + 2) = pack_f16x2(v.z, v.w);
}

// ---------------- x -> fp16 RN ----------------
__global__ void split_act_kernel(const float* __restrict__ src) {
    int i = blockIdx.x * 256 + threadIdx.x;
    int row = i >> 8;
    int k4 = (i & 255) * 4;
    float4 v = *(const float4*)(src + (size_t)row * DD + k4);
    __half* o = g_Af + (size_t)row * DD + k4;
    *(uint32_t*)o = pack_f16x2(v.x, v.y);
    *(uint32_t*)(o + 2) = pack_f16x2(v.z, v.w);
}

// ---------------- fp16 GEMM core (K=1024, nc=32): shared by QKV and O ----------------
template<int MODE>   // 0: QKV (which=blockIdx.z), 1: O
__device__ __forceinline__ void gemm_f16_body(float* ext_out) {
    const int which = (MODE == 0) ? (int)blockIdx.z : 3;
    __shared__ alignas(16) __half As[2][128 * 32];
    __shared__ alignas(16) __half Bs[2][128 * 32];

    const __half* Ag = ((MODE == 0) ? g_Af : g_AO) + (size_t)blockIdx.y * 128 * DD;
    const __half* Bg = ((MODE == 0) ? g_Wf + (size_t)which * DD * DD : g_wo_f16)
                       + (size_t)blockIdx.x * 128 * DD;
    const int tid = threadIdx.x;
    const int lane = tid & 31, wid = tid >> 5;
    const int warp_m = wid >> 1, warp_n = wid & 1;
    const int m0 = blockIdx.y * 128;
    const int n0 = blockIdx.x * 128;

    float c[2][4][2][4];
    #pragma unroll
    for (int i = 0; i < 2; i++)
        #pragma unroll
        for (int g = 0; g < 4; g++)
            #pragma unroll
            for (int j = 0; j < 2; j++)
                #pragma unroll
                for (int q = 0; q < 4; q++) c[i][g][j][q] = 0.0f;

    int ld_row[2], ld_ch[2];
    #pragma unroll
    for (int p = 0; p < 2; p++) {
        int e = tid + p * 256;
        ld_row[p] = e >> 2;
        ld_ch[p] = e & 3;
    }
    const int nc = 32;

    #pragma unroll
    for (int p = 0; p < 2; p++) {
        int row = ld_row[p], ch = ld_ch[p];
        int so = row * 32 + SWZ(row, ch) * 8;
        cp16(&As[0][so], Ag + (size_t)row * DD + ch * 8);
        cp16(&Bs[0][so], Bg + (size_t)row * DD + ch * 8);
    }
    asm volatile("cp.async.commit_group;");

    for (int kc = 0; kc < nc; kc++) {
        if (kc + 1 < nc) {
            int s = (kc + 1) & 1;
            int koff = (kc + 1) * 32;
            #pragma unroll
            for (int p = 0; p < 2; p++) {
                int row = ld_row[p], ch = ld_ch[p];
                int so = row * 32 + SWZ(row, ch) * 8;
                cp16(&As[s][so], Ag + (size_t)row * DD + koff + ch * 8);
                cp16(&Bs[s][so], Bg + (size_t)row * DD + koff + ch * 8);
            }
            asm volatile("cp.async.commit_group;");
            asm volatile("cp.async.wait_group 1;");
        } else {
            asm volatile("cp.async.wait_group 0;");
        }
        __syncthreads();

        const __half* Asb = As[kc & 1];
        const __half* Bsb = Bs[kc & 1];

        #pragma unroll
        for (int kk = 0; kk < 2; kk++) {
            uint32_t af[2][4], bf[4][4];
            #pragma unroll
            for (int i = 0; i < 2; i++) {
                int row = warp_m * 32 + i * 16 + (lane & 15);
                int ch = kk * 2 + (lane >> 4);
                LDM4(af[i], Asb + row * 32 + SWZ(row, ch) * 8);
            }
            #pragma unroll
            for (int g = 0; g < 4; g++) {
                int row = warp_n * 64 + g * 16 + (lane & 7) + ((lane >> 4) << 3);
                int ch = kk * 2 + ((lane >> 3) & 1);
                LDM4(bf[g], Bsb + row * 32 + SWZ(row, ch) * 8);
            }
            #pragma unroll
            for (int i = 0; i < 2; i++)
                #pragma unroll
                for (int g = 0; g < 4; g++) {
                    MMAF16(c[i][g][0], af[i], bf[g][0], bf[g][1]);
                    MMAF16(c[i][g][1], af[i], bf[g][2], bf[g][3]);
                }
        }
        __syncthreads();
    }

    // epilogue
    #pragma unroll
    for (int i = 0; i < 2; i++)
        #pragma unroll
        for (int g = 0; g < 4; g++)
            #pragma unroll
            for (int j = 0; j < 2; j++) {
                int rr = m0 + warp_m * 32 + i * 16 + (lane >> 2);
                int cc = n0 + warp_n * 64 + g * 16 + j * 8 + ((lane & 3) << 1);
                if (MODE == 0) {
                    int b = rr >> 11, t = rr & 2047;
                    int hh = cc >> 6, s2 = cc & 63;
                    size_t off = ((size_t)(b * HH + hh) * TT + t) * SS + s2;
                    __half* dh = (which == 0) ? g_Qh : (which == 1) ? g_Kh : g_Vh;
                    *(uint32_t*)(dh + off) = pack_f16x2(c[i][g][j][0], c[i][g][j][1]);
                    *(uint32_t*)(dh + off + 8 * SS) = pack_f16x2(c[i][g][j][2], c[i][g][j][3]);
                } else {
                    *(float2*)(ext_out + (size_t)rr * DD + cc) =
                        make_float2(c[i][g][j][0], c[i][g][j][1]);
                    *(float2*)(ext_out + (size_t)(rr + 8) * DD + cc) =
                        make_float2(c[i][g][j][2], c[i][g][j][3]);
                }
            }
}

__global__ __launch_bounds__(256, 2) void gemm_qkv_f16_kernel() {
    gemm_f16_body<0>(nullptr);
}
__global__ __launch_bounds__(256, 2) void gemm_o_f16_kernel(float* __restrict__ ext_out) {
    gemm_f16_body<1>(ext_out);
}

// ---------------- tensor-core flash attention (fp16, no running max, smem bias) ----
// grid (64 bh fast, 16 qt slow DESCENDING): heavy q-tiles launch first.
#define CLOG2E 0.18033688011112042f   // 0.125 * log2(e)

__global__ __launch_bounds__(256, 2) void attn_tc_kernel() {
    extern __shared__ __half smraw[];   // [2 stages][2 arrays: Kh,Vh][64*64] + float lb[EBN]
    float* lb_s = (float*)(smraw + 4 * 4096);
    const int tid = threadIdx.x, lane = tid & 31, warp = tid >> 5;
    const int qt = (int)gridDim.y - 1 - (int)blockIdx.y;   // descending work order
    const int bh = blockIdx.x;
    const size_t bhbase = (size_t)bh * TT * SS;

    // ---- stage Q (128x64 = 1024 x 16B) into arrays 0,1; load bias table ----
    {
        const __half* src = g_Qh + bhbase + (size_t)qt * 128 * 64;
        #pragma unroll
        for (int i = 0; i < 4; i++) {
            int idx = tid + 256 * i;                  // 0..1023
            int r = idx >> 3, ch = idx & 7;           // r in [0,128)
            int a = r >> 6, rl = r & 63;
            cp16(smraw + a * 4096 + rl * 64 + SWZ8(rl, ch), src + r * 64 + ch * 8);
        }
    }
    for (int i = tid; i < EBN; i += 256) lb_s[i] = g_ebias[i];
    asm volatile("cp.async.commit_group;");
    asm volatile("cp.async.wait_group 0;");
    __syncthreads();

    uint32_t qh[4][4];
    {
        int r = warp * 16 + (lane & 15);
        int a = r >> 6, rl = r & 63;
        #pragma unroll
        for (int kk = 0; kk < 4; kk++) {
            int ch = kk * 2 + (lane >> 4);
            LDM4(qh[kk], smraw + a * 4096 + rl * 64 + SWZ8(rl, ch));
        }
    }
    __syncthreads();

    float oc[8][4];
    #pragma unroll
    for (int j = 0; j < 8; j++)
        #pragma unroll
        for (int q = 0; q < 4; q++) oc[j][q] = 0.0f;
    float l0 = 0.0f, l1 = 0.0f;

    const int rg = lane >> 2;
    const int cb = (lane & 3) << 1;
    const int brow = (lane & 7) + ((lane >> 4) << 3);
    const int bchx = (lane >> 3) & 1;
    const int vrow16 = ((lane >> 3) & 1) * 8 + (lane & 7);
    const int vchh = lane >> 4;
    const int ktmax = 2 * qt + 1;

    const __half* kvsrc[2] = {g_Kh + bhbase, g_Vh + bhbase};

    #define LOAD_KV(KT, ST) do { \
        _Pragma("unroll") \
        for (int _i = 0; _i < 4; _i++) { \
            int _g = tid + 256 * _i;           /* 0..1023 */ \
            int _arr = _g >> 9, _idx = _g & 511; \
            int _r = _idx >> 3, _ch = _idx & 7; \
            cp16(smraw + ((ST) * 2 + _arr) * 4096 + _r * 64 + SWZ8(_r, _ch), \
                 kvsrc[_arr] + (size_t)(KT) * 4096 + _r * 64 + _ch * 8); \
        } \
        asm volatile("cp.async.commit_group;"); \
    } while (0)

    LOAD_KV(0, 0);

    for (int kt = 0; kt <= ktmax; kt++) {
        const int st = kt & 1;
        if (kt < ktmax) {
            LOAD_KV(kt + 1, st ^ 1);
            asm volatile("cp.async.wait_group 1;");
        } else {
            asm volatile("cp.async.wait_group 0;");
        }
        __syncthreads();

        if (qt * 128 + warp * 16 + 15 >= kt * 64) {
            const __half* Kh_ = smraw + (st * 2 + 0) * 4096;
            const __half* Vh_ = smraw + (st * 2 + 1) * 4096;

            // ---- S = Q K^T (fp16) ----
            float sc[8][4];
            #pragma unroll
            for (int j = 0; j < 8; j++)
                #pragma unroll
                for (int q = 0; q < 4; q++) sc[j][q] = 0.0f;
            #pragma unroll
            for (int g = 0; g < 4; g++) {
                int row = g * 16 + brow;
                #pragma unroll
                for (int kk = 0; kk < 4; kk++) {
                    int ch = kk * 2 + bchx;
                    uint32_t bh4[4];
                    LDM4(bh4, &Kh_[row * 64 + SWZ8(row, ch)]);
                    MMAF16(sc[2*g],   qh[kk], bh4[0], bh4[1]);
                    MMAF16(sc[2*g+1], qh[kk], bh4[2], bh4[3]);
                }
            }

            // ---- softmax terms: e = 2^(s*C + lb[d]); masked lb=-1e30 -> ~0 ----
            int base0 = qt * 128 + warp * 16 + rg - kt * 64 + 128;
            int base1 = base0 + 8;
            float ls0 = 0.0f, ls1 = 0.0f;
            #pragma unroll
            for (int j = 0; j < 8; j++) {
                int c0 = j * 8 + cb;
                float e0 = exp2p(fmaf(sc[j][0], CLOG2E, lb_s[base0 - c0]));
                float e1 = exp2p(fmaf(sc[j][1], CLOG2E, lb_s[base0 - c0 - 1]));
                float e2 = exp2p(fmaf(sc[j][2], CLOG2E, lb_s[base1 - c0]));
                float e3 = exp2p(fmaf(sc[j][3], CLOG2E, lb_s[base1 - c0 - 1]));
                sc[j][0] = e0; sc[j][1] = e1; sc[j][2] = e2; sc[j][3] = e3;
                ls0 += e0 + e1; ls1 += e2 + e3;
            }
            l0 += ls0;
            l1 += ls1;

            // ---- repack P (C-frag -> A-frag, RN fp16) ----
            uint32_t pah[4][4];
            #pragma unroll
            for (int kk = 0; kk < 4; kk++) {
                #pragma unroll
                for (int half = 0; half < 2; half++) {
                    int j = 2 * kk + half;
                    pah[kk][half * 2]     = pack_f16x2(sc[j][0], sc[j][1]);
                    pah[kk][half * 2 + 1] = pack_f16x2(sc[j][2], sc[j][3]);
                }
            }

            // ---- O += P V (fp16 1-term; V row-major via ldmatrix.trans) ----
            #pragma unroll
            for (int g = 0; g < 4; g++) {
                int ch = 2 * g + vchh;
                #pragma unroll
                for (int kk = 0; kk < 4; kk++) {
                    int row = kk * 16 + vrow16;
                    uint32_t vh4[4];
                    LDM4T(vh4, &Vh_[row * 64 + SWZ8(row, ch)]);
                    MMAF16(oc[2*g],   pah[kk], vh4[0], vh4[1]);
                    MMAF16(oc[2*g+1], pah[kk], vh4[2], vh4[3]);
                }
            }
        }
        __syncthreads();
    }

    // ---- l reduction across quad + epilogue (fp16 AO) ----
    l0 += __shfl_xor_sync(0xffffffffu, l0, 1);
    l0 += __shfl_xor_sync(0xffffffffu, l0, 2);
    l1 += __shfl_xor_sync(0xffffffffu, l1, 1);
    l1 += __shfl_xor_sync(0xffffffffu, l1, 2);
    float inv0 = 1.0f / l0, inv1 = 1.0f / l1;
    int b = bh >> 4, hh = bh & 15;
    int t0 = qt * 128 + warp * 16 + rg;
    __half* rowp = g_AO + (size_t)(b * TT + t0) * DD + hh * 64 + cb;
    #pragma unroll
    for (int j = 0; j < 8; j++) {
        *(uint32_t*)(rowp + j * 8) = pack_f16x2(oc[j][0] * inv0, oc[j][1] * inv0);
        *(uint32_t*)(rowp + (size_t)8 * DD + j * 8) = pack_f16x2(oc[j][2] * inv1, oc[j][3] * inv1);
    }
}

// ---------------- launch ----------------
extern "C" void kernel_launch(void* const* d_in, const int* in_sizes, int n_in,
                              void* d_out, int out_size) {
    const float* x   = (const float*)d_in[0];
    const float* wq  = (const float*)d_in[1];
    const float* wk  = (const float*)d_in[2];
    const float* wv  = (const float*)d_in[3];
    const float* wo  = (const float*)d_in[4];
    const float* wu  = (const float*)d_in[5];
    const float* wsv = (const float*)d_in[6];
    const float* ps  = (const float*)d_in[7];
    float* out = (float*)d_out;

    static int smem_set = 0;
    if (!smem_set) {
        cudaFuncSetAttribute(attn_tc_kernel, cudaFuncAttributeMaxDynamicSharedMemorySize,
                             32768 + EBN * 4);
        smem_set = 1;
    }

    zero_absmax_kernel<<<1, 32>>>();
    absmax_all_kernel<<<dim3(64, 6), 256>>>(wq, wk, wv, wo, wu, wsv);
    build_ebias_kernel<<<9, 256>>>(ps);
    compose_split_kernel<<<dim3(8, 16, 2), 256>>>(wq, wk, wu, wsv);
    split_w_vo_kernel<<<dim3(DD*DD/1024, 2), 256>>>(wv, wo);
    split_act_kernel<<<MM*DD/1024, 256>>>(x);
    gemm_qkv_f16_kernel<<<dim3(DD/128, MM/128, 3), 256>>>();          // QKV fp16 1-term
    attn_tc_kernel<<<dim3(BB*HH, TT/128), 256, 32768 + EBN*4>>>();    // qt slow, descending
    gemm_o_f16_kernel<<<dim3(DD/128, MM/128), 256>>>(out);            // O: fp16 1-term
}